// round 5
// baseline (speedup 1.0000x reference)
#include <cuda_runtime.h>
#include <cuda_bf16.h>
#include <math.h>
#include <stdint.h>

// ---------------------------------------------------------------------------
// Problem constants
// ---------------------------------------------------------------------------
#define D_MODEL   1024
#define D_STATE   16
#define D_CONV    4
#define D_INNER   2048
#define DT_RANK   64
#define BATCH     2
#define SEQLEN    1024
#define ROWS      (BATCH * SEQLEN)          // 2048
#define XDBL_COLS (DT_RANK + 2 * D_STATE)   // 96
#define EPS       1e-5f

#define XP_SPLITS 8
#define XP_KSPL   (D_INNER / XP_SPLITS)     // 256

// ---------------------------------------------------------------------------
// Scratch (__device__ globals; no cudaMalloc allowed)
// ---------------------------------------------------------------------------
__device__ float g_h    [ROWS * D_MODEL];      // rmsnorm out
__device__ float g_xz   [ROWS * 2 * D_INNER];  // in_proj out (x | z)
__device__ float g_xc   [ROWS * D_INNER];      // conv+silu out
__device__ float g_xpart[XP_SPLITS * ROWS * XDBL_COLS]; // x_proj split-K partials
__device__ float g_xdbl [ROWS * XDBL_COLS];    // x_proj out (dt_lowrank | B | C)
__device__ float g_dt   [ROWS * D_INNER];      // softplus(dt)
__device__ float g_y    [ROWS * D_INNER];      // scan out

// ---------------------------------------------------------------------------
// Helpers
// ---------------------------------------------------------------------------
__device__ __forceinline__ float softplusf(float v)
{
    return v > 20.f ? v : log1pf(__expf(v));
}

// packed fp32x2 FMA: d.lo += a.lo*b.lo ; d.hi += a.hi*b.hi
__device__ __forceinline__ void ffma2(unsigned long long& d,
                                      unsigned long long a,
                                      unsigned long long b)
{
    asm("fma.rn.f32x2 %0, %1, %2, %0;" : "+l"(d) : "l"(a), "l"(b));
}

__device__ __forceinline__ float pair_sum(unsigned long long v)
{
    unsigned lo, hi;
    asm("mov.b64 {%0, %1}, %2;" : "=r"(lo), "=r"(hi) : "l"(v));
    return __uint_as_float(lo) + __uint_as_float(hi);
}

// ---------------------------------------------------------------------------
// RMSNorm
// ---------------------------------------------------------------------------
__global__ __launch_bounds__(256)
void rmsnorm_kernel(const float* __restrict__ x, const float* __restrict__ w,
                    float* __restrict__ out)
{
    int r = blockIdx.x;
    int t = threadIdx.x;
    const float4* xr = (const float4*)(x + (size_t)r * D_MODEL);
    float4 v = xr[t];
    float s = v.x * v.x + v.y * v.y + v.z * v.z + v.w * v.w;
    #pragma unroll
    for (int o = 16; o; o >>= 1) s += __shfl_xor_sync(0xffffffffu, s, o);

    __shared__ float ws[8];
    __shared__ float s_inv;
    if ((t & 31) == 0) ws[t >> 5] = s;
    __syncthreads();
    if (t == 0) {
        float tot = 0.f;
        #pragma unroll
        for (int i = 0; i < 8; i++) tot += ws[i];
        float rms = sqrtf(tot) * (1.0f / 32.0f);
        s_inv = 1.0f / (rms + EPS);
    }
    __syncthreads();
    float inv = s_inv;
    float4 wv = ((const float4*)w)[t];
    float4 o;
    o.x = v.x * inv * wv.x;
    o.y = v.y * inv * wv.y;
    o.z = v.z * inv * wv.z;
    o.w = v.w * inv * wv.w;
    ((float4*)(out + (size_t)r * D_MODEL))[t] = o;
}

// ---------------------------------------------------------------------------
// Packed-f32 GEMM:  C[m][n] = sum_k A[m][k] * B[n][k]
// Block tile 128x64, BK=32, 3-stage cp.async, 8 warps (32x32 warp tiles),
// thread tile 8m x 4n, fma.rn.f32x2 with lanes paired along K.
// EPI: 0 = plain store, 1 = softplus(acc + bias[n]) store.
// split-K via blockIdx.z (k range z*k_len..), C += z*split_cstride.
// Requires M % 128 == 0, k_len % 32 == 0, N % 4 == 0. N guarded.
// ---------------------------------------------------------------------------
#define BK        32
#define STG       3
#define RBYTES    144                       // 36 floats per row (16B-aligned, padded)
#define A_BYTES   (128 * RBYTES)            // 18432
#define B_BYTES   (64 * RBYTES)             // 9216
#define STAGE_B   (A_BYTES + B_BYTES)       // 27648
#define GEMM_SMEM (STG * STAGE_B)           // 82944

template<int EPI>
__global__ __launch_bounds__(256, 2)
void gemm_f2(const float* __restrict__ A, int lda,
             const float* __restrict__ B, int ldb,
             float* __restrict__ C, int ldc,
             int N, int k_len, long long split_cstride,
             const float* __restrict__ bias)
{
    extern __shared__ unsigned char smem_raw[];
    const uint32_t smem = (uint32_t)__cvta_generic_to_shared(smem_raw);

    const int tid  = threadIdx.x;
    const int wid  = tid >> 5;
    const int lane = tid & 31;
    const int lr   = lane >> 3;          // 0..3
    const int lc   = lane & 7;           // 0..7
    const int warpM = (wid & 3) * 32;
    const int warpN = (wid >> 2) * 32;

    const int bm = blockIdx.y * 128;
    const int bn = blockIdx.x * 64;
    const int k0base = blockIdx.z * k_len;
    C += (size_t)blockIdx.z * split_cstride;
    const int ktiles = k_len / BK;

    // ---- stage loader: A 128x32 floats, B 64x32 floats, 16B cp.async chunks,
    //      xor-swizzled on 16B granularity within each 128B row.
    auto load_stage = [&](int stage, int kt) {
        const int k0 = k0base + kt * BK;
        const uint32_t sa = smem + stage * STAGE_B;
        const uint32_t sb = sa + A_BYTES;
        #pragma unroll
        for (int i = 0; i < 4; i++) {
            int lin = i * 256 + tid;         // 0..1023
            int c   = lin & 7;
            int row = lin >> 3;              // 0..127
            uint32_t dst = sa + row * RBYTES + ((c ^ (row & 7)) << 4);
            const float* src = A + (size_t)(bm + row) * lda + k0 + c * 4;
            asm volatile("cp.async.cg.shared.global [%0], [%1], 16;"
                         :: "r"(dst), "l"(src));
        }
        #pragma unroll
        for (int i = 0; i < 2; i++) {
            int lin = i * 256 + tid;         // 0..511
            int c   = lin & 7;
            int row = lin >> 3;              // 0..63
            int gn  = bn + row;
            uint32_t dst = sb + row * RBYTES + ((c ^ (row & 7)) << 4);
            const float* src = B + (size_t)(gn < N ? gn : 0) * ldb + k0 + c * 4;
            int ok = (gn < N) ? 16 : 0;
            asm volatile("cp.async.cg.shared.global [%0], [%1], 16, %2;"
                         :: "r"(dst), "l"(src), "r"(ok));
        }
    };

    unsigned long long acc2[8][4];
    #pragma unroll
    for (int i = 0; i < 8; i++)
        #pragma unroll
        for (int j = 0; j < 4; j++) acc2[i][j] = 0ull;

    // ---- prologue: stages 0, 1
    load_stage(0, 0);
    asm volatile("cp.async.commit_group;");
    if (ktiles > 1) load_stage(1, 1);
    asm volatile("cp.async.commit_group;");

    for (int kt = 0; kt < ktiles; kt++) {
        if (kt >= ktiles - 1) asm volatile("cp.async.wait_group 0;");
        else                  asm volatile("cp.async.wait_group 1;");
        __syncthreads();

        const uint32_t Ab = smem + (kt % STG) * STAGE_B;
        const uint32_t Bb = Ab + A_BYTES;

        #pragma unroll
        for (int kp = 0; kp < 16; kp++) {      // 16 k-pairs per BK=32
            const int ch  = kp >> 1;
            const int sub = (kp & 1) << 3;
            unsigned long long a2[8], b2[4];
            #pragma unroll
            for (int j = 0; j < 4; j++) {
                int r = warpN + lc * 4 + j;
                uint32_t ad = Bb + r * RBYTES + (((ch ^ (r & 7)) << 4) | sub);
                asm volatile("ld.shared.b64 %0, [%1];" : "=l"(b2[j]) : "r"(ad));
            }
            #pragma unroll
            for (int i = 0; i < 8; i++) {
                int r = warpM + lr * 8 + i;
                uint32_t ad = Ab + r * RBYTES + (((ch ^ (r & 7)) << 4) | sub);
                asm volatile("ld.shared.b64 %0, [%1];" : "=l"(a2[i]) : "r"(ad));
            }
            #pragma unroll
            for (int i = 0; i < 8; i++)
                #pragma unroll
                for (int j = 0; j < 4; j++)
                    ffma2(acc2[i][j], a2[i], b2[j]);
        }
        __syncthreads();

        if (kt + 2 < ktiles) load_stage((kt + 2) % STG, kt + 2);
        asm volatile("cp.async.commit_group;");
    }

    // ---- epilogue
    const int gn0 = bn + warpN + lc * 4;
    if (gn0 < N) {
        float b0, b1, b2v, b3;
        if (EPI == 1) {
            b0 = bias[gn0]; b1 = bias[gn0 + 1]; b2v = bias[gn0 + 2]; b3 = bias[gn0 + 3];
        }
        #pragma unroll
        for (int i = 0; i < 8; i++) {
            int gm = bm + warpM + lr * 8 + i;
            float4 v;
            v.x = pair_sum(acc2[i][0]);
            v.y = pair_sum(acc2[i][1]);
            v.z = pair_sum(acc2[i][2]);
            v.w = pair_sum(acc2[i][3]);
            if (EPI == 1) {
                v.x = softplusf(v.x + b0);
                v.y = softplusf(v.y + b1);
                v.z = softplusf(v.z + b2v);
                v.w = softplusf(v.w + b3);
            }
            *(float4*)(C + (size_t)gm * ldc + gn0) = v;
        }
    }
}

// ---------------------------------------------------------------------------
// x_proj split-K reduce: sum 8 partials
// ---------------------------------------------------------------------------
__global__ __launch_bounds__(256)
void xp_reduce_kernel()
{
    int i = blockIdx.x * 256 + threadIdx.x;
    if (i >= ROWS * XDBL_COLS) return;
    float s = 0.f;
    #pragma unroll
    for (int p = 0; p < XP_SPLITS; p++)
        s += g_xpart[(size_t)p * ROWS * XDBL_COLS + i];
    g_xdbl[i] = s;
}

// ---------------------------------------------------------------------------
// Depthwise causal conv + bias + SiLU
// ---------------------------------------------------------------------------
__global__ __launch_bounds__(256)
void conv_silu_kernel(const float* __restrict__ xz,
                      const float* __restrict__ cw,
                      const float* __restrict__ cb,
                      float* __restrict__ xc)
{
    int idx = blockIdx.x * blockDim.x + threadIdx.x;
    if (idx >= ROWS * D_INNER) return;
    int d = idx & (D_INNER - 1);
    int r = idx >> 11;
    int l = r & (SEQLEN - 1);
    int b = r >> 10;

    float acc = cb[d];
    #pragma unroll
    for (int k = 0; k < D_CONV; k++) {
        int ls = l + k - (D_CONV - 1);
        if (ls >= 0)
            acc = fmaf(xz[((size_t)(b * SEQLEN + ls)) * (2 * D_INNER) + d],
                       cw[d * D_CONV + k], acc);
    }
    float sig = 1.0f / (1.0f + __expf(-acc));
    xc[idx] = acc * sig;
}

// ---------------------------------------------------------------------------
// Selective scan. 16 lanes per (b,d) channel, one state per lane.
// ---------------------------------------------------------------------------
__global__ __launch_bounds__(128)
void scan_kernel(const float* __restrict__ xdbl,
                 const float* __restrict__ dt,
                 const float* __restrict__ xc,
                 const float* __restrict__ xz,
                 const float* __restrict__ A_log,
                 const float* __restrict__ Dw,
                 float* __restrict__ y)
{
    int t = blockIdx.x * blockDim.x + threadIdx.x;
    int n  = t & (D_STATE - 1);
    int ch = t >> 4;
    int b  = ch >> 11;
    int d  = ch & (D_INNER - 1);

    float A  = -__expf(A_log[d * D_STATE + n]);
    float Dd = Dw[d];

    const float* xdbl_b = xdbl + (size_t)b * SEQLEN * XDBL_COLS;
    const float* dt_b   = dt   + (size_t)b * SEQLEN * D_INNER + d;
    const float* xc_b   = xc   + (size_t)b * SEQLEN * D_INNER + d;
    const float* z_b    = xz   + (size_t)b * SEQLEN * (2 * D_INNER) + D_INNER + d;
    float*       y_b    = y    + (size_t)b * SEQLEN * D_INNER + d;

    float h = 0.f;
    for (int l = 0; l < SEQLEN; l++) {
        float dtv = dt_b[(size_t)l * D_INNER];
        float xcv = xc_b[(size_t)l * D_INNER];
        float Bv  = xdbl_b[l * XDBL_COLS + DT_RANK + n];
        float Cv  = xdbl_b[l * XDBL_COLS + DT_RANK + D_STATE + n];

        float dA = __expf(dtv * A);
        h = fmaf(dA, h, dtv * xcv * Bv);

        float p = h * Cv;
        p += __shfl_xor_sync(0xffffffffu, p, 8);
        p += __shfl_xor_sync(0xffffffffu, p, 4);
        p += __shfl_xor_sync(0xffffffffu, p, 2);
        p += __shfl_xor_sync(0xffffffffu, p, 1);

        if (n == 0) {
            float zv  = z_b[(size_t)l * (2 * D_INNER)];
            float sil = zv / (1.0f + __expf(-zv));
            y_b[(size_t)l * D_INNER] = (p + Dd * xcv) * sil;
        }
    }
}

// ---------------------------------------------------------------------------
// Launch
// ---------------------------------------------------------------------------
extern "C" void kernel_launch(void* const* d_in, const int* in_sizes, int n_in,
                              void* d_out, int out_size)
{
    const float* hidden   = (const float*)d_in[0];
    const float* norm_w   = (const float*)d_in[1];
    const float* in_proj  = (const float*)d_in[2];
    const float* conv_w   = (const float*)d_in[3];
    const float* conv_b   = (const float*)d_in[4];
    const float* x_proj   = (const float*)d_in[5];
    const float* dt_proj  = (const float*)d_in[6];
    const float* dt_b     = (const float*)d_in[7];
    const float* A_log    = (const float*)d_in[8];
    const float* Dw       = (const float*)d_in[9];
    const float* out_proj = (const float*)d_in[10];

    float* out = (float*)d_out;

    float *h, *xz, *xc, *xpart, *xdbl, *dt, *y;
    cudaGetSymbolAddress((void**)&h,     g_h);
    cudaGetSymbolAddress((void**)&xz,    g_xz);
    cudaGetSymbolAddress((void**)&xc,    g_xc);
    cudaGetSymbolAddress((void**)&xpart, g_xpart);
    cudaGetSymbolAddress((void**)&xdbl,  g_xdbl);
    cudaGetSymbolAddress((void**)&dt,    g_dt);
    cudaGetSymbolAddress((void**)&y,     g_y);

    cudaFuncSetAttribute(gemm_f2<0>, cudaFuncAttributeMaxDynamicSharedMemorySize, GEMM_SMEM);
    cudaFuncSetAttribute(gemm_f2<1>, cudaFuncAttributeMaxDynamicSharedMemorySize, GEMM_SMEM);

    // 1. RMSNorm
    rmsnorm_kernel<<<ROWS, 256>>>(hidden, norm_w, h);

    // 2. in_proj: (2048 x 1024) @ (4096 x 1024)^T -> xz (2048 x 4096)
    gemm_f2<0><<<dim3(2 * D_INNER / 64, ROWS / 128, 1), 256, GEMM_SMEM>>>(
        h, D_MODEL, in_proj, D_MODEL, xz, 2 * D_INNER,
        2 * D_INNER, D_MODEL, 0, nullptr);

    // 3. conv + silu
    conv_silu_kernel<<<(ROWS * D_INNER) / 256, 256>>>(xz, conv_w, conv_b, xc);

    // 4. x_proj split-K: (2048 x 2048) @ (96 x 2048)^T -> 8 partials (2048 x 96)
    gemm_f2<0><<<dim3(2, ROWS / 128, XP_SPLITS), 256, GEMM_SMEM>>>(
        xc, D_INNER, x_proj, D_INNER, xpart, XDBL_COLS,
        XDBL_COLS, XP_KSPL, (long long)ROWS * XDBL_COLS, nullptr);

    // 4b. reduce partials
    xp_reduce_kernel<<<(ROWS * XDBL_COLS + 255) / 256, 256>>>();

    // 5. dt_proj + softplus: (2048 x 96[:64]) @ (2048 x 64)^T -> dt (2048 x 2048)
    gemm_f2<1><<<dim3(D_INNER / 64, ROWS / 128, 1), 256, GEMM_SMEM>>>(
        xdbl, XDBL_COLS, dt_proj, DT_RANK, dt, D_INNER,
        D_INNER, DT_RANK, 0, dt_b);

    // 6. selective scan + gate
    scan_kernel<<<(BATCH * D_INNER * D_STATE) / 128, 128>>>(
        xdbl, dt, xc, xz, A_log, Dw, y);

    // 7. out_proj: (2048 x 2048) @ (1024 x 2048)^T -> out (2048 x 1024)
    gemm_f2<0><<<dim3(D_MODEL / 64, ROWS / 128, 1), 256, GEMM_SMEM>>>(
        y, D_INNER, out_proj, D_INNER, out, D_MODEL,
        D_MODEL, D_INNER, 0, nullptr);

    // 8. residual
    size_t half = (size_t)out_size / 2;
    cudaMemcpyAsync(out + half, hidden, half * sizeof(float),
                    cudaMemcpyDeviceToDevice);
}

// round 6
// speedup vs baseline: 2.8213x; 2.8213x over previous
#include <cuda_runtime.h>
#include <cuda_fp16.h>
#include <math.h>
#include <stdint.h>

// ---------------------------------------------------------------------------
// Problem constants
// ---------------------------------------------------------------------------
#define D_MODEL   1024
#define D_STATE   16
#define D_CONV    4
#define D_INNER   2048
#define DT_RANK   64
#define BATCH     2
#define SEQLEN    1024
#define ROWS      (BATCH * SEQLEN)          // 2048
#define XDBL_COLS (DT_RANK + 2 * D_STATE)   // 96
#define EPS       1e-5f

#define XP_SPLITS 8
#define XP_KSPL   (D_INNER / XP_SPLITS)     // 256

// ---------------------------------------------------------------------------
// Scratch (__device__ globals; no cudaMalloc allowed)
// ---------------------------------------------------------------------------
__device__ __half g_ht  [ROWS * D_MODEL];        // rmsnorm out (fp16)
__device__ float  g_xz  [ROWS * 2 * D_INNER];    // in_proj out (x | z) fp32
__device__ float  g_xc  [ROWS * D_INNER];        // conv+silu fp32 (scan)
__device__ __half g_xct [ROWS * D_INNER];        // conv+silu fp16 (x_proj A)
__device__ float  g_xpart[XP_SPLITS * ROWS * XDBL_COLS]; // split-K partials
__device__ float  g_xdbl [ROWS * XDBL_COLS];     // x_proj out fp32 (scan B,C)
__device__ __half g_xdblt[ROWS * XDBL_COLS];     // x_proj out fp16 (dt A)
__device__ float  g_dt  [ROWS * D_INNER];        // softplus(dt) fp32
__device__ __half g_yt  [ROWS * D_INNER];        // scan out fp16 (out_proj A)
__device__ __half g_wi  [2 * D_INNER * D_MODEL]; // fp16 weights
__device__ __half g_wo  [D_MODEL * D_INNER];
__device__ __half g_wx  [XDBL_COLS * D_INNER];
__device__ __half g_wd  [D_INNER * DT_RANK];

// ---------------------------------------------------------------------------
// Helpers
// ---------------------------------------------------------------------------
__device__ __forceinline__ float softplusf(float v)
{
    return v > 20.f ? v : log1pf(__expf(v));
}

__device__ __forceinline__ void mma_f16(float c[4], const uint32_t a[4],
                                        const uint32_t b0, const uint32_t b1)
{
    asm volatile(
        "mma.sync.aligned.m16n8k16.row.col.f32.f16.f16.f32 "
        "{%0,%1,%2,%3}, {%4,%5,%6,%7}, {%8,%9}, {%0,%1,%2,%3};"
        : "+f"(c[0]), "+f"(c[1]), "+f"(c[2]), "+f"(c[3])
        : "r"(a[0]), "r"(a[1]), "r"(a[2]), "r"(a[3]), "r"(b0), "r"(b1));
}

#define LDSM_X4(r0, r1, r2, r3, addr) \
    asm volatile("ldmatrix.sync.aligned.m8n8.x4.shared.b16 {%0,%1,%2,%3}, [%4];" \
                 : "=r"(r0), "=r"(r1), "=r"(r2), "=r"(r3) : "r"(addr))

// ---------------------------------------------------------------------------
// Weight pre-conversion (fp32 -> fp16)
// ---------------------------------------------------------------------------
#define NWI (2 * D_INNER * D_MODEL)
#define NWO (D_MODEL * D_INNER)
#define NWX (XDBL_COLS * D_INNER)
#define NWD (D_INNER * DT_RANK)
#define NW_TOTAL (NWI + NWO + NWX + NWD)

__global__ __launch_bounds__(256)
void cvt_weights_kernel(const float* __restrict__ wi, const float* __restrict__ wo,
                        const float* __restrict__ wx, const float* __restrict__ wd)
{
    int i = blockIdx.x * 256 + threadIdx.x;
    if (i < NWI)                       g_wi[i] = __float2half_rn(wi[i]);
    else if (i < NWI + NWO)            g_wo[i - NWI] = __float2half_rn(wo[i - NWI]);
    else if (i < NWI + NWO + NWX)      g_wx[i - NWI - NWO] = __float2half_rn(wx[i - NWI - NWO]);
    else if (i < NW_TOTAL)             g_wd[i - NWI - NWO - NWX] = __float2half_rn(wd[i - NWI - NWO - NWX]);
}

// ---------------------------------------------------------------------------
// RMSNorm -> fp16
// ---------------------------------------------------------------------------
__global__ __launch_bounds__(256)
void rmsnorm_kernel(const float* __restrict__ x, const float* __restrict__ w,
                    __half* __restrict__ out)
{
    int r = blockIdx.x;
    int t = threadIdx.x;
    const float4* xr = (const float4*)(x + (size_t)r * D_MODEL);
    float4 v = xr[t];
    float s = v.x * v.x + v.y * v.y + v.z * v.z + v.w * v.w;
    #pragma unroll
    for (int o = 16; o; o >>= 1) s += __shfl_xor_sync(0xffffffffu, s, o);

    __shared__ float ws[8];
    __shared__ float s_inv;
    if ((t & 31) == 0) ws[t >> 5] = s;
    __syncthreads();
    if (t == 0) {
        float tot = 0.f;
        #pragma unroll
        for (int i = 0; i < 8; i++) tot += ws[i];
        float rms = sqrtf(tot) * (1.0f / 32.0f);
        s_inv = 1.0f / (rms + EPS);
    }
    __syncthreads();
    float inv = s_inv;
    float4 wv = ((const float4*)w)[t];
    __half2 h0 = __floats2half2_rn(v.x * inv * wv.x, v.y * inv * wv.y);
    __half2 h1 = __floats2half2_rn(v.z * inv * wv.z, v.w * inv * wv.w);
    uint2 o;
    o.x = *(unsigned*)&h0;
    o.y = *(unsigned*)&h1;
    ((uint2*)(out + (size_t)r * D_MODEL))[t] = o;
}

// ---------------------------------------------------------------------------
// FP16 HMMA GEMM:  C[m][n] = sum_k A[m][k] * B[n][k]   (fp32 accumulate)
// Block tile 128x128, BK=32, 3-stage cp.async, 8 warps = 2(M) x 4(N), each 64x32.
// ldmatrix.x4 fragments, smem row stride 40 halfs (80 B, conflict-free).
// EPI: 0 = fp32 store; 1 = softplus(acc+bias) fp32; 2 = fp32 + fp16 dup.
// split-K via blockIdx.z: k in [z*k_len, (z+1)*k_len), C += z*split_cstride.
// Requires M % 128 == 0, k_len % 32 == 0, N % 2 == 0. N guarded.
// ---------------------------------------------------------------------------
#define BK        32
#define STG       3
#define RHALFS    40
#define RB        80                         // row bytes in smem
#define A_BYTES   (128 * RB)                 // 10240
#define STAGE_B   (2 * A_BYTES)              // 20480
#define GEMM_SMEM (STG * STAGE_B)            // 61440

template<int EPI>
__global__ __launch_bounds__(256, 2)
void gemm_h(const __half* __restrict__ A, int lda,
            const __half* __restrict__ B, int ldb,
            float* __restrict__ C, int ldc,
            __half* __restrict__ Caux,
            int N, int k_len, long long split_cstride,
            const float* __restrict__ bias)
{
    extern __shared__ unsigned char smem_raw[];
    const uint32_t smem = (uint32_t)__cvta_generic_to_shared(smem_raw);

    const int tid  = threadIdx.x;
    const int wid  = tid >> 5;
    const int lane = tid & 31;
    const int wm   = (wid & 1) * 64;
    const int wn   = (wid >> 1) * 32;

    const int bm = blockIdx.y * 128;
    const int bn = blockIdx.x * 128;
    const int k0base = blockIdx.z * k_len;
    C += (size_t)blockIdx.z * split_cstride;
    const int ktiles = k_len / BK;

    // ---- stage loader: A/B 128 rows x 32 halfs (64 B) each, 16B cp.async
    auto load_stage = [&](int stage, int kt) {
        const int k0 = k0base + kt * BK;
        const uint32_t sa = smem + stage * STAGE_B;
        const uint32_t sb = sa + A_BYTES;
        #pragma unroll
        for (int i = 0; i < 2; i++) {
            int lin = i * 256 + tid;         // 0..511
            int c   = lin & 3;
            int row = lin >> 2;              // 0..127
            uint32_t dst = sa + row * RB + c * 16;
            const __half* src = A + (size_t)(bm + row) * lda + k0 + c * 8;
            asm volatile("cp.async.cg.shared.global [%0], [%1], 16;"
                         :: "r"(dst), "l"(src));
        }
        #pragma unroll
        for (int i = 0; i < 2; i++) {
            int lin = i * 256 + tid;
            int c   = lin & 3;
            int row = lin >> 2;
            int gn  = bn + row;
            uint32_t dst = sb + row * RB + c * 16;
            const __half* src = B + (size_t)(gn < N ? gn : 0) * ldb + k0 + c * 8;
            int ok = (gn < N) ? 16 : 0;
            asm volatile("cp.async.cg.shared.global [%0], [%1], 16, %2;"
                         :: "r"(dst), "l"(src), "r"(ok));
        }
    };

    float acc[4][4][4];
    #pragma unroll
    for (int i = 0; i < 4; i++)
        #pragma unroll
        for (int j = 0; j < 4; j++)
            #pragma unroll
            for (int q = 0; q < 4; q++) acc[i][j][q] = 0.f;

    load_stage(0, 0);
    asm volatile("cp.async.commit_group;");
    if (ktiles > 1) load_stage(1, 1);
    asm volatile("cp.async.commit_group;");

    // fragment address components (constant across ktiles)
    const int a_row = ((lane >> 3) & 1) * 8 + (lane & 7);   // + mt*16 + wm
    const int a_kc  = (lane >> 4) * 8;                       // + ks*16
    const int b_row = (lane >> 4) * 8 + (lane & 7);          // + np*16 + wn
    const int b_kc  = ((lane >> 3) & 1) * 8;                 // + ks*16

    for (int kt = 0; kt < ktiles; kt++) {
        if (kt >= ktiles - 1) asm volatile("cp.async.wait_group 0;");
        else                  asm volatile("cp.async.wait_group 1;");
        __syncthreads();

        const uint32_t Ab = smem + (kt % STG) * STAGE_B;
        const uint32_t Bb = Ab + A_BYTES;

        #pragma unroll
        for (int ks = 0; ks < 2; ks++) {
            uint32_t a[4][4], b[4][2];
            #pragma unroll
            for (int mt = 0; mt < 4; mt++) {
                uint32_t ad = Ab + (wm + mt * 16 + a_row) * RB + (ks * 16 + a_kc) * 2;
                LDSM_X4(a[mt][0], a[mt][1], a[mt][2], a[mt][3], ad);
            }
            #pragma unroll
            for (int np = 0; np < 2; np++) {
                uint32_t bd = Bb + (wn + np * 16 + b_row) * RB + (ks * 16 + b_kc) * 2;
                LDSM_X4(b[2 * np][0], b[2 * np][1], b[2 * np + 1][0], b[2 * np + 1][1], bd);
            }
            #pragma unroll
            for (int mt = 0; mt < 4; mt++)
                #pragma unroll
                for (int nt = 0; nt < 4; nt++)
                    mma_f16(acc[mt][nt], a[mt], b[nt][0], b[nt][1]);
        }
        __syncthreads();

        if (kt + 2 < ktiles) load_stage((kt + 2) % STG, kt + 2);
        asm volatile("cp.async.commit_group;");
    }

    // ---- epilogue
    const int g4 = lane >> 2;
    const int t2 = (lane & 3) * 2;
    #pragma unroll
    for (int mt = 0; mt < 4; mt++) {
        int gm = bm + wm + mt * 16 + g4;
        #pragma unroll
        for (int nt = 0; nt < 4; nt++) {
            int gn = bn + wn + nt * 8 + t2;
            if (gn < N) {
                float2 v0 = make_float2(acc[mt][nt][0], acc[mt][nt][1]);
                float2 v1 = make_float2(acc[mt][nt][2], acc[mt][nt][3]);
                if (EPI == 1) {
                    float b0 = bias[gn], b1 = bias[gn + 1];
                    v0.x = softplusf(v0.x + b0);
                    v0.y = softplusf(v0.y + b1);
                    v1.x = softplusf(v1.x + b0);
                    v1.y = softplusf(v1.y + b1);
                }
                *(float2*)(C + (size_t)gm * ldc + gn)       = v0;
                *(float2*)(C + (size_t)(gm + 8) * ldc + gn) = v1;
                if (EPI == 2) {
                    __half2 h0 = __floats2half2_rn(v0.x, v0.y);
                    __half2 h1 = __floats2half2_rn(v1.x, v1.y);
                    *(__half2*)(Caux + (size_t)gm * ldc + gn)       = h0;
                    *(__half2*)(Caux + (size_t)(gm + 8) * ldc + gn) = h1;
                }
            }
        }
    }
}

// ---------------------------------------------------------------------------
// x_proj split-K reduce: sum 8 partials -> fp32 + fp16
// ---------------------------------------------------------------------------
__global__ __launch_bounds__(256)
void xp_reduce_kernel()
{
    int i = blockIdx.x * 256 + threadIdx.x;
    if (i >= ROWS * XDBL_COLS) return;
    float s = 0.f;
    #pragma unroll
    for (int p = 0; p < XP_SPLITS; p++)
        s += g_xpart[(size_t)p * ROWS * XDBL_COLS + i];
    g_xdbl[i]  = s;
    g_xdblt[i] = __float2half_rn(s);
}

// ---------------------------------------------------------------------------
// Depthwise causal conv + bias + SiLU -> fp32 (scan) + fp16 (x_proj A)
// ---------------------------------------------------------------------------
__global__ __launch_bounds__(256)
void conv_silu_kernel(const float* __restrict__ xz,
                      const float* __restrict__ cw,
                      const float* __restrict__ cb,
                      float* __restrict__ xc,
                      __half* __restrict__ xct)
{
    int idx = blockIdx.x * blockDim.x + threadIdx.x;
    if (idx >= ROWS * D_INNER) return;
    int d = idx & (D_INNER - 1);
    int r = idx >> 11;
    int l = r & (SEQLEN - 1);
    int b = r >> 10;

    float acc = cb[d];
    #pragma unroll
    for (int k = 0; k < D_CONV; k++) {
        int ls = l + k - (D_CONV - 1);
        if (ls >= 0)
            acc = fmaf(xz[((size_t)(b * SEQLEN + ls)) * (2 * D_INNER) + d],
                       cw[d * D_CONV + k], acc);
    }
    float sig = 1.0f / (1.0f + __expf(-acc));
    float v = acc * sig;
    xc[idx]  = v;
    xct[idx] = __float2half_rn(v);
}

// ---------------------------------------------------------------------------
// Selective scan. 16 lanes per (b,d) channel. Output fp16 (feeds out_proj).
// ---------------------------------------------------------------------------
__global__ __launch_bounds__(128)
void scan_kernel(const float* __restrict__ xdbl,
                 const float* __restrict__ dt,
                 const float* __restrict__ xc,
                 const float* __restrict__ xz,
                 const float* __restrict__ A_log,
                 const float* __restrict__ Dw,
                 __half* __restrict__ y)
{
    int t = blockIdx.x * blockDim.x + threadIdx.x;
    int n  = t & (D_STATE - 1);
    int ch = t >> 4;
    int b  = ch >> 11;
    int d  = ch & (D_INNER - 1);

    float A  = -__expf(A_log[d * D_STATE + n]);
    float Dd = Dw[d];

    const float* xdbl_b = xdbl + (size_t)b * SEQLEN * XDBL_COLS;
    const float* dt_b   = dt   + (size_t)b * SEQLEN * D_INNER + d;
    const float* xc_b   = xc   + (size_t)b * SEQLEN * D_INNER + d;
    const float* z_b    = xz   + (size_t)b * SEQLEN * (2 * D_INNER) + D_INNER + d;
    __half*      y_b    = y    + (size_t)b * SEQLEN * D_INNER + d;

    float h = 0.f;
    for (int l = 0; l < SEQLEN; l++) {
        float dtv = dt_b[(size_t)l * D_INNER];
        float xcv = xc_b[(size_t)l * D_INNER];
        float Bv  = xdbl_b[l * XDBL_COLS + DT_RANK + n];
        float Cv  = xdbl_b[l * XDBL_COLS + DT_RANK + D_STATE + n];

        float dA = __expf(dtv * A);
        h = fmaf(dA, h, dtv * xcv * Bv);

        float p = h * Cv;
        p += __shfl_xor_sync(0xffffffffu, p, 8);
        p += __shfl_xor_sync(0xffffffffu, p, 4);
        p += __shfl_xor_sync(0xffffffffu, p, 2);
        p += __shfl_xor_sync(0xffffffffu, p, 1);

        if (n == 0) {
            float zv  = z_b[(size_t)l * (2 * D_INNER)];
            float sil = zv / (1.0f + __expf(-zv));
            y_b[(size_t)l * D_INNER] = __float2half_rn((p + Dd * xcv) * sil);
        }
    }
}

// ---------------------------------------------------------------------------
// Launch
// ---------------------------------------------------------------------------
extern "C" void kernel_launch(void* const* d_in, const int* in_sizes, int n_in,
                              void* d_out, int out_size)
{
    const float* hidden   = (const float*)d_in[0];
    const float* norm_w   = (const float*)d_in[1];
    const float* in_proj  = (const float*)d_in[2];
    const float* conv_w   = (const float*)d_in[3];
    const float* conv_b   = (const float*)d_in[4];
    const float* x_proj   = (const float*)d_in[5];
    const float* dt_proj  = (const float*)d_in[6];
    const float* dt_b     = (const float*)d_in[7];
    const float* A_log    = (const float*)d_in[8];
    const float* Dw       = (const float*)d_in[9];
    const float* out_proj = (const float*)d_in[10];

    float* out = (float*)d_out;

    __half *ht, *xct, *xdblt, *yt, *wi, *wo, *wx, *wd;
    float *xz, *xc, *xpart, *xdbl, *dt;
    cudaGetSymbolAddress((void**)&ht,    g_ht);
    cudaGetSymbolAddress((void**)&xz,    g_xz);
    cudaGetSymbolAddress((void**)&xc,    g_xc);
    cudaGetSymbolAddress((void**)&xct,   g_xct);
    cudaGetSymbolAddress((void**)&xpart, g_xpart);
    cudaGetSymbolAddress((void**)&xdbl,  g_xdbl);
    cudaGetSymbolAddress((void**)&xdblt, g_xdblt);
    cudaGetSymbolAddress((void**)&dt,    g_dt);
    cudaGetSymbolAddress((void**)&yt,    g_yt);
    cudaGetSymbolAddress((void**)&wi,    g_wi);
    cudaGetSymbolAddress((void**)&wo,    g_wo);
    cudaGetSymbolAddress((void**)&wx,    g_wx);
    cudaGetSymbolAddress((void**)&wd,    g_wd);

    cudaFuncSetAttribute(gemm_h<0>, cudaFuncAttributeMaxDynamicSharedMemorySize, GEMM_SMEM);
    cudaFuncSetAttribute(gemm_h<1>, cudaFuncAttributeMaxDynamicSharedMemorySize, GEMM_SMEM);
    cudaFuncSetAttribute(gemm_h<2>, cudaFuncAttributeMaxDynamicSharedMemorySize, GEMM_SMEM);

    // 0. weight conversion (fp16)
    cvt_weights_kernel<<<(NW_TOTAL + 255) / 256, 256>>>(in_proj, out_proj, x_proj, dt_proj);

    // 1. RMSNorm -> fp16
    rmsnorm_kernel<<<ROWS, 256>>>(hidden, norm_w, ht);

    // 2. in_proj: (2048 x 1024) @ (4096 x 1024)^T -> xz (2048 x 4096) fp32
    gemm_h<0><<<dim3(2 * D_INNER / 128, ROWS / 128, 1), 256, GEMM_SMEM>>>(
        ht, D_MODEL, wi, D_MODEL, xz, 2 * D_INNER, nullptr,
        2 * D_INNER, D_MODEL, 0, nullptr);

    // 3. conv + silu -> xc fp32 + xct fp16
    conv_silu_kernel<<<(ROWS * D_INNER) / 256, 256>>>(xz, conv_w, conv_b, xc, xct);

    // 4. x_proj split-K: (2048 x 2048) @ (96 x 2048)^T -> 8 partials
    gemm_h<0><<<dim3(1, ROWS / 128, XP_SPLITS), 256, GEMM_SMEM>>>(
        xct, D_INNER, wx, D_INNER, xpart, XDBL_COLS, nullptr,
        XDBL_COLS, XP_KSPL, (long long)ROWS * XDBL_COLS, nullptr);

    // 4b. reduce -> xdbl fp32 + xdblt fp16
    xp_reduce_kernel<<<(ROWS * XDBL_COLS + 255) / 256, 256>>>();

    // 5. dt_proj + softplus: (2048 x 96[:64]) @ (2048 x 64)^T -> dt fp32
    gemm_h<1><<<dim3(D_INNER / 128, ROWS / 128, 1), 256, GEMM_SMEM>>>(
        xdblt, XDBL_COLS, wd, DT_RANK, dt, D_INNER, nullptr,
        D_INNER, DT_RANK, 0, dt_b);

    // 6. selective scan + gate -> yt fp16
    scan_kernel<<<(BATCH * D_INNER * D_STATE) / 128, 128>>>(
        xdbl, dt, xc, xz, A_log, Dw, yt);

    // 7. out_proj: (2048 x 2048) @ (1024 x 2048)^T -> out fp32
    gemm_h<0><<<dim3(D_MODEL / 128, ROWS / 128, 1), 256, GEMM_SMEM>>>(
        yt, D_INNER, wo, D_INNER, out, D_MODEL, nullptr,
        D_MODEL, D_INNER, 0, nullptr);

    // 8. residual
    size_t half = (size_t)out_size / 2;
    cudaMemcpyAsync(out + half, hidden, half * sizeof(float),
                    cudaMemcpyDeviceToDevice);
}

// round 7
// speedup vs baseline: 4.5041x; 1.5965x over previous
#include <cuda_runtime.h>
#include <cuda_fp16.h>
#include <math.h>
#include <stdint.h>

// ---------------------------------------------------------------------------
// Problem constants
// ---------------------------------------------------------------------------
#define D_MODEL   1024
#define D_STATE   16
#define D_CONV    4
#define D_INNER   2048
#define DT_RANK   64
#define BATCH     2
#define SEQLEN    1024
#define ROWS      (BATCH * SEQLEN)          // 2048
#define XDBL_COLS (DT_RANK + 2 * D_STATE)   // 96
#define EPS       1e-5f

#define XP_SPLITS 8
#define XP_KSPL   (D_INNER / XP_SPLITS)     // 256

// ---------------------------------------------------------------------------
// Scratch (__device__ globals; no cudaMalloc allowed)
// ---------------------------------------------------------------------------
__device__ __half g_ht  [ROWS * D_MODEL];        // rmsnorm out (fp16)
__device__ float  g_xz  [ROWS * 2 * D_INNER];    // in_proj out (x | z) fp32
__device__ float  g_xc  [ROWS * D_INNER];        // conv+silu fp32 (scan)
__device__ __half g_xct [ROWS * D_INNER];        // conv+silu fp16 (x_proj A)
__device__ float  g_xpart[XP_SPLITS * ROWS * XDBL_COLS]; // split-K partials
__device__ float  g_xdbl [ROWS * XDBL_COLS];     // x_proj out fp32 (scan B,C)
__device__ __half g_xdblt[ROWS * XDBL_COLS];     // x_proj out fp16 (dt A)
__device__ float  g_dt  [ROWS * D_INNER];        // softplus(dt) fp32
__device__ __half g_yt  [ROWS * D_INNER];        // scan out fp16 (out_proj A)
__device__ __half g_wi  [2 * D_INNER * D_MODEL]; // fp16 weights
__device__ __half g_wo  [D_MODEL * D_INNER];
__device__ __half g_wx  [XDBL_COLS * D_INNER];
__device__ __half g_wd  [D_INNER * DT_RANK];

// ---------------------------------------------------------------------------
// Helpers
// ---------------------------------------------------------------------------
__device__ __forceinline__ float softplusf(float v)
{
    return v > 20.f ? v : log1pf(__expf(v));
}

__device__ __forceinline__ void mma_f16(float c[4], const uint32_t a[4],
                                        const uint32_t b0, const uint32_t b1)
{
    asm volatile(
        "mma.sync.aligned.m16n8k16.row.col.f32.f16.f16.f32 "
        "{%0,%1,%2,%3}, {%4,%5,%6,%7}, {%8,%9}, {%0,%1,%2,%3};"
        : "+f"(c[0]), "+f"(c[1]), "+f"(c[2]), "+f"(c[3])
        : "r"(a[0]), "r"(a[1]), "r"(a[2]), "r"(a[3]), "r"(b0), "r"(b1));
}

#define LDSM_X4(r0, r1, r2, r3, addr) \
    asm volatile("ldmatrix.sync.aligned.m8n8.x4.shared.b16 {%0,%1,%2,%3}, [%4];" \
                 : "=r"(r0), "=r"(r1), "=r"(r2), "=r"(r3) : "r"(addr))

// ---------------------------------------------------------------------------
// Weight pre-conversion (fp32 -> fp16)
// ---------------------------------------------------------------------------
#define NWI (2 * D_INNER * D_MODEL)
#define NWO (D_MODEL * D_INNER)
#define NWX (XDBL_COLS * D_INNER)
#define NWD (D_INNER * DT_RANK)
#define NW_TOTAL (NWI + NWO + NWX + NWD)

__global__ __launch_bounds__(256)
void cvt_weights_kernel(const float* __restrict__ wi, const float* __restrict__ wo,
                        const float* __restrict__ wx, const float* __restrict__ wd)
{
    int i = blockIdx.x * 256 + threadIdx.x;
    if (i < NWI)                       g_wi[i] = __float2half_rn(wi[i]);
    else if (i < NWI + NWO)            g_wo[i - NWI] = __float2half_rn(wo[i - NWI]);
    else if (i < NWI + NWO + NWX)      g_wx[i - NWI - NWO] = __float2half_rn(wx[i - NWI - NWO]);
    else if (i < NW_TOTAL)             g_wd[i - NWI - NWO - NWX] = __float2half_rn(wd[i - NWI - NWO - NWX]);
}

// ---------------------------------------------------------------------------
// RMSNorm -> fp16
// ---------------------------------------------------------------------------
__global__ __launch_bounds__(256)
void rmsnorm_kernel(const float* __restrict__ x, const float* __restrict__ w,
                    __half* __restrict__ out)
{
    int r = blockIdx.x;
    int t = threadIdx.x;
    const float4* xr = (const float4*)(x + (size_t)r * D_MODEL);
    float4 v = xr[t];
    float s = v.x * v.x + v.y * v.y + v.z * v.z + v.w * v.w;
    #pragma unroll
    for (int o = 16; o; o >>= 1) s += __shfl_xor_sync(0xffffffffu, s, o);

    __shared__ float ws[8];
    __shared__ float s_inv;
    if ((t & 31) == 0) ws[t >> 5] = s;
    __syncthreads();
    if (t == 0) {
        float tot = 0.f;
        #pragma unroll
        for (int i = 0; i < 8; i++) tot += ws[i];
        float rms = sqrtf(tot) * (1.0f / 32.0f);
        s_inv = 1.0f / (rms + EPS);
    }
    __syncthreads();
    float inv = s_inv;
    float4 wv = ((const float4*)w)[t];
    __half2 h0 = __floats2half2_rn(v.x * inv * wv.x, v.y * inv * wv.y);
    __half2 h1 = __floats2half2_rn(v.z * inv * wv.z, v.w * inv * wv.w);
    uint2 o;
    o.x = *(unsigned*)&h0;
    o.y = *(unsigned*)&h1;
    ((uint2*)(out + (size_t)r * D_MODEL))[t] = o;
}

// ---------------------------------------------------------------------------
// FP16 HMMA GEMM:  C[m][n] = sum_k A[m][k] * B[n][k]   (fp32 accumulate)
// Block tile 128x64, BK=32, 3-stage cp.async, 8 warps = 4(M) x 2(N), each 32x32.
// 3 CTAs/SM for latency hiding. ldmatrix.x4 fragments, smem stride 80 B.
// EPI: 0 = fp32 store; 1 = softplus(acc+bias) fp32; 2 = fp32 + fp16 dup.
// split-K via blockIdx.z. Requires M % 128 == 0, k_len % 32 == 0. N guarded.
// ---------------------------------------------------------------------------
#define BK        32
#define STG       3
#define RB        80                         // smem row bytes (40 halfs)
#define A_BYTES   (128 * RB)                 // 10240
#define B_BYTES   (64 * RB)                  // 5120
#define STAGE_B   (A_BYTES + B_BYTES)        // 15360
#define GEMM_SMEM (STG * STAGE_B)            // 46080

template<int EPI>
__global__ __launch_bounds__(256, 3)
void gemm_h(const __half* __restrict__ A, int lda,
            const __half* __restrict__ B, int ldb,
            float* __restrict__ C, int ldc,
            __half* __restrict__ Caux,
            int N, int k_len, long long split_cstride,
            const float* __restrict__ bias)
{
    extern __shared__ unsigned char smem_raw[];
    const uint32_t smem = (uint32_t)__cvta_generic_to_shared(smem_raw);

    const int tid  = threadIdx.x;
    const int wid  = tid >> 5;
    const int lane = tid & 31;
    const int wm   = (wid & 3) * 32;     // 4 warps along M
    const int wn   = (wid >> 2) * 32;    // 2 warps along N

    const int bm = blockIdx.y * 128;
    const int bn = blockIdx.x * 64;
    const int k0base = blockIdx.z * k_len;
    C += (size_t)blockIdx.z * split_cstride;
    const int ktiles = k_len / BK;

    // ---- stage loader: A 128 rows x 64 B, B 64 rows x 64 B, 16B cp.async
    auto load_stage = [&](int stage, int kt) {
        const int k0 = k0base + kt * BK;
        const uint32_t sa = smem + stage * STAGE_B;
        const uint32_t sb = sa + A_BYTES;
        #pragma unroll
        for (int i = 0; i < 2; i++) {
            int lin = i * 256 + tid;         // 0..511
            int c   = lin & 3;
            int row = lin >> 2;              // 0..127
            uint32_t dst = sa + row * RB + c * 16;
            const __half* src = A + (size_t)(bm + row) * lda + k0 + c * 8;
            asm volatile("cp.async.cg.shared.global [%0], [%1], 16;"
                         :: "r"(dst), "l"(src));
        }
        {
            int c   = tid & 3;
            int row = tid >> 2;              // 0..63
            int gn  = bn + row;
            uint32_t dst = sb + row * RB + c * 16;
            const __half* src = B + (size_t)(gn < N ? gn : 0) * ldb + k0 + c * 8;
            int ok = (gn < N) ? 16 : 0;
            asm volatile("cp.async.cg.shared.global [%0], [%1], 16, %2;"
                         :: "r"(dst), "l"(src), "r"(ok));
        }
    };

    float acc[2][4][4];
    #pragma unroll
    for (int i = 0; i < 2; i++)
        #pragma unroll
        for (int j = 0; j < 4; j++)
            #pragma unroll
            for (int q = 0; q < 4; q++) acc[i][j][q] = 0.f;

    load_stage(0, 0);
    asm volatile("cp.async.commit_group;");
    if (ktiles > 1) load_stage(1, 1);
    asm volatile("cp.async.commit_group;");

    // fragment address components
    const int a_row = ((lane >> 3) & 1) * 8 + (lane & 7);
    const int a_kc  = (lane >> 4) * 8;
    const int b_row = (lane >> 4) * 8 + (lane & 7);
    const int b_kc  = ((lane >> 3) & 1) * 8;

    for (int kt = 0; kt < ktiles; kt++) {
        if (kt >= ktiles - 1) asm volatile("cp.async.wait_group 0;");
        else                  asm volatile("cp.async.wait_group 1;");
        __syncthreads();

        const uint32_t Ab = smem + (kt % STG) * STAGE_B;
        const uint32_t Bb = Ab + A_BYTES;

        #pragma unroll
        for (int ks = 0; ks < 2; ks++) {
            uint32_t a[2][4], b[4][2];
            #pragma unroll
            for (int mt = 0; mt < 2; mt++) {
                uint32_t ad = Ab + (wm + mt * 16 + a_row) * RB + (ks * 16 + a_kc) * 2;
                LDSM_X4(a[mt][0], a[mt][1], a[mt][2], a[mt][3], ad);
            }
            #pragma unroll
            for (int np = 0; np < 2; np++) {
                uint32_t bd = Bb + (wn + np * 16 + b_row) * RB + (ks * 16 + b_kc) * 2;
                LDSM_X4(b[2 * np][0], b[2 * np][1], b[2 * np + 1][0], b[2 * np + 1][1], bd);
            }
            #pragma unroll
            for (int mt = 0; mt < 2; mt++)
                #pragma unroll
                for (int nt = 0; nt < 4; nt++)
                    mma_f16(acc[mt][nt], a[mt], b[nt][0], b[nt][1]);
        }
        __syncthreads();

        if (kt + 2 < ktiles) load_stage((kt + 2) % STG, kt + 2);
        asm volatile("cp.async.commit_group;");
    }

    // ---- epilogue
    const int g4 = lane >> 2;
    const int t2 = (lane & 3) * 2;
    #pragma unroll
    for (int mt = 0; mt < 2; mt++) {
        int gm = bm + wm + mt * 16 + g4;
        #pragma unroll
        for (int nt = 0; nt < 4; nt++) {
            int gn = bn + wn + nt * 8 + t2;
            if (gn < N) {
                float2 v0 = make_float2(acc[mt][nt][0], acc[mt][nt][1]);
                float2 v1 = make_float2(acc[mt][nt][2], acc[mt][nt][3]);
                if (EPI == 1) {
                    float b0 = bias[gn], b1 = bias[gn + 1];
                    v0.x = softplusf(v0.x + b0);
                    v0.y = softplusf(v0.y + b1);
                    v1.x = softplusf(v1.x + b0);
                    v1.y = softplusf(v1.y + b1);
                }
                *(float2*)(C + (size_t)gm * ldc + gn)       = v0;
                *(float2*)(C + (size_t)(gm + 8) * ldc + gn) = v1;
                if (EPI == 2) {
                    __half2 h0 = __floats2half2_rn(v0.x, v0.y);
                    __half2 h1 = __floats2half2_rn(v1.x, v1.y);
                    *(__half2*)(Caux + (size_t)gm * ldc + gn)       = h0;
                    *(__half2*)(Caux + (size_t)(gm + 8) * ldc + gn) = h1;
                }
            }
        }
    }
}

// ---------------------------------------------------------------------------
// x_proj split-K reduce: sum 8 partials -> fp32 + fp16
// ---------------------------------------------------------------------------
__global__ __launch_bounds__(256)
void xp_reduce_kernel()
{
    int i = blockIdx.x * 256 + threadIdx.x;
    if (i >= ROWS * XDBL_COLS) return;
    float s = 0.f;
    #pragma unroll
    for (int p = 0; p < XP_SPLITS; p++)
        s += g_xpart[(size_t)p * ROWS * XDBL_COLS + i];
    g_xdbl[i]  = s;
    g_xdblt[i] = __float2half_rn(s);
}

// ---------------------------------------------------------------------------
// Depthwise causal conv + bias + SiLU -> fp32 (scan) + fp16 (x_proj A)
// ---------------------------------------------------------------------------
__global__ __launch_bounds__(256)
void conv_silu_kernel(const float* __restrict__ xz,
                      const float* __restrict__ cw,
                      const float* __restrict__ cb,
                      float* __restrict__ xc,
                      __half* __restrict__ xct)
{
    int idx = blockIdx.x * blockDim.x + threadIdx.x;
    if (idx >= ROWS * D_INNER) return;
    int d = idx & (D_INNER - 1);
    int r = idx >> 11;
    int l = r & (SEQLEN - 1);
    int b = r >> 10;

    float acc = cb[d];
    #pragma unroll
    for (int k = 0; k < D_CONV; k++) {
        int ls = l + k - (D_CONV - 1);
        if (ls >= 0)
            acc = fmaf(xz[((size_t)(b * SEQLEN + ls)) * (2 * D_INNER) + d],
                       cw[d * D_CONV + k], acc);
    }
    float sig = 1.0f / (1.0f + __expf(-acc));
    float v = acc * sig;
    xc[idx]  = v;
    xct[idx] = __float2half_rn(v);
}

// ---------------------------------------------------------------------------
// Selective scan. 16 lanes per (b,d) channel; software-pipelined loads.
// ---------------------------------------------------------------------------
__global__ __launch_bounds__(256)
void scan_kernel(const float* __restrict__ xdbl,
                 const float* __restrict__ dt,
                 const float* __restrict__ xc,
                 const float* __restrict__ xz,
                 const float* __restrict__ A_log,
                 const float* __restrict__ Dw,
                 __half* __restrict__ y)
{
    int t = blockIdx.x * blockDim.x + threadIdx.x;
    int n  = t & (D_STATE - 1);
    int ch = t >> 4;
    int b  = ch >> 11;
    int d  = ch & (D_INNER - 1);

    float A  = -__expf(A_log[d * D_STATE + n]);
    float Dd = Dw[d];

    const float* xdbl_b = xdbl + (size_t)b * SEQLEN * XDBL_COLS;
    const float* dt_b   = dt   + (size_t)b * SEQLEN * D_INNER + d;
    const float* xc_b   = xc   + (size_t)b * SEQLEN * D_INNER + d;
    const float* z_b    = xz   + (size_t)b * SEQLEN * (2 * D_INNER) + D_INNER + d;
    __half*      y_b    = y    + (size_t)b * SEQLEN * D_INNER + d;

    // prologue loads for l = 0
    float dtv = __ldg(dt_b);
    float xcv = __ldg(xc_b);
    float Bv  = __ldg(xdbl_b + DT_RANK + n);
    float Cv  = __ldg(xdbl_b + DT_RANK + D_STATE + n);
    float zv  = __ldg(z_b);

    float h = 0.f;
    for (int l = 0; l < SEQLEN; l++) {
        float dA  = __expf(dtv * A);
        float dBu = dtv * xcv * Bv;

        // prefetch next iteration (overlaps with shuffle chain below)
        float ndt = 0.f, nxc = 0.f, nB = 0.f, nC = 0.f, nz = 0.f;
        if (l + 1 < SEQLEN) {
            ndt = __ldg(dt_b + (size_t)(l + 1) * D_INNER);
            nxc = __ldg(xc_b + (size_t)(l + 1) * D_INNER);
            nB  = __ldg(xdbl_b + (l + 1) * XDBL_COLS + DT_RANK + n);
            nC  = __ldg(xdbl_b + (l + 1) * XDBL_COLS + DT_RANK + D_STATE + n);
            nz  = __ldg(z_b + (size_t)(l + 1) * (2 * D_INNER));
        }

        h = fmaf(dA, h, dBu);

        float p = h * Cv;
        p += __shfl_xor_sync(0xffffffffu, p, 8);
        p += __shfl_xor_sync(0xffffffffu, p, 4);
        p += __shfl_xor_sync(0xffffffffu, p, 2);
        p += __shfl_xor_sync(0xffffffffu, p, 1);

        if (n == 0) {
            float sil = zv / (1.0f + __expf(-zv));
            y_b[(size_t)l * D_INNER] = __float2half_rn((p + Dd * xcv) * sil);
        }

        dtv = ndt; xcv = nxc; Bv = nB; Cv = nC; zv = nz;
    }
}

// ---------------------------------------------------------------------------
// Launch
// ---------------------------------------------------------------------------
extern "C" void kernel_launch(void* const* d_in, const int* in_sizes, int n_in,
                              void* d_out, int out_size)
{
    const float* hidden   = (const float*)d_in[0];
    const float* norm_w   = (const float*)d_in[1];
    const float* in_proj  = (const float*)d_in[2];
    const float* conv_w   = (const float*)d_in[3];
    const float* conv_b   = (const float*)d_in[4];
    const float* x_proj   = (const float*)d_in[5];
    const float* dt_proj  = (const float*)d_in[6];
    const float* dt_b     = (const float*)d_in[7];
    const float* A_log    = (const float*)d_in[8];
    const float* Dw       = (const float*)d_in[9];
    const float* out_proj = (const float*)d_in[10];

    float* out = (float*)d_out;

    __half *ht, *xct, *xdblt, *yt, *wi, *wo, *wx, *wd;
    float *xz, *xc, *xpart, *xdbl, *dt;
    cudaGetSymbolAddress((void**)&ht,    g_ht);
    cudaGetSymbolAddress((void**)&xz,    g_xz);
    cudaGetSymbolAddress((void**)&xc,    g_xc);
    cudaGetSymbolAddress((void**)&xct,   g_xct);
    cudaGetSymbolAddress((void**)&xpart, g_xpart);
    cudaGetSymbolAddress((void**)&xdbl,  g_xdbl);
    cudaGetSymbolAddress((void**)&xdblt, g_xdblt);
    cudaGetSymbolAddress((void**)&dt,    g_dt);
    cudaGetSymbolAddress((void**)&yt,    g_yt);
    cudaGetSymbolAddress((void**)&wi,    g_wi);
    cudaGetSymbolAddress((void**)&wo,    g_wo);
    cudaGetSymbolAddress((void**)&wx,    g_wx);
    cudaGetSymbolAddress((void**)&wd,    g_wd);

    cudaFuncSetAttribute(gemm_h<0>, cudaFuncAttributeMaxDynamicSharedMemorySize, GEMM_SMEM);
    cudaFuncSetAttribute(gemm_h<1>, cudaFuncAttributeMaxDynamicSharedMemorySize, GEMM_SMEM);
    cudaFuncSetAttribute(gemm_h<2>, cudaFuncAttributeMaxDynamicSharedMemorySize, GEMM_SMEM);

    // 0. weight conversion (fp16)
    cvt_weights_kernel<<<(NW_TOTAL + 255) / 256, 256>>>(in_proj, out_proj, x_proj, dt_proj);

    // 1. RMSNorm -> fp16
    rmsnorm_kernel<<<ROWS, 256>>>(hidden, norm_w, ht);

    // 2. in_proj: (2048 x 1024) @ (4096 x 1024)^T -> xz (2048 x 4096) fp32
    gemm_h<0><<<dim3(2 * D_INNER / 64, ROWS / 128, 1), 256, GEMM_SMEM>>>(
        ht, D_MODEL, wi, D_MODEL, xz, 2 * D_INNER, nullptr,
        2 * D_INNER, D_MODEL, 0, nullptr);

    // 3. conv + silu -> xc fp32 + xct fp16
    conv_silu_kernel<<<(ROWS * D_INNER) / 256, 256>>>(xz, conv_w, conv_b, xc, xct);

    // 4. x_proj split-K: (2048 x 2048) @ (96 x 2048)^T -> 8 partials
    gemm_h<0><<<dim3(2, ROWS / 128, XP_SPLITS), 256, GEMM_SMEM>>>(
        xct, D_INNER, wx, D_INNER, xpart, XDBL_COLS, nullptr,
        XDBL_COLS, XP_KSPL, (long long)ROWS * XDBL_COLS, nullptr);

    // 4b. reduce -> xdbl fp32 + xdblt fp16
    xp_reduce_kernel<<<(ROWS * XDBL_COLS + 255) / 256, 256>>>();

    // 5. dt_proj + softplus: (2048 x 96[:64]) @ (2048 x 64)^T -> dt fp32
    gemm_h<1><<<dim3(D_INNER / 64, ROWS / 128, 1), 256, GEMM_SMEM>>>(
        xdblt, XDBL_COLS, wd, DT_RANK, dt, D_INNER, nullptr,
        D_INNER, DT_RANK, 0, dt_b);

    // 6. selective scan + gate -> yt fp16
    scan_kernel<<<(BATCH * D_INNER * D_STATE) / 256, 256>>>(
        xdbl, dt, xc, xz, A_log, Dw, yt);

    // 7. out_proj: (2048 x 2048) @ (1024 x 2048)^T -> out fp32
    gemm_h<0><<<dim3(D_MODEL / 64, ROWS / 128, 1), 256, GEMM_SMEM>>>(
        yt, D_INNER, wo, D_INNER, out, D_MODEL, nullptr,
        D_MODEL, D_INNER, 0, nullptr);

    // 8. residual
    size_t half = (size_t)out_size / 2;
    cudaMemcpyAsync(out + half, hidden, half * sizeof(float),
                    cudaMemcpyDeviceToDevice);
}

// round 8
// speedup vs baseline: 4.6338x; 1.0288x over previous
#include <cuda_runtime.h>
#include <cuda_fp16.h>
#include <math.h>
#include <stdint.h>

// ---------------------------------------------------------------------------
// Problem constants
// ---------------------------------------------------------------------------
#define D_MODEL   1024
#define D_STATE   16
#define D_CONV    4
#define D_INNER   2048
#define DT_RANK   64
#define BATCH     2
#define SEQLEN    1024
#define ROWS      (BATCH * SEQLEN)          // 2048
#define XDBL_COLS (DT_RANK + 2 * D_STATE)   // 96
#define EPS       1e-5f

#define XP_SPLITS 8
#define XP_KSPL   (D_INNER / XP_SPLITS)     // 256

// ---------------------------------------------------------------------------
// Scratch (__device__ globals; no cudaMalloc allowed)
// ---------------------------------------------------------------------------
__device__ __half g_ht  [ROWS * D_MODEL];        // rmsnorm out (fp16)
__device__ float  g_xz  [ROWS * 2 * D_INNER];    // in_proj out (x | z) fp32
__device__ float  g_xc  [ROWS * D_INNER];        // conv+silu fp32 (scan)
__device__ __half g_xct [ROWS * D_INNER];        // conv+silu fp16 (x_proj A)
__device__ float  g_xpart[XP_SPLITS * ROWS * XDBL_COLS]; // split-K partials
__device__ float  g_xdbl [ROWS * XDBL_COLS];     // x_proj out fp32 (scan B,C)
__device__ __half g_xdblt[ROWS * XDBL_COLS];     // x_proj out fp16 (dt A)
__device__ float  g_dt  [ROWS * D_INNER];        // softplus(dt) fp32
__device__ __half g_yt  [ROWS * D_INNER];        // scan out fp16 (out_proj A)
__device__ __half g_wi  [2 * D_INNER * D_MODEL]; // fp16 weights
__device__ __half g_wo  [D_MODEL * D_INNER];
__device__ __half g_wx  [XDBL_COLS * D_INNER];
__device__ __half g_wd  [D_INNER * DT_RANK];

// ---------------------------------------------------------------------------
// Helpers
// ---------------------------------------------------------------------------
__device__ __forceinline__ float softplusf(float v)
{
    return v > 20.f ? v : log1pf(__expf(v));
}

__device__ __forceinline__ void mma_f16(float c[4], const uint32_t a[4],
                                        const uint32_t b0, const uint32_t b1)
{
    asm volatile(
        "mma.sync.aligned.m16n8k16.row.col.f32.f16.f16.f32 "
        "{%0,%1,%2,%3}, {%4,%5,%6,%7}, {%8,%9}, {%0,%1,%2,%3};"
        : "+f"(c[0]), "+f"(c[1]), "+f"(c[2]), "+f"(c[3])
        : "r"(a[0]), "r"(a[1]), "r"(a[2]), "r"(a[3]), "r"(b0), "r"(b1));
}

#define LDSM_X4(r0, r1, r2, r3, addr) \
    asm volatile("ldmatrix.sync.aligned.m8n8.x4.shared.b16 {%0,%1,%2,%3}, [%4];" \
                 : "=r"(r0), "=r"(r1), "=r"(r2), "=r"(r3) : "r"(addr))

// ---------------------------------------------------------------------------
// Weight pre-conversion (fp32 -> fp16)
// ---------------------------------------------------------------------------
#define NWI (2 * D_INNER * D_MODEL)
#define NWO (D_MODEL * D_INNER)
#define NWX (XDBL_COLS * D_INNER)
#define NWD (D_INNER * DT_RANK)
#define NW_TOTAL (NWI + NWO + NWX + NWD)

__global__ __launch_bounds__(256)
void cvt_weights_kernel(const float* __restrict__ wi, const float* __restrict__ wo,
                        const float* __restrict__ wx, const float* __restrict__ wd)
{
    int i = blockIdx.x * 256 + threadIdx.x;
    if (i < NWI)                       g_wi[i] = __float2half_rn(wi[i]);
    else if (i < NWI + NWO)            g_wo[i - NWI] = __float2half_rn(wo[i - NWI]);
    else if (i < NWI + NWO + NWX)      g_wx[i - NWI - NWO] = __float2half_rn(wx[i - NWI - NWO]);
    else if (i < NW_TOTAL)             g_wd[i - NWI - NWO - NWX] = __float2half_rn(wd[i - NWI - NWO - NWX]);
}

// ---------------------------------------------------------------------------
// RMSNorm -> fp16
// ---------------------------------------------------------------------------
__global__ __launch_bounds__(256)
void rmsnorm_kernel(const float* __restrict__ x, const float* __restrict__ w,
                    __half* __restrict__ out)
{
    int r = blockIdx.x;
    int t = threadIdx.x;
    const float4* xr = (const float4*)(x + (size_t)r * D_MODEL);
    float4 v = xr[t];
    float s = v.x * v.x + v.y * v.y + v.z * v.z + v.w * v.w;
    #pragma unroll
    for (int o = 16; o; o >>= 1) s += __shfl_xor_sync(0xffffffffu, s, o);

    __shared__ float ws[8];
    __shared__ float s_inv;
    if ((t & 31) == 0) ws[t >> 5] = s;
    __syncthreads();
    if (t == 0) {
        float tot = 0.f;
        #pragma unroll
        for (int i = 0; i < 8; i++) tot += ws[i];
        float rms = sqrtf(tot) * (1.0f / 32.0f);
        s_inv = 1.0f / (rms + EPS);
    }
    __syncthreads();
    float inv = s_inv;
    float4 wv = ((const float4*)w)[t];
    __half2 h0 = __floats2half2_rn(v.x * inv * wv.x, v.y * inv * wv.y);
    __half2 h1 = __floats2half2_rn(v.z * inv * wv.z, v.w * inv * wv.w);
    uint2 o;
    o.x = *(unsigned*)&h0;
    o.y = *(unsigned*)&h1;
    ((uint2*)(out + (size_t)r * D_MODEL))[t] = o;
}

// ---------------------------------------------------------------------------
// FP16 HMMA GEMM:  C[m][n] = sum_k A[m][k] * B[n][k]   (fp32 accumulate)
// Block tile 128x64, BK=32, 4-stage cp.async, ONE __syncthreads per ktile
// (stage written at iter kt is (kt+3)%4 == (kt-1)%4, the buffer the barrier
//  just proved drained). 8 warps = 4(M) x 2(N), 32x32 each, 3 CTAs/SM.
// EPI: 0 = fp32 store; 1 = softplus(acc+bias) fp32; 2 = fp32 + fp16 dup.
// split-K via blockIdx.z. Requires M % 128 == 0, k_len % 32 == 0. N guarded.
// ---------------------------------------------------------------------------
#define BK        32
#define STG       4
#define RB        80                         // smem row bytes (40 halfs)
#define A_BYTES   (128 * RB)                 // 10240
#define B_BYTES   (64 * RB)                  // 5120
#define STAGE_B   (A_BYTES + B_BYTES)        // 15360
#define GEMM_SMEM (STG * STAGE_B)            // 61440

template<int EPI>
__global__ __launch_bounds__(256, 3)
void gemm_h(const __half* __restrict__ A, int lda,
            const __half* __restrict__ B, int ldb,
            float* __restrict__ C, int ldc,
            __half* __restrict__ Caux,
            int N, int k_len, long long split_cstride,
            const float* __restrict__ bias)
{
    extern __shared__ unsigned char smem_raw[];
    const uint32_t smem = (uint32_t)__cvta_generic_to_shared(smem_raw);

    const int tid  = threadIdx.x;
    const int wid  = tid >> 5;
    const int lane = tid & 31;
    const int wm   = (wid & 3) * 32;     // 4 warps along M
    const int wn   = (wid >> 2) * 32;    // 2 warps along N

    const int bm = blockIdx.y * 128;
    const int bn = blockIdx.x * 64;
    const int k0base = blockIdx.z * k_len;
    C += (size_t)blockIdx.z * split_cstride;
    const int ktiles = k_len / BK;

    // ---- stage loader: A 128 rows x 64 B, B 64 rows x 64 B, 16B cp.async
    auto load_stage = [&](int stage, int kt) {
        const int k0 = k0base + kt * BK;
        const uint32_t sa = smem + stage * STAGE_B;
        const uint32_t sb = sa + A_BYTES;
        #pragma unroll
        for (int i = 0; i < 2; i++) {
            int lin = i * 256 + tid;         // 0..511
            int c   = lin & 3;
            int row = lin >> 2;              // 0..127
            uint32_t dst = sa + row * RB + c * 16;
            const __half* src = A + (size_t)(bm + row) * lda + k0 + c * 8;
            asm volatile("cp.async.cg.shared.global [%0], [%1], 16;"
                         :: "r"(dst), "l"(src));
        }
        {
            int c   = tid & 3;
            int row = tid >> 2;              // 0..63
            int gn  = bn + row;
            uint32_t dst = sb + row * RB + c * 16;
            const __half* src = B + (size_t)(gn < N ? gn : 0) * ldb + k0 + c * 8;
            int ok = (gn < N) ? 16 : 0;
            asm volatile("cp.async.cg.shared.global [%0], [%1], 16, %2;"
                         :: "r"(dst), "l"(src), "r"(ok));
        }
    };

    float acc[2][4][4];
    #pragma unroll
    for (int i = 0; i < 2; i++)
        #pragma unroll
        for (int j = 0; j < 4; j++)
            #pragma unroll
            for (int q = 0; q < 4; q++) acc[i][j][q] = 0.f;

    // ---- prologue: 3 stages in flight
    #pragma unroll
    for (int s = 0; s < STG - 1; s++) {
        if (s < ktiles) load_stage(s, s);
        asm volatile("cp.async.commit_group;");
    }

    // fragment address components
    const int a_row = ((lane >> 3) & 1) * 8 + (lane & 7);
    const int a_kc  = (lane >> 4) * 8;
    const int b_row = (lane >> 4) * 8 + (lane & 7);
    const int b_kc  = ((lane >> 3) & 1) * 8;

    for (int kt = 0; kt < ktiles; kt++) {
        asm volatile("cp.async.wait_group %0;" :: "n"(STG - 2));
        __syncthreads();

        // issue next loads first (into the buffer drained by the barrier above)
        if (kt + STG - 1 < ktiles) load_stage((kt + STG - 1) % STG, kt + STG - 1);
        asm volatile("cp.async.commit_group;");

        const uint32_t Ab = smem + (kt % STG) * STAGE_B;
        const uint32_t Bb = Ab + A_BYTES;

        #pragma unroll
        for (int ks = 0; ks < 2; ks++) {
            uint32_t a[2][4], b[4][2];
            #pragma unroll
            for (int mt = 0; mt < 2; mt++) {
                uint32_t ad = Ab + (wm + mt * 16 + a_row) * RB + (ks * 16 + a_kc) * 2;
                LDSM_X4(a[mt][0], a[mt][1], a[mt][2], a[mt][3], ad);
            }
            #pragma unroll
            for (int np = 0; np < 2; np++) {
                uint32_t bd = Bb + (wn + np * 16 + b_row) * RB + (ks * 16 + b_kc) * 2;
                LDSM_X4(b[2 * np][0], b[2 * np][1], b[2 * np + 1][0], b[2 * np + 1][1], bd);
            }
            #pragma unroll
            for (int mt = 0; mt < 2; mt++)
                #pragma unroll
                for (int nt = 0; nt < 4; nt++)
                    mma_f16(acc[mt][nt], a[mt], b[nt][0], b[nt][1]);
        }
    }

    // ---- epilogue
    const int g4 = lane >> 2;
    const int t2 = (lane & 3) * 2;
    #pragma unroll
    for (int mt = 0; mt < 2; mt++) {
        int gm = bm + wm + mt * 16 + g4;
        #pragma unroll
        for (int nt = 0; nt < 4; nt++) {
            int gn = bn + wn + nt * 8 + t2;
            if (gn < N) {
                float2 v0 = make_float2(acc[mt][nt][0], acc[mt][nt][1]);
                float2 v1 = make_float2(acc[mt][nt][2], acc[mt][nt][3]);
                if (EPI == 1) {
                    float b0 = bias[gn], b1 = bias[gn + 1];
                    v0.x = softplusf(v0.x + b0);
                    v0.y = softplusf(v0.y + b1);
                    v1.x = softplusf(v1.x + b0);
                    v1.y = softplusf(v1.y + b1);
                }
                *(float2*)(C + (size_t)gm * ldc + gn)       = v0;
                *(float2*)(C + (size_t)(gm + 8) * ldc + gn) = v1;
                if (EPI == 2) {
                    __half2 h0 = __floats2half2_rn(v0.x, v0.y);
                    __half2 h1 = __floats2half2_rn(v1.x, v1.y);
                    *(__half2*)(Caux + (size_t)gm * ldc + gn)       = h0;
                    *(__half2*)(Caux + (size_t)(gm + 8) * ldc + gn) = h1;
                }
            }
        }
    }
}

// ---------------------------------------------------------------------------
// x_proj split-K reduce: sum 8 partials -> fp32 + fp16
// ---------------------------------------------------------------------------
__global__ __launch_bounds__(256)
void xp_reduce_kernel()
{
    int i = blockIdx.x * 256 + threadIdx.x;
    if (i >= ROWS * XDBL_COLS) return;
    float s = 0.f;
    #pragma unroll
    for (int p = 0; p < XP_SPLITS; p++)
        s += g_xpart[(size_t)p * ROWS * XDBL_COLS + i];
    g_xdbl[i]  = s;
    g_xdblt[i] = __float2half_rn(s);
}

// ---------------------------------------------------------------------------
// Depthwise causal conv + bias + SiLU -> fp32 (scan) + fp16 (x_proj A)
// ---------------------------------------------------------------------------
__global__ __launch_bounds__(256)
void conv_silu_kernel(const float* __restrict__ xz,
                      const float* __restrict__ cw,
                      const float* __restrict__ cb,
                      float* __restrict__ xc,
                      __half* __restrict__ xct)
{
    int idx = blockIdx.x * blockDim.x + threadIdx.x;
    if (idx >= ROWS * D_INNER) return;
    int d = idx & (D_INNER - 1);
    int r = idx >> 11;
    int l = r & (SEQLEN - 1);
    int b = r >> 10;

    float acc = cb[d];
    #pragma unroll
    for (int k = 0; k < D_CONV; k++) {
        int ls = l + k - (D_CONV - 1);
        if (ls >= 0)
            acc = fmaf(xz[((size_t)(b * SEQLEN + ls)) * (2 * D_INNER) + d],
                       cw[d * D_CONV + k], acc);
    }
    float sig = 1.0f / (1.0f + __expf(-acc));
    float v = acc * sig;
    xc[idx]  = v;
    xct[idx] = __float2half_rn(v);
}

// ---------------------------------------------------------------------------
// Selective scan. 16 lanes per (b,d) channel; software-pipelined loads.
// ---------------------------------------------------------------------------
__global__ __launch_bounds__(256)
void scan_kernel(const float* __restrict__ xdbl,
                 const float* __restrict__ dt,
                 const float* __restrict__ xc,
                 const float* __restrict__ xz,
                 const float* __restrict__ A_log,
                 const float* __restrict__ Dw,
                 __half* __restrict__ y)
{
    int t = blockIdx.x * blockDim.x + threadIdx.x;
    int n  = t & (D_STATE - 1);
    int ch = t >> 4;
    int b  = ch >> 11;
    int d  = ch & (D_INNER - 1);

    float A  = -__expf(A_log[d * D_STATE + n]);
    float Dd = Dw[d];

    const float* xdbl_b = xdbl + (size_t)b * SEQLEN * XDBL_COLS;
    const float* dt_b   = dt   + (size_t)b * SEQLEN * D_INNER + d;
    const float* xc_b   = xc   + (size_t)b * SEQLEN * D_INNER + d;
    const float* z_b    = xz   + (size_t)b * SEQLEN * (2 * D_INNER) + D_INNER + d;
    __half*      y_b    = y    + (size_t)b * SEQLEN * D_INNER + d;

    // prologue loads for l = 0
    float dtv = __ldg(dt_b);
    float xcv = __ldg(xc_b);
    float Bv  = __ldg(xdbl_b + DT_RANK + n);
    float Cv  = __ldg(xdbl_b + DT_RANK + D_STATE + n);
    float zv  = __ldg(z_b);

    float h = 0.f;
    for (int l = 0; l < SEQLEN; l++) {
        float dA  = __expf(dtv * A);
        float dBu = dtv * xcv * Bv;

        // prefetch next iteration (overlaps with shuffle chain below)
        float ndt = 0.f, nxc = 0.f, nB = 0.f, nC = 0.f, nz = 0.f;
        if (l + 1 < SEQLEN) {
            ndt = __ldg(dt_b + (size_t)(l + 1) * D_INNER);
            nxc = __ldg(xc_b + (size_t)(l + 1) * D_INNER);
            nB  = __ldg(xdbl_b + (l + 1) * XDBL_COLS + DT_RANK + n);
            nC  = __ldg(xdbl_b + (l + 1) * XDBL_COLS + DT_RANK + D_STATE + n);
            nz  = __ldg(z_b + (size_t)(l + 1) * (2 * D_INNER));
        }

        h = fmaf(dA, h, dBu);

        float p = h * Cv;
        p += __shfl_xor_sync(0xffffffffu, p, 8);
        p += __shfl_xor_sync(0xffffffffu, p, 4);
        p += __shfl_xor_sync(0xffffffffu, p, 2);
        p += __shfl_xor_sync(0xffffffffu, p, 1);

        if (n == 0) {
            float sil = zv / (1.0f + __expf(-zv));
            y_b[(size_t)l * D_INNER] = __float2half_rn((p + Dd * xcv) * sil);
        }

        dtv = ndt; xcv = nxc; Bv = nB; Cv = nC; zv = nz;
    }
}

// ---------------------------------------------------------------------------
// Launch
// ---------------------------------------------------------------------------
extern "C" void kernel_launch(void* const* d_in, const int* in_sizes, int n_in,
                              void* d_out, int out_size)
{
    const float* hidden   = (const float*)d_in[0];
    const float* norm_w   = (const float*)d_in[1];
    const float* in_proj  = (const float*)d_in[2];
    const float* conv_w   = (const float*)d_in[3];
    const float* conv_b   = (const float*)d_in[4];
    const float* x_proj   = (const float*)d_in[5];
    const float* dt_proj  = (const float*)d_in[6];
    const float* dt_b     = (const float*)d_in[7];
    const float* A_log    = (const float*)d_in[8];
    const float* Dw       = (const float*)d_in[9];
    const float* out_proj = (const float*)d_in[10];

    float* out = (float*)d_out;

    __half *ht, *xct, *xdblt, *yt, *wi, *wo, *wx, *wd;
    float *xz, *xc, *xpart, *xdbl, *dt;
    cudaGetSymbolAddress((void**)&ht,    g_ht);
    cudaGetSymbolAddress((void**)&xz,    g_xz);
    cudaGetSymbolAddress((void**)&xc,    g_xc);
    cudaGetSymbolAddress((void**)&xct,   g_xct);
    cudaGetSymbolAddress((void**)&xpart, g_xpart);
    cudaGetSymbolAddress((void**)&xdbl,  g_xdbl);
    cudaGetSymbolAddress((void**)&xdblt, g_xdblt);
    cudaGetSymbolAddress((void**)&dt,    g_dt);
    cudaGetSymbolAddress((void**)&yt,    g_yt);
    cudaGetSymbolAddress((void**)&wi,    g_wi);
    cudaGetSymbolAddress((void**)&wo,    g_wo);
    cudaGetSymbolAddress((void**)&wx,    g_wx);
    cudaGetSymbolAddress((void**)&wd,    g_wd);

    cudaFuncSetAttribute(gemm_h<0>, cudaFuncAttributeMaxDynamicSharedMemorySize, GEMM_SMEM);
    cudaFuncSetAttribute(gemm_h<1>, cudaFuncAttributeMaxDynamicSharedMemorySize, GEMM_SMEM);
    cudaFuncSetAttribute(gemm_h<2>, cudaFuncAttributeMaxDynamicSharedMemorySize, GEMM_SMEM);

    // 0. weight conversion (fp16)
    cvt_weights_kernel<<<(NW_TOTAL + 255) / 256, 256>>>(in_proj, out_proj, x_proj, dt_proj);

    // 1. RMSNorm -> fp16
    rmsnorm_kernel<<<ROWS, 256>>>(hidden, norm_w, ht);

    // 2. in_proj: (2048 x 1024) @ (4096 x 1024)^T -> xz (2048 x 4096) fp32
    gemm_h<0><<<dim3(2 * D_INNER / 64, ROWS / 128, 1), 256, GEMM_SMEM>>>(
        ht, D_MODEL, wi, D_MODEL, xz, 2 * D_INNER, nullptr,
        2 * D_INNER, D_MODEL, 0, nullptr);

    // 3. conv + silu -> xc fp32 + xct fp16
    conv_silu_kernel<<<(ROWS * D_INNER) / 256, 256>>>(xz, conv_w, conv_b, xc, xct);

    // 4. x_proj split-K: (2048 x 2048) @ (96 x 2048)^T -> 8 partials
    gemm_h<0><<<dim3(2, ROWS / 128, XP_SPLITS), 256, GEMM_SMEM>>>(
        xct, D_INNER, wx, D_INNER, xpart, XDBL_COLS, nullptr,
        XDBL_COLS, XP_KSPL, (long long)ROWS * XDBL_COLS, nullptr);

    // 4b. reduce -> xdbl fp32 + xdblt fp16
    xp_reduce_kernel<<<(ROWS * XDBL_COLS + 255) / 256, 256>>>();

    // 5. dt_proj + softplus: (2048 x 96[:64]) @ (2048 x 64)^T -> dt fp32
    gemm_h<1><<<dim3(D_INNER / 64, ROWS / 128, 1), 256, GEMM_SMEM>>>(
        xdblt, XDBL_COLS, wd, DT_RANK, dt, D_INNER, nullptr,
        D_INNER, DT_RANK, 0, dt_b);

    // 6. selective scan + gate -> yt fp16
    scan_kernel<<<(BATCH * D_INNER * D_STATE) / 256, 256>>>(
        xdbl, dt, xc, xz, A_log, Dw, yt);

    // 7. out_proj: (2048 x 2048) @ (1024 x 2048)^T -> out fp32
    gemm_h<0><<<dim3(D_MODEL / 64, ROWS / 128, 1), 256, GEMM_SMEM>>>(
        yt, D_INNER, wo, D_INNER, out, D_MODEL, nullptr,
        D_MODEL, D_INNER, 0, nullptr);

    // 8. residual
    size_t half = (size_t)out_size / 2;
    cudaMemcpyAsync(out + half, hidden, half * sizeof(float),
                    cudaMemcpyDeviceToDevice);
}

// round 9
// speedup vs baseline: 4.7152x; 1.0176x over previous
#include <cuda_runtime.h>
#include <cuda_fp16.h>
#include <math.h>
#include <stdint.h>

// ---------------------------------------------------------------------------
// Problem constants
// ---------------------------------------------------------------------------
#define D_MODEL   1024
#define D_STATE   16
#define D_CONV    4
#define D_INNER   2048
#define DT_RANK   64
#define BATCH     2
#define SEQLEN    1024
#define ROWS      (BATCH * SEQLEN)          // 2048
#define XDBL_COLS (DT_RANK + 2 * D_STATE)   // 96
#define EPS       1e-5f

#define XP_SPLITS 8
#define XP_KSPL   (D_INNER / XP_SPLITS)     // 256

// ---------------------------------------------------------------------------
// Scratch (__device__ globals; no cudaMalloc allowed)
// ---------------------------------------------------------------------------
__device__ __half g_ht  [ROWS * D_MODEL];        // rmsnorm out (fp16)
__device__ float  g_xz  [ROWS * 2 * D_INNER];    // in_proj out (x | z) fp32
__device__ float  g_xc  [ROWS * D_INNER];        // conv+silu fp32 (scan)
__device__ __half g_xct [ROWS * D_INNER];        // conv+silu fp16 (x_proj A)
__device__ float  g_xpart[XP_SPLITS * ROWS * XDBL_COLS]; // split-K partials
__device__ float  g_xdbl [ROWS * XDBL_COLS];     // x_proj out fp32 (scan B,C)
__device__ __half g_xdblt[ROWS * XDBL_COLS];     // x_proj out fp16 (dt A)
__device__ float  g_dt  [ROWS * D_INNER];        // softplus(dt) fp32
__device__ __half g_yt  [ROWS * D_INNER];        // scan out fp16 (out_proj A)
__device__ __half g_wi  [2 * D_INNER * D_MODEL]; // fp16 weights
__device__ __half g_wo  [D_MODEL * D_INNER];
__device__ __half g_wx  [XDBL_COLS * D_INNER];
__device__ __half g_wd  [D_INNER * DT_RANK];

// ---------------------------------------------------------------------------
// Helpers
// ---------------------------------------------------------------------------
__device__ __forceinline__ float softplusf(float v)
{
    return v > 20.f ? v : log1pf(__expf(v));
}

__device__ __forceinline__ void mma_f16(float c[4], const uint32_t a[4],
                                        const uint32_t b0, const uint32_t b1)
{
    asm volatile(
        "mma.sync.aligned.m16n8k16.row.col.f32.f16.f16.f32 "
        "{%0,%1,%2,%3}, {%4,%5,%6,%7}, {%8,%9}, {%0,%1,%2,%3};"
        : "+f"(c[0]), "+f"(c[1]), "+f"(c[2]), "+f"(c[3])
        : "r"(a[0]), "r"(a[1]), "r"(a[2]), "r"(a[3]), "r"(b0), "r"(b1));
}

#define LDSM_X4(r0, r1, r2, r3, addr) \
    asm volatile("ldmatrix.sync.aligned.m8n8.x4.shared.b16 {%0,%1,%2,%3}, [%4];" \
                 : "=r"(r0), "=r"(r1), "=r"(r2), "=r"(r3) : "r"(addr))

// ---------------------------------------------------------------------------
// Dummy kernel: positions in_proj at ncu's capture slot (launch index 3)
// ---------------------------------------------------------------------------
__global__ void dummy_kernel() {}

// ---------------------------------------------------------------------------
// Weight pre-conversion (fp32 -> fp16)
// ---------------------------------------------------------------------------
#define NWI (2 * D_INNER * D_MODEL)
#define NWO (D_MODEL * D_INNER)
#define NWX (XDBL_COLS * D_INNER)
#define NWD (D_INNER * DT_RANK)
#define NW_TOTAL (NWI + NWO + NWX + NWD)

__global__ __launch_bounds__(256)
void cvt_weights_kernel(const float* __restrict__ wi, const float* __restrict__ wo,
                        const float* __restrict__ wx, const float* __restrict__ wd)
{
    int i = blockIdx.x * 256 + threadIdx.x;
    if (i < NWI)                       g_wi[i] = __float2half_rn(wi[i]);
    else if (i < NWI + NWO)            g_wo[i - NWI] = __float2half_rn(wo[i - NWI]);
    else if (i < NWI + NWO + NWX)      g_wx[i - NWI - NWO] = __float2half_rn(wx[i - NWI - NWO]);
    else if (i < NW_TOTAL)             g_wd[i - NWI - NWO - NWX] = __float2half_rn(wd[i - NWI - NWO - NWX]);
}

// ---------------------------------------------------------------------------
// RMSNorm -> fp16
// ---------------------------------------------------------------------------
__global__ __launch_bounds__(256)
void rmsnorm_kernel(const float* __restrict__ x, const float* __restrict__ w,
                    __half* __restrict__ out)
{
    int r = blockIdx.x;
    int t = threadIdx.x;
    const float4* xr = (const float4*)(x + (size_t)r * D_MODEL);
    float4 v = xr[t];
    float s = v.x * v.x + v.y * v.y + v.z * v.z + v.w * v.w;
    #pragma unroll
    for (int o = 16; o; o >>= 1) s += __shfl_xor_sync(0xffffffffu, s, o);

    __shared__ float ws[8];
    __shared__ float s_inv;
    if ((t & 31) == 0) ws[t >> 5] = s;
    __syncthreads();
    if (t == 0) {
        float tot = 0.f;
        #pragma unroll
        for (int i = 0; i < 8; i++) tot += ws[i];
        float rms = sqrtf(tot) * (1.0f / 32.0f);
        s_inv = 1.0f / (rms + EPS);
    }
    __syncthreads();
    float inv = s_inv;
    float4 wv = ((const float4*)w)[t];
    __half2 h0 = __floats2half2_rn(v.x * inv * wv.x, v.y * inv * wv.y);
    __half2 h1 = __floats2half2_rn(v.z * inv * wv.z, v.w * inv * wv.w);
    uint2 o;
    o.x = *(unsigned*)&h0;
    o.y = *(unsigned*)&h1;
    ((uint2*)(out + (size_t)r * D_MODEL))[t] = o;
}

// ---------------------------------------------------------------------------
// FP16 HMMA GEMM:  C[m][n] = sum_k A[m][k] * B[n][k]   (fp32 accumulate)
// Block tile 128x64, BK=64, 3-stage cp.async, ONE __syncthreads per ktile.
// Xor-swizzled 128B smem rows (no padding; xor term == lane&7).
// 8 warps = 4(M) x 2(N), 32x32 each, 3 CTAs/SM.
// EPI: 0 = fp32 store; 1 = softplus(acc+bias) fp32; 2 = fp32 + fp16 dup.
// split-K via blockIdx.z. Requires M % 128 == 0, k_len % 64 == 0. N guarded.
// ---------------------------------------------------------------------------
#define BK        64
#define STG       3
#define RB        128                        // smem row bytes (64 halfs, swizzled)
#define A_BYTES   (128 * RB)                 // 16384
#define B_BYTES   (64 * RB)                  // 8192
#define STAGE_B   (A_BYTES + B_BYTES)        // 24576
#define GEMM_SMEM (STG * STAGE_B)            // 73728

template<int EPI>
__global__ __launch_bounds__(256, 3)
void gemm_h(const __half* __restrict__ A, int lda,
            const __half* __restrict__ B, int ldb,
            float* __restrict__ C, int ldc,
            __half* __restrict__ Caux,
            int N, int k_len, long long split_cstride,
            const float* __restrict__ bias)
{
    extern __shared__ unsigned char smem_raw[];
    const uint32_t smem = (uint32_t)__cvta_generic_to_shared(smem_raw);

    const int tid  = threadIdx.x;
    const int wid  = tid >> 5;
    const int lane = tid & 31;
    const int wm   = (wid & 3) * 32;     // 4 warps along M
    const int wn   = (wid >> 2) * 32;    // 2 warps along N

    const int bm = blockIdx.y * 128;
    const int bn = blockIdx.x * 64;
    const int k0base = blockIdx.z * k_len;
    C += (size_t)blockIdx.z * split_cstride;
    const int ktiles = k_len / BK;

    // ---- stage loader: A 128 rows, B 64 rows, 8 x 16B chunks per row,
    //      chunk swizzle: chunk' = chunk ^ (row & 7)
    auto load_stage = [&](int stage, int kt) {
        const int k0 = k0base + kt * BK;
        const uint32_t sa = smem + stage * STAGE_B;
        const uint32_t sb = sa + A_BYTES;
        #pragma unroll
        for (int i = 0; i < 4; i++) {
            int lin = i * 256 + tid;         // 0..1023
            int c   = lin & 7;
            int row = lin >> 3;              // 0..127
            uint32_t dst = sa + row * RB + ((c ^ (row & 7)) << 4);
            const __half* src = A + (size_t)(bm + row) * lda + k0 + c * 8;
            asm volatile("cp.async.cg.shared.global [%0], [%1], 16;"
                         :: "r"(dst), "l"(src));
        }
        #pragma unroll
        for (int i = 0; i < 2; i++) {
            int lin = i * 256 + tid;         // 0..511
            int c   = lin & 7;
            int row = lin >> 3;              // 0..63
            int gn  = bn + row;
            uint32_t dst = sb + row * RB + ((c ^ (row & 7)) << 4);
            const __half* src = B + (size_t)(gn < N ? gn : 0) * ldb + k0 + c * 8;
            int ok = (gn < N) ? 16 : 0;
            asm volatile("cp.async.cg.shared.global [%0], [%1], 16, %2;"
                         :: "r"(dst), "l"(src), "r"(ok));
        }
    };

    float acc[2][4][4];
    #pragma unroll
    for (int i = 0; i < 2; i++)
        #pragma unroll
        for (int j = 0; j < 4; j++)
            #pragma unroll
            for (int q = 0; q < 4; q++) acc[i][j][q] = 0.f;

    // ---- prologue: 2 stages in flight
    #pragma unroll
    for (int s = 0; s < STG - 1; s++) {
        if (s < ktiles) load_stage(s, s);
        asm volatile("cp.async.commit_group;");
    }

    // fragment address components (ldmatrix row layout; xor term == lane&7)
    const int a_row = ((lane >> 3) & 1) * 8 + (lane & 7);
    const int a_kh  = lane >> 4;             // 0/1: which 16B chunk within 16 halfs pair
    const int b_row = (lane >> 4) * 8 + (lane & 7);
    const int b_kh  = (lane >> 3) & 1;
    const int lxor  = lane & 7;

    for (int kt = 0; kt < ktiles; kt++) {
        asm volatile("cp.async.wait_group %0;" :: "n"(STG - 2));
        __syncthreads();

        // issue next loads first (into the buffer the barrier just freed)
        if (kt + STG - 1 < ktiles) load_stage((kt + STG - 1) % STG, kt + STG - 1);
        asm volatile("cp.async.commit_group;");

        const uint32_t Ab = smem + (kt % STG) * STAGE_B;
        const uint32_t Bb = Ab + A_BYTES;

        #pragma unroll
        for (int ks = 0; ks < 4; ks++) {     // 4 x k16 per BK=64
            const uint32_t ca = (uint32_t)((((ks << 1) | a_kh) ^ lxor) << 4);
            const uint32_t cb = (uint32_t)((((ks << 1) | b_kh) ^ lxor) << 4);
            uint32_t a[2][4], b[4][2];
            #pragma unroll
            for (int mt = 0; mt < 2; mt++) {
                uint32_t ad = Ab + (wm + mt * 16 + a_row) * RB + ca;
                LDSM_X4(a[mt][0], a[mt][1], a[mt][2], a[mt][3], ad);
            }
            #pragma unroll
            for (int np = 0; np < 2; np++) {
                uint32_t bd = Bb + (wn + np * 16 + b_row) * RB + cb;
                LDSM_X4(b[2 * np][0], b[2 * np][1], b[2 * np + 1][0], b[2 * np + 1][1], bd);
            }
            #pragma unroll
            for (int mt = 0; mt < 2; mt++)
                #pragma unroll
                for (int nt = 0; nt < 4; nt++)
                    mma_f16(acc[mt][nt], a[mt], b[nt][0], b[nt][1]);
        }
    }

    // ---- epilogue
    const int g4 = lane >> 2;
    const int t2 = (lane & 3) * 2;
    #pragma unroll
    for (int mt = 0; mt < 2; mt++) {
        int gm = bm + wm + mt * 16 + g4;
        #pragma unroll
        for (int nt = 0; nt < 4; nt++) {
            int gn = bn + wn + nt * 8 + t2;
            if (gn < N) {
                float2 v0 = make_float2(acc[mt][nt][0], acc[mt][nt][1]);
                float2 v1 = make_float2(acc[mt][nt][2], acc[mt][nt][3]);
                if (EPI == 1) {
                    float b0 = bias[gn], b1 = bias[gn + 1];
                    v0.x = softplusf(v0.x + b0);
                    v0.y = softplusf(v0.y + b1);
                    v1.x = softplusf(v1.x + b0);
                    v1.y = softplusf(v1.y + b1);
                }
                *(float2*)(C + (size_t)gm * ldc + gn)       = v0;
                *(float2*)(C + (size_t)(gm + 8) * ldc + gn) = v1;
                if (EPI == 2) {
                    __half2 h0 = __floats2half2_rn(v0.x, v0.y);
                    __half2 h1 = __floats2half2_rn(v1.x, v1.y);
                    *(__half2*)(Caux + (size_t)gm * ldc + gn)       = h0;
                    *(__half2*)(Caux + (size_t)(gm + 8) * ldc + gn) = h1;
                }
            }
        }
    }
}

// ---------------------------------------------------------------------------
// x_proj split-K reduce: sum 8 partials -> fp32 + fp16
// ---------------------------------------------------------------------------
__global__ __launch_bounds__(256)
void xp_reduce_kernel()
{
    int i = blockIdx.x * 256 + threadIdx.x;
    if (i >= ROWS * XDBL_COLS) return;
    float s = 0.f;
    #pragma unroll
    for (int p = 0; p < XP_SPLITS; p++)
        s += g_xpart[(size_t)p * ROWS * XDBL_COLS + i];
    g_xdbl[i]  = s;
    g_xdblt[i] = __float2half_rn(s);
}

// ---------------------------------------------------------------------------
// Depthwise causal conv + bias + SiLU -> fp32 (scan) + fp16 (x_proj A)
// ---------------------------------------------------------------------------
__global__ __launch_bounds__(256)
void conv_silu_kernel(const float* __restrict__ xz,
                      const float* __restrict__ cw,
                      const float* __restrict__ cb,
                      float* __restrict__ xc,
                      __half* __restrict__ xct)
{
    int idx = blockIdx.x * blockDim.x + threadIdx.x;
    if (idx >= ROWS * D_INNER) return;
    int d = idx & (D_INNER - 1);
    int r = idx >> 11;
    int l = r & (SEQLEN - 1);
    int b = r >> 10;

    float acc = cb[d];
    #pragma unroll
    for (int k = 0; k < D_CONV; k++) {
        int ls = l + k - (D_CONV - 1);
        if (ls >= 0)
            acc = fmaf(xz[((size_t)(b * SEQLEN + ls)) * (2 * D_INNER) + d],
                       cw[d * D_CONV + k], acc);
    }
    float sig = 1.0f / (1.0f + __expf(-acc));
    float v = acc * sig;
    xc[idx]  = v;
    xct[idx] = __float2half_rn(v);
}

// ---------------------------------------------------------------------------
// Selective scan. 16 lanes per (b,d) channel; software-pipelined loads.
// ---------------------------------------------------------------------------
__global__ __launch_bounds__(256)
void scan_kernel(const float* __restrict__ xdbl,
                 const float* __restrict__ dt,
                 const float* __restrict__ xc,
                 const float* __restrict__ xz,
                 const float* __restrict__ A_log,
                 const float* __restrict__ Dw,
                 __half* __restrict__ y)
{
    int t = blockIdx.x * blockDim.x + threadIdx.x;
    int n  = t & (D_STATE - 1);
    int ch = t >> 4;
    int b  = ch >> 11;
    int d  = ch & (D_INNER - 1);

    float A  = -__expf(A_log[d * D_STATE + n]);
    float Dd = Dw[d];

    const float* xdbl_b = xdbl + (size_t)b * SEQLEN * XDBL_COLS;
    const float* dt_b   = dt   + (size_t)b * SEQLEN * D_INNER + d;
    const float* xc_b   = xc   + (size_t)b * SEQLEN * D_INNER + d;
    const float* z_b    = xz   + (size_t)b * SEQLEN * (2 * D_INNER) + D_INNER + d;
    __half*      y_b    = y    + (size_t)b * SEQLEN * D_INNER + d;

    // prologue loads for l = 0
    float dtv = __ldg(dt_b);
    float xcv = __ldg(xc_b);
    float Bv  = __ldg(xdbl_b + DT_RANK + n);
    float Cv  = __ldg(xdbl_b + DT_RANK + D_STATE + n);
    float zv  = __ldg(z_b);

    float h = 0.f;
    for (int l = 0; l < SEQLEN; l++) {
        float dA  = __expf(dtv * A);
        float dBu = dtv * xcv * Bv;

        // prefetch next iteration (overlaps with shuffle chain below)
        float ndt = 0.f, nxc = 0.f, nB = 0.f, nC = 0.f, nz = 0.f;
        if (l + 1 < SEQLEN) {
            ndt = __ldg(dt_b + (size_t)(l + 1) * D_INNER);
            nxc = __ldg(xc_b + (size_t)(l + 1) * D_INNER);
            nB  = __ldg(xdbl_b + (l + 1) * XDBL_COLS + DT_RANK + n);
            nC  = __ldg(xdbl_b + (l + 1) * XDBL_COLS + DT_RANK + D_STATE + n);
            nz  = __ldg(z_b + (size_t)(l + 1) * (2 * D_INNER));
        }

        h = fmaf(dA, h, dBu);

        float p = h * Cv;
        p += __shfl_xor_sync(0xffffffffu, p, 8);
        p += __shfl_xor_sync(0xffffffffu, p, 4);
        p += __shfl_xor_sync(0xffffffffu, p, 2);
        p += __shfl_xor_sync(0xffffffffu, p, 1);

        if (n == 0) {
            float sil = zv / (1.0f + __expf(-zv));
            y_b[(size_t)l * D_INNER] = __float2half_rn((p + Dd * xcv) * sil);
        }

        dtv = ndt; xcv = nxc; Bv = nB; Cv = nC; zv = nz;
    }
}

// ---------------------------------------------------------------------------
// Launch
// ---------------------------------------------------------------------------
extern "C" void kernel_launch(void* const* d_in, const int* in_sizes, int n_in,
                              void* d_out, int out_size)
{
    const float* hidden   = (const float*)d_in[0];
    const float* norm_w   = (const float*)d_in[1];
    const float* in_proj  = (const float*)d_in[2];
    const float* conv_w   = (const float*)d_in[3];
    const float* conv_b   = (const float*)d_in[4];
    const float* x_proj   = (const float*)d_in[5];
    const float* dt_proj  = (const float*)d_in[6];
    const float* dt_b     = (const float*)d_in[7];
    const float* A_log    = (const float*)d_in[8];
    const float* Dw       = (const float*)d_in[9];
    const float* out_proj = (const float*)d_in[10];

    float* out = (float*)d_out;

    __half *ht, *xct, *xdblt, *yt, *wi, *wo, *wx, *wd;
    float *xz, *xc, *xpart, *xdbl, *dt;
    cudaGetSymbolAddress((void**)&ht,    g_ht);
    cudaGetSymbolAddress((void**)&xz,    g_xz);
    cudaGetSymbolAddress((void**)&xc,    g_xc);
    cudaGetSymbolAddress((void**)&xct,   g_xct);
    cudaGetSymbolAddress((void**)&xpart, g_xpart);
    cudaGetSymbolAddress((void**)&xdbl,  g_xdbl);
    cudaGetSymbolAddress((void**)&xdblt, g_xdblt);
    cudaGetSymbolAddress((void**)&dt,    g_dt);
    cudaGetSymbolAddress((void**)&yt,    g_yt);
    cudaGetSymbolAddress((void**)&wi,    g_wi);
    cudaGetSymbolAddress((void**)&wo,    g_wo);
    cudaGetSymbolAddress((void**)&wx,    g_wx);
    cudaGetSymbolAddress((void**)&wd,    g_wd);

    cudaFuncSetAttribute(gemm_h<0>, cudaFuncAttributeMaxDynamicSharedMemorySize, GEMM_SMEM);
    cudaFuncSetAttribute(gemm_h<1>, cudaFuncAttributeMaxDynamicSharedMemorySize, GEMM_SMEM);
    cudaFuncSetAttribute(gemm_h<2>, cudaFuncAttributeMaxDynamicSharedMemorySize, GEMM_SMEM);

    // 0. weight conversion (fp16)                                  [launch 0]
    cvt_weights_kernel<<<(NW_TOTAL + 255) / 256, 256>>>(in_proj, out_proj, x_proj, dt_proj);

    // 1. RMSNorm -> fp16                                           [launch 1]
    rmsnorm_kernel<<<ROWS, 256>>>(hidden, norm_w, ht);

    // 1b. dummy: put in_proj at ncu capture slot (index 3)         [launch 2]
    dummy_kernel<<<1, 32>>>();

    // 2. in_proj: (2048 x 1024) @ (4096 x 1024)^T -> xz            [launch 3]
    gemm_h<0><<<dim3(2 * D_INNER / 64, ROWS / 128, 1), 256, GEMM_SMEM>>>(
        ht, D_MODEL, wi, D_MODEL, xz, 2 * D_INNER, nullptr,
        2 * D_INNER, D_MODEL, 0, nullptr);

    // 3. conv + silu -> xc fp32 + xct fp16
    conv_silu_kernel<<<(ROWS * D_INNER) / 256, 256>>>(xz, conv_w, conv_b, xc, xct);

    // 4. x_proj split-K: (2048 x 2048) @ (96 x 2048)^T -> 8 partials
    gemm_h<0><<<dim3(2, ROWS / 128, XP_SPLITS), 256, GEMM_SMEM>>>(
        xct, D_INNER, wx, D_INNER, xpart, XDBL_COLS, nullptr,
        XDBL_COLS, XP_KSPL, (long long)ROWS * XDBL_COLS, nullptr);

    // 4b. reduce -> xdbl fp32 + xdblt fp16
    xp_reduce_kernel<<<(ROWS * XDBL_COLS + 255) / 256, 256>>>();

    // 5. dt_proj + softplus: (2048 x 96[:64]) @ (2048 x 64)^T -> dt fp32
    gemm_h<1><<<dim3(D_INNER / 64, ROWS / 128, 1), 256, GEMM_SMEM>>>(
        xdblt, XDBL_COLS, wd, DT_RANK, dt, D_INNER, nullptr,
        D_INNER, DT_RANK, 0, dt_b);

    // 6. selective scan + gate -> yt fp16
    scan_kernel<<<(BATCH * D_INNER * D_STATE) / 256, 256>>>(
        xdbl, dt, xc, xz, A_log, Dw, yt);

    // 7. out_proj: (2048 x 2048) @ (1024 x 2048)^T -> out fp32
    gemm_h<0><<<dim3(D_MODEL / 64, ROWS / 128, 1), 256, GEMM_SMEM>>>(
        yt, D_INNER, wo, D_INNER, out, D_MODEL, nullptr,
        D_MODEL, D_INNER, 0, nullptr);

    // 8. residual
    size_t half = (size_t)out_size / 2;
    cudaMemcpyAsync(out + half, hidden, half * sizeof(float),
                    cudaMemcpyDeviceToDevice);
}

// round 10
// speedup vs baseline: 7.4022x; 1.5698x over previous
#include <cuda_runtime.h>
#include <cuda_fp16.h>
#include <math.h>
#include <stdint.h>

// ---------------------------------------------------------------------------
// Problem constants
// ---------------------------------------------------------------------------
#define D_MODEL   1024
#define D_STATE   16
#define D_CONV    4
#define D_INNER   2048
#define DT_RANK   64
#define BATCH     2
#define SEQLEN    1024
#define ROWS      (BATCH * SEQLEN)          // 2048
#define XDBL_COLS (DT_RANK + 2 * D_STATE)   // 96
#define EPS       1e-5f

#define XP_SPLITS 8
#define XP_KSPL   (D_INNER / XP_SPLITS)     // 256

// ---------------------------------------------------------------------------
// Scratch (__device__ globals; no cudaMalloc allowed)
// ---------------------------------------------------------------------------
__device__ __half g_ht  [ROWS * D_MODEL];        // rmsnorm out (fp16)
__device__ float  g_xz  [ROWS * 2 * D_INNER];    // in_proj out (x | z) fp32
__device__ float  g_xc  [ROWS * D_INNER];        // conv+silu fp32 (scan)
__device__ __half g_xct [ROWS * D_INNER];        // conv+silu fp16 (x_proj A)
__device__ float  g_xpart[XP_SPLITS * ROWS * XDBL_COLS]; // split-K partials
__device__ float  g_xdbl [ROWS * XDBL_COLS];     // x_proj out fp32 (scan B,C)
__device__ __half g_xdblt[ROWS * XDBL_COLS];     // x_proj out fp16 (dt A)
__device__ float  g_dt  [ROWS * D_INNER];        // softplus(dt) fp32
__device__ __half g_yt  [ROWS * D_INNER];        // scan out fp16 (out_proj A)
__device__ __half g_wi  [2 * D_INNER * D_MODEL]; // fp16 weights
__device__ __half g_wo  [D_MODEL * D_INNER];
__device__ __half g_wx  [XDBL_COLS * D_INNER];
__device__ __half g_wd  [D_INNER * DT_RANK];

// ---------------------------------------------------------------------------
// Helpers
// ---------------------------------------------------------------------------
__device__ __forceinline__ float softplusf(float v)
{
    return v > 20.f ? v : log1pf(__expf(v));
}

__device__ __forceinline__ void mma_f16(float c[4], const uint32_t a[4],
                                        const uint32_t b0, const uint32_t b1)
{
    asm volatile(
        "mma.sync.aligned.m16n8k16.row.col.f32.f16.f16.f32 "
        "{%0,%1,%2,%3}, {%4,%5,%6,%7}, {%8,%9}, {%0,%1,%2,%3};"
        : "+f"(c[0]), "+f"(c[1]), "+f"(c[2]), "+f"(c[3])
        : "r"(a[0]), "r"(a[1]), "r"(a[2]), "r"(a[3]), "r"(b0), "r"(b1));
}

#define LDSM_X4(r0, r1, r2, r3, addr) \
    asm volatile("ldmatrix.sync.aligned.m8n8.x4.shared.b16 {%0,%1,%2,%3}, [%4];" \
                 : "=r"(r0), "=r"(r1), "=r"(r2), "=r"(r3) : "r"(addr))

// ---------------------------------------------------------------------------
// Dummy kernel: positions in_proj at ncu's capture slot (launch index 3)
// ---------------------------------------------------------------------------
__global__ void dummy_kernel() {}

// ---------------------------------------------------------------------------
// Weight pre-conversion (fp32 -> fp16)
// ---------------------------------------------------------------------------
#define NWI (2 * D_INNER * D_MODEL)
#define NWO (D_MODEL * D_INNER)
#define NWX (XDBL_COLS * D_INNER)
#define NWD (D_INNER * DT_RANK)
#define NW_TOTAL (NWI + NWO + NWX + NWD)

__global__ __launch_bounds__(256)
void cvt_weights_kernel(const float* __restrict__ wi, const float* __restrict__ wo,
                        const float* __restrict__ wx, const float* __restrict__ wd)
{
    int i = blockIdx.x * 256 + threadIdx.x;
    if (i < NWI)                       g_wi[i] = __float2half_rn(wi[i]);
    else if (i < NWI + NWO)            g_wo[i - NWI] = __float2half_rn(wo[i - NWI]);
    else if (i < NWI + NWO + NWX)      g_wx[i - NWI - NWO] = __float2half_rn(wx[i - NWI - NWO]);
    else if (i < NW_TOTAL)             g_wd[i - NWI - NWO - NWX] = __float2half_rn(wd[i - NWI - NWO - NWX]);
}

// ---------------------------------------------------------------------------
// RMSNorm -> fp16
// ---------------------------------------------------------------------------
__global__ __launch_bounds__(256)
void rmsnorm_kernel(const float* __restrict__ x, const float* __restrict__ w,
                    __half* __restrict__ out)
{
    int r = blockIdx.x;
    int t = threadIdx.x;
    const float4* xr = (const float4*)(x + (size_t)r * D_MODEL);
    float4 v = xr[t];
    float s = v.x * v.x + v.y * v.y + v.z * v.z + v.w * v.w;
    #pragma unroll
    for (int o = 16; o; o >>= 1) s += __shfl_xor_sync(0xffffffffu, s, o);

    __shared__ float ws[8];
    __shared__ float s_inv;
    if ((t & 31) == 0) ws[t >> 5] = s;
    __syncthreads();
    if (t == 0) {
        float tot = 0.f;
        #pragma unroll
        for (int i = 0; i < 8; i++) tot += ws[i];
        float rms = sqrtf(tot) * (1.0f / 32.0f);
        s_inv = 1.0f / (rms + EPS);
    }
    __syncthreads();
    float inv = s_inv;
    float4 wv = ((const float4*)w)[t];
    __half2 h0 = __floats2half2_rn(v.x * inv * wv.x, v.y * inv * wv.y);
    __half2 h1 = __floats2half2_rn(v.z * inv * wv.z, v.w * inv * wv.w);
    uint2 o;
    o.x = *(unsigned*)&h0;
    o.y = *(unsigned*)&h1;
    ((uint2*)(out + (size_t)r * D_MODEL))[t] = o;
}

// ---------------------------------------------------------------------------
// FP16 HMMA GEMM:  C[m][n] = sum_k A[m][k] * B[n][k]   (fp32 accumulate)
// Block tile 128x64, BK=64, 3-stage cp.async, ONE __syncthreads per ktile.
// Xor-swizzled 128B smem rows. 8 warps = 4(M) x 2(N), 3 CTAs/SM.
// ---------------------------------------------------------------------------
#define BK        64
#define STG       3
#define RB        128
#define A_BYTES   (128 * RB)
#define B_BYTES   (64 * RB)
#define STAGE_B   (A_BYTES + B_BYTES)
#define GEMM_SMEM (STG * STAGE_B)

template<int EPI>
__global__ __launch_bounds__(256, 3)
void gemm_h(const __half* __restrict__ A, int lda,
            const __half* __restrict__ B, int ldb,
            float* __restrict__ C, int ldc,
            __half* __restrict__ Caux,
            int N, int k_len, long long split_cstride,
            const float* __restrict__ bias)
{
    extern __shared__ unsigned char smem_raw[];
    const uint32_t smem = (uint32_t)__cvta_generic_to_shared(smem_raw);

    const int tid  = threadIdx.x;
    const int wid  = tid >> 5;
    const int lane = tid & 31;
    const int wm   = (wid & 3) * 32;
    const int wn   = (wid >> 2) * 32;

    const int bm = blockIdx.y * 128;
    const int bn = blockIdx.x * 64;
    const int k0base = blockIdx.z * k_len;
    C += (size_t)blockIdx.z * split_cstride;
    const int ktiles = k_len / BK;

    auto load_stage = [&](int stage, int kt) {
        const int k0 = k0base + kt * BK;
        const uint32_t sa = smem + stage * STAGE_B;
        const uint32_t sb = sa + A_BYTES;
        #pragma unroll
        for (int i = 0; i < 4; i++) {
            int lin = i * 256 + tid;
            int c   = lin & 7;
            int row = lin >> 3;
            uint32_t dst = sa + row * RB + ((c ^ (row & 7)) << 4);
            const __half* src = A + (size_t)(bm + row) * lda + k0 + c * 8;
            asm volatile("cp.async.cg.shared.global [%0], [%1], 16;"
                         :: "r"(dst), "l"(src));
        }
        #pragma unroll
        for (int i = 0; i < 2; i++) {
            int lin = i * 256 + tid;
            int c   = lin & 7;
            int row = lin >> 3;
            int gn  = bn + row;
            uint32_t dst = sb + row * RB + ((c ^ (row & 7)) << 4);
            const __half* src = B + (size_t)(gn < N ? gn : 0) * ldb + k0 + c * 8;
            int ok = (gn < N) ? 16 : 0;
            asm volatile("cp.async.cg.shared.global [%0], [%1], 16, %2;"
                         :: "r"(dst), "l"(src), "r"(ok));
        }
    };

    float acc[2][4][4];
    #pragma unroll
    for (int i = 0; i < 2; i++)
        #pragma unroll
        for (int j = 0; j < 4; j++)
            #pragma unroll
            for (int q = 0; q < 4; q++) acc[i][j][q] = 0.f;

    #pragma unroll
    for (int s = 0; s < STG - 1; s++) {
        if (s < ktiles) load_stage(s, s);
        asm volatile("cp.async.commit_group;");
    }

    const int a_row = ((lane >> 3) & 1) * 8 + (lane & 7);
    const int a_kh  = lane >> 4;
    const int b_row = (lane >> 4) * 8 + (lane & 7);
    const int b_kh  = (lane >> 3) & 1;
    const int lxor  = lane & 7;

    for (int kt = 0; kt < ktiles; kt++) {
        asm volatile("cp.async.wait_group %0;" :: "n"(STG - 2));
        __syncthreads();

        if (kt + STG - 1 < ktiles) load_stage((kt + STG - 1) % STG, kt + STG - 1);
        asm volatile("cp.async.commit_group;");

        const uint32_t Ab = smem + (kt % STG) * STAGE_B;
        const uint32_t Bb = Ab + A_BYTES;

        #pragma unroll
        for (int ks = 0; ks < 4; ks++) {
            const uint32_t ca = (uint32_t)((((ks << 1) | a_kh) ^ lxor) << 4);
            const uint32_t cb = (uint32_t)((((ks << 1) | b_kh) ^ lxor) << 4);
            uint32_t a[2][4], b[4][2];
            #pragma unroll
            for (int mt = 0; mt < 2; mt++) {
                uint32_t ad = Ab + (wm + mt * 16 + a_row) * RB + ca;
                LDSM_X4(a[mt][0], a[mt][1], a[mt][2], a[mt][3], ad);
            }
            #pragma unroll
            for (int np = 0; np < 2; np++) {
                uint32_t bd = Bb + (wn + np * 16 + b_row) * RB + cb;
                LDSM_X4(b[2 * np][0], b[2 * np][1], b[2 * np + 1][0], b[2 * np + 1][1], bd);
            }
            #pragma unroll
            for (int mt = 0; mt < 2; mt++)
                #pragma unroll
                for (int nt = 0; nt < 4; nt++)
                    mma_f16(acc[mt][nt], a[mt], b[nt][0], b[nt][1]);
        }
    }

    const int g4 = lane >> 2;
    const int t2 = (lane & 3) * 2;
    #pragma unroll
    for (int mt = 0; mt < 2; mt++) {
        int gm = bm + wm + mt * 16 + g4;
        #pragma unroll
        for (int nt = 0; nt < 4; nt++) {
            int gn = bn + wn + nt * 8 + t2;
            if (gn < N) {
                float2 v0 = make_float2(acc[mt][nt][0], acc[mt][nt][1]);
                float2 v1 = make_float2(acc[mt][nt][2], acc[mt][nt][3]);
                if (EPI == 1) {
                    float b0 = bias[gn], b1 = bias[gn + 1];
                    v0.x = softplusf(v0.x + b0);
                    v0.y = softplusf(v0.y + b1);
                    v1.x = softplusf(v1.x + b0);
                    v1.y = softplusf(v1.y + b1);
                }
                *(float2*)(C + (size_t)gm * ldc + gn)       = v0;
                *(float2*)(C + (size_t)(gm + 8) * ldc + gn) = v1;
                if (EPI == 2) {
                    __half2 h0 = __floats2half2_rn(v0.x, v0.y);
                    __half2 h1 = __floats2half2_rn(v1.x, v1.y);
                    *(__half2*)(Caux + (size_t)gm * ldc + gn)       = h0;
                    *(__half2*)(Caux + (size_t)(gm + 8) * ldc + gn) = h1;
                }
            }
        }
    }
}

// ---------------------------------------------------------------------------
// x_proj split-K reduce: sum 8 partials -> fp32 + fp16
// ---------------------------------------------------------------------------
__global__ __launch_bounds__(256)
void xp_reduce_kernel()
{
    int i = blockIdx.x * 256 + threadIdx.x;
    if (i >= ROWS * XDBL_COLS) return;
    float s = 0.f;
    #pragma unroll
    for (int p = 0; p < XP_SPLITS; p++)
        s += g_xpart[(size_t)p * ROWS * XDBL_COLS + i];
    g_xdbl[i]  = s;
    g_xdblt[i] = __float2half_rn(s);
}

// ---------------------------------------------------------------------------
// Depthwise causal conv + bias + SiLU -> fp32 (scan) + fp16 (x_proj A)
// ---------------------------------------------------------------------------
__global__ __launch_bounds__(256)
void conv_silu_kernel(const float* __restrict__ xz,
                      const float* __restrict__ cw,
                      const float* __restrict__ cb,
                      float* __restrict__ xc,
                      __half* __restrict__ xct)
{
    int idx = blockIdx.x * blockDim.x + threadIdx.x;
    if (idx >= ROWS * D_INNER) return;
    int d = idx & (D_INNER - 1);
    int r = idx >> 11;
    int l = r & (SEQLEN - 1);
    int b = r >> 10;

    float acc = cb[d];
    #pragma unroll
    for (int k = 0; k < D_CONV; k++) {
        int ls = l + k - (D_CONV - 1);
        if (ls >= 0)
            acc = fmaf(xz[((size_t)(b * SEQLEN + ls)) * (2 * D_INNER) + d],
                       cw[d * D_CONV + k], acc);
    }
    float sig = 1.0f / (1.0f + __expf(-acc));
    float v = acc * sig;
    xc[idx]  = v;
    xct[idx] = __float2half_rn(v);
}

// ---------------------------------------------------------------------------
// Selective scan, smem-chunked.
// Block = 256 threads = 16 channels x 16 states. 256 blocks.
// Per 64-step chunk: cooperative cp.async of dt/xc/z/B/C tiles (coalesced),
// double-buffered; compute reads broadcast LDS instead of strided L2.
// ---------------------------------------------------------------------------
#define SCH 64                                  // chunk length
#define NCH (SEQLEN / SCH)                      // 16 chunks

__global__ __launch_bounds__(256)
void scan_kernel(const float* __restrict__ xdbl,
                 const float* __restrict__ dt,
                 const float* __restrict__ xc,
                 const float* __restrict__ xz,
                 const float* __restrict__ A_log,
                 const float* __restrict__ Dw,
                 __half* __restrict__ y)
{
    // smem: [2 buffers][5 arrays][64][16] floats
    __shared__ float s_dt[2][SCH][16];
    __shared__ float s_xc[2][SCH][16];
    __shared__ float s_z [2][SCH][16];
    __shared__ float s_B [2][SCH][16];
    __shared__ float s_C [2][SCH][16];

    const int tid = threadIdx.x;
    const int n   = tid & 15;          // state
    const int dl  = tid >> 4;          // local channel 0..15
    const int b   = blockIdx.x >> 7;   // 128 blocks per batch
    const int d0  = (blockIdx.x & 127) * 16;
    const int d   = d0 + dl;

    const float A  = -__expf(A_log[d * D_STATE + n]);
    const float Dd = Dw[d];

    // loader mapping: thread covers (row l = tid>>2, float4 c = tid&3)
    const int lr = tid >> 2;           // 0..63
    const int lc = tid & 3;            // 0..3

    const float* dt_g = dt   + (size_t)b * SEQLEN * D_INNER + d0 + lc * 4;
    const float* xc_g = xc   + (size_t)b * SEQLEN * D_INNER + d0 + lc * 4;
    const float* z_g  = xz   + (size_t)b * SEQLEN * (2 * D_INNER) + D_INNER + d0 + lc * 4;
    const float* B_g  = xdbl + (size_t)b * SEQLEN * XDBL_COLS + DT_RANK + lc * 4;
    const float* C_g  = B_g + D_STATE;

    auto load_chunk = [&](int ch, int buf) {
        int l = ch * SCH + lr;
        uint32_t ddt = (uint32_t)__cvta_generic_to_shared(&s_dt[buf][lr][lc * 4]);
        uint32_t dxc = (uint32_t)__cvta_generic_to_shared(&s_xc[buf][lr][lc * 4]);
        uint32_t dz  = (uint32_t)__cvta_generic_to_shared(&s_z [buf][lr][lc * 4]);
        uint32_t dB  = (uint32_t)__cvta_generic_to_shared(&s_B [buf][lr][lc * 4]);
        uint32_t dC  = (uint32_t)__cvta_generic_to_shared(&s_C [buf][lr][lc * 4]);
        asm volatile("cp.async.cg.shared.global [%0], [%1], 16;"
                     :: "r"(ddt), "l"(dt_g + (size_t)l * D_INNER));
        asm volatile("cp.async.cg.shared.global [%0], [%1], 16;"
                     :: "r"(dxc), "l"(xc_g + (size_t)l * D_INNER));
        asm volatile("cp.async.cg.shared.global [%0], [%1], 16;"
                     :: "r"(dz),  "l"(z_g + (size_t)l * (2 * D_INNER)));
        asm volatile("cp.async.cg.shared.global [%0], [%1], 16;"
                     :: "r"(dB),  "l"(B_g + (size_t)l * XDBL_COLS));
        asm volatile("cp.async.cg.shared.global [%0], [%1], 16;"
                     :: "r"(dC),  "l"(C_g + (size_t)l * XDBL_COLS));
    };

    __half* y_b = y + (size_t)b * SEQLEN * D_INNER + d;

    // prologue
    load_chunk(0, 0);
    asm volatile("cp.async.commit_group;");

    float h = 0.f;
    for (int ch = 0; ch < NCH; ch++) {
        const int buf = ch & 1;
        if (ch + 1 < NCH) load_chunk(ch + 1, buf ^ 1);
        asm volatile("cp.async.commit_group;");
        if (ch + 1 < NCH) asm volatile("cp.async.wait_group 1;");
        else              asm volatile("cp.async.wait_group 0;");
        __syncthreads();

        #pragma unroll 4
        for (int l = 0; l < SCH; l++) {
            float dtv = s_dt[buf][l][dl];
            float xcv = s_xc[buf][l][dl];
            float Bv  = s_B [buf][l][n];
            float Cv  = s_C [buf][l][n];

            float dA = __expf(dtv * A);
            h = fmaf(dA, h, dtv * xcv * Bv);

            float p = h * Cv;
            p += __shfl_xor_sync(0xffffffffu, p, 8);
            p += __shfl_xor_sync(0xffffffffu, p, 4);
            p += __shfl_xor_sync(0xffffffffu, p, 2);
            p += __shfl_xor_sync(0xffffffffu, p, 1);

            if (n == 0) {
                float zv  = s_z[buf][l][dl];
                float sil = zv / (1.0f + __expf(-zv));
                y_b[(size_t)(ch * SCH + l) * D_INNER] =
                    __float2half_rn((p + Dd * xcv) * sil);
            }
        }
        __syncthreads();
    }
}

// ---------------------------------------------------------------------------
// Launch
// ---------------------------------------------------------------------------
extern "C" void kernel_launch(void* const* d_in, const int* in_sizes, int n_in,
                              void* d_out, int out_size)
{
    const float* hidden   = (const float*)d_in[0];
    const float* norm_w   = (const float*)d_in[1];
    const float* in_proj  = (const float*)d_in[2];
    const float* conv_w   = (const float*)d_in[3];
    const float* conv_b   = (const float*)d_in[4];
    const float* x_proj   = (const float*)d_in[5];
    const float* dt_proj  = (const float*)d_in[6];
    const float* dt_b     = (const float*)d_in[7];
    const float* A_log    = (const float*)d_in[8];
    const float* Dw       = (const float*)d_in[9];
    const float* out_proj = (const float*)d_in[10];

    float* out = (float*)d_out;

    __half *ht, *xct, *xdblt, *yt, *wi, *wo, *wx, *wd;
    float *xz, *xc, *xpart, *xdbl, *dt;
    cudaGetSymbolAddress((void**)&ht,    g_ht);
    cudaGetSymbolAddress((void**)&xz,    g_xz);
    cudaGetSymbolAddress((void**)&xc,    g_xc);
    cudaGetSymbolAddress((void**)&xct,   g_xct);
    cudaGetSymbolAddress((void**)&xpart, g_xpart);
    cudaGetSymbolAddress((void**)&xdbl,  g_xdbl);
    cudaGetSymbolAddress((void**)&xdblt, g_xdblt);
    cudaGetSymbolAddress((void**)&dt,    g_dt);
    cudaGetSymbolAddress((void**)&yt,    g_yt);
    cudaGetSymbolAddress((void**)&wi,    g_wi);
    cudaGetSymbolAddress((void**)&wo,    g_wo);
    cudaGetSymbolAddress((void**)&wx,    g_wx);
    cudaGetSymbolAddress((void**)&wd,    g_wd);

    cudaFuncSetAttribute(gemm_h<0>, cudaFuncAttributeMaxDynamicSharedMemorySize, GEMM_SMEM);
    cudaFuncSetAttribute(gemm_h<1>, cudaFuncAttributeMaxDynamicSharedMemorySize, GEMM_SMEM);
    cudaFuncSetAttribute(gemm_h<2>, cudaFuncAttributeMaxDynamicSharedMemorySize, GEMM_SMEM);

    // 0. weight conversion (fp16)                                  [launch 0]
    cvt_weights_kernel<<<(NW_TOTAL + 255) / 256, 256>>>(in_proj, out_proj, x_proj, dt_proj);

    // 1. RMSNorm -> fp16                                           [launch 1]
    rmsnorm_kernel<<<ROWS, 256>>>(hidden, norm_w, ht);

    // 1b. dummy: keep in_proj at ncu capture slot (index 3)        [launch 2]
    dummy_kernel<<<1, 32>>>();

    // 2. in_proj: (2048 x 1024) @ (4096 x 1024)^T -> xz            [launch 3]
    gemm_h<0><<<dim3(2 * D_INNER / 64, ROWS / 128, 1), 256, GEMM_SMEM>>>(
        ht, D_MODEL, wi, D_MODEL, xz, 2 * D_INNER, nullptr,
        2 * D_INNER, D_MODEL, 0, nullptr);

    // 3. conv + silu -> xc fp32 + xct fp16
    conv_silu_kernel<<<(ROWS * D_INNER) / 256, 256>>>(xz, conv_w, conv_b, xc, xct);

    // 4. x_proj split-K: (2048 x 2048) @ (96 x 2048)^T -> 8 partials
    gemm_h<0><<<dim3(2, ROWS / 128, XP_SPLITS), 256, GEMM_SMEM>>>(
        xct, D_INNER, wx, D_INNER, xpart, XDBL_COLS, nullptr,
        XDBL_COLS, XP_KSPL, (long long)ROWS * XDBL_COLS, nullptr);

    // 4b. reduce -> xdbl fp32 + xdblt fp16
    xp_reduce_kernel<<<(ROWS * XDBL_COLS + 255) / 256, 256>>>();

    // 5. dt_proj + softplus: (2048 x 96[:64]) @ (2048 x 64)^T -> dt fp32
    gemm_h<1><<<dim3(D_INNER / 64, ROWS / 128, 1), 256, GEMM_SMEM>>>(
        xdblt, XDBL_COLS, wd, DT_RANK, dt, D_INNER, nullptr,
        D_INNER, DT_RANK, 0, dt_b);

    // 6. selective scan + gate -> yt fp16 (smem-chunked)
    scan_kernel<<<BATCH * D_INNER / 16, 256>>>(
        xdbl, dt, xc, xz, A_log, Dw, yt);

    // 7. out_proj: (2048 x 2048) @ (1024 x 2048)^T -> out fp32
    gemm_h<0><<<dim3(D_MODEL / 64, ROWS / 128, 1), 256, GEMM_SMEM>>>(
        yt, D_INNER, wo, D_INNER, out, D_MODEL, nullptr,
        D_MODEL, D_INNER, 0, nullptr);

    // 8. residual
    size_t half = (size_t)out_size / 2;
    cudaMemcpyAsync(out + half, hidden, half * sizeof(float),
                    cudaMemcpyDeviceToDevice);
}

// round 11
// speedup vs baseline: 7.5684x; 1.0225x over previous
#include <cuda_runtime.h>
#include <cuda_fp16.h>
#include <math.h>
#include <stdint.h>

// ---------------------------------------------------------------------------
// Problem constants
// ---------------------------------------------------------------------------
#define D_MODEL   1024
#define D_STATE   16
#define D_CONV    4
#define D_INNER   2048
#define DT_RANK   64
#define BATCH     2
#define SEQLEN    1024
#define ROWS      (BATCH * SEQLEN)          // 2048
#define XDBL_COLS (DT_RANK + 2 * D_STATE)   // 96
#define EPS       1e-5f

#define XP_SPLITS 8
#define XP_KSPL   (D_INNER / XP_SPLITS)     // 256

// ---------------------------------------------------------------------------
// Scratch (__device__ globals; no cudaMalloc allowed)
// ---------------------------------------------------------------------------
__device__ __half g_ht  [ROWS * D_MODEL];        // rmsnorm out (fp16)
__device__ float  g_xz  [ROWS * 2 * D_INNER];    // in_proj out (x | z) fp32
__device__ float  g_xc  [ROWS * D_INNER];        // conv+silu fp32 (scan)
__device__ __half g_xct [ROWS * D_INNER];        // conv+silu fp16 (x_proj A)
__device__ float  g_xpart[XP_SPLITS * ROWS * XDBL_COLS]; // split-K partials
__device__ float  g_xdbl [ROWS * XDBL_COLS];     // x_proj out fp32 (scan B,C)
__device__ __half g_xdblt[ROWS * XDBL_COLS];     // x_proj out fp16 (dt A)
__device__ float  g_dt  [ROWS * D_INNER];        // softplus(dt) fp32
__device__ __half g_yt  [ROWS * D_INNER];        // scan out fp16 (out_proj A)
__device__ __half g_wi  [2 * D_INNER * D_MODEL]; // fp16 weights
__device__ __half g_wo  [D_MODEL * D_INNER];
__device__ __half g_wx  [XDBL_COLS * D_INNER];
__device__ __half g_wd  [D_INNER * DT_RANK];

// ---------------------------------------------------------------------------
// Helpers
// ---------------------------------------------------------------------------
__device__ __forceinline__ float softplusf(float v)
{
    return v > 20.f ? v : log1pf(__expf(v));
}

__device__ __forceinline__ void mma_f16(float c[4], const uint32_t a[4],
                                        const uint32_t b0, const uint32_t b1)
{
    asm volatile(
        "mma.sync.aligned.m16n8k16.row.col.f32.f16.f16.f32 "
        "{%0,%1,%2,%3}, {%4,%5,%6,%7}, {%8,%9}, {%0,%1,%2,%3};"
        : "+f"(c[0]), "+f"(c[1]), "+f"(c[2]), "+f"(c[3])
        : "r"(a[0]), "r"(a[1]), "r"(a[2]), "r"(a[3]), "r"(b0), "r"(b1));
}

#define LDSM_X4(r0, r1, r2, r3, addr) \
    asm volatile("ldmatrix.sync.aligned.m8n8.x4.shared.b16 {%0,%1,%2,%3}, [%4];" \
                 : "=r"(r0), "=r"(r1), "=r"(r2), "=r"(r3) : "r"(addr))

// ---------------------------------------------------------------------------
// Dummy kernel: positions in_proj at ncu's capture slot (launch index 3)
// ---------------------------------------------------------------------------
__global__ void dummy_kernel() {}

// ---------------------------------------------------------------------------
// Weight pre-conversion (fp32 -> fp16)
// ---------------------------------------------------------------------------
#define NWI (2 * D_INNER * D_MODEL)
#define NWO (D_MODEL * D_INNER)
#define NWX (XDBL_COLS * D_INNER)
#define NWD (D_INNER * DT_RANK)
#define NW_TOTAL (NWI + NWO + NWX + NWD)

__global__ __launch_bounds__(256)
void cvt_weights_kernel(const float* __restrict__ wi, const float* __restrict__ wo,
                        const float* __restrict__ wx, const float* __restrict__ wd)
{
    int i = blockIdx.x * 256 + threadIdx.x;
    if (i < NWI)                       g_wi[i] = __float2half_rn(wi[i]);
    else if (i < NWI + NWO)            g_wo[i - NWI] = __float2half_rn(wo[i - NWI]);
    else if (i < NWI + NWO + NWX)      g_wx[i - NWI - NWO] = __float2half_rn(wx[i - NWI - NWO]);
    else if (i < NW_TOTAL)             g_wd[i - NWI - NWO - NWX] = __float2half_rn(wd[i - NWI - NWO - NWX]);
}

// ---------------------------------------------------------------------------
// RMSNorm -> fp16, and store raw input to output residual half (kills memcpy)
// ---------------------------------------------------------------------------
__global__ __launch_bounds__(256)
void rmsnorm_kernel(const float* __restrict__ x, const float* __restrict__ w,
                    __half* __restrict__ out, float* __restrict__ resid)
{
    int r = blockIdx.x;
    int t = threadIdx.x;
    const float4* xr = (const float4*)(x + (size_t)r * D_MODEL);
    float4 v = xr[t];
    float s = v.x * v.x + v.y * v.y + v.z * v.z + v.w * v.w;
    #pragma unroll
    for (int o = 16; o; o >>= 1) s += __shfl_xor_sync(0xffffffffu, s, o);

    __shared__ float ws[8];
    __shared__ float s_inv;
    if ((t & 31) == 0) ws[t >> 5] = s;
    __syncthreads();
    if (t == 0) {
        float tot = 0.f;
        #pragma unroll
        for (int i = 0; i < 8; i++) tot += ws[i];
        float rms = sqrtf(tot) * (1.0f / 32.0f);
        s_inv = 1.0f / (rms + EPS);
    }
    __syncthreads();
    float inv = s_inv;
    float4 wv = ((const float4*)w)[t];
    __half2 h0 = __floats2half2_rn(v.x * inv * wv.x, v.y * inv * wv.y);
    __half2 h1 = __floats2half2_rn(v.z * inv * wv.z, v.w * inv * wv.w);
    uint2 o;
    o.x = *(unsigned*)&h0;
    o.y = *(unsigned*)&h1;
    ((uint2*)(out + (size_t)r * D_MODEL))[t] = o;
    ((float4*)(resid + (size_t)r * D_MODEL))[t] = v;   // residual passthrough
}

// ---------------------------------------------------------------------------
// FP16 HMMA GEMM:  C[m][n] = sum_k A[m][k] * B[n][k]   (fp32 accumulate)
// Block tile 128x64, BK=64, 3-stage cp.async, ONE __syncthreads per ktile.
// Xor-swizzled 128B smem rows. 8 warps = 4(M) x 2(N), 3 CTAs/SM.
// ---------------------------------------------------------------------------
#define BK        64
#define STG       3
#define RB        128
#define A_BYTES   (128 * RB)
#define B_BYTES   (64 * RB)
#define STAGE_B   (A_BYTES + B_BYTES)
#define GEMM_SMEM (STG * STAGE_B)

template<int EPI>
__global__ __launch_bounds__(256, 3)
void gemm_h(const __half* __restrict__ A, int lda,
            const __half* __restrict__ B, int ldb,
            float* __restrict__ C, int ldc,
            __half* __restrict__ Caux,
            int N, int k_len, long long split_cstride,
            const float* __restrict__ bias)
{
    extern __shared__ unsigned char smem_raw[];
    const uint32_t smem = (uint32_t)__cvta_generic_to_shared(smem_raw);

    const int tid  = threadIdx.x;
    const int wid  = tid >> 5;
    const int lane = tid & 31;
    const int wm   = (wid & 3) * 32;
    const int wn   = (wid >> 2) * 32;

    const int bm = blockIdx.y * 128;
    const int bn = blockIdx.x * 64;
    const int k0base = blockIdx.z * k_len;
    C += (size_t)blockIdx.z * split_cstride;
    const int ktiles = k_len / BK;

    auto load_stage = [&](int stage, int kt) {
        const int k0 = k0base + kt * BK;
        const uint32_t sa = smem + stage * STAGE_B;
        const uint32_t sb = sa + A_BYTES;
        #pragma unroll
        for (int i = 0; i < 4; i++) {
            int lin = i * 256 + tid;
            int c   = lin & 7;
            int row = lin >> 3;
            uint32_t dst = sa + row * RB + ((c ^ (row & 7)) << 4);
            const __half* src = A + (size_t)(bm + row) * lda + k0 + c * 8;
            asm volatile("cp.async.cg.shared.global [%0], [%1], 16;"
                         :: "r"(dst), "l"(src));
        }
        #pragma unroll
        for (int i = 0; i < 2; i++) {
            int lin = i * 256 + tid;
            int c   = lin & 7;
            int row = lin >> 3;
            int gn  = bn + row;
            uint32_t dst = sb + row * RB + ((c ^ (row & 7)) << 4);
            const __half* src = B + (size_t)(gn < N ? gn : 0) * ldb + k0 + c * 8;
            int ok = (gn < N) ? 16 : 0;
            asm volatile("cp.async.cg.shared.global [%0], [%1], 16, %2;"
                         :: "r"(dst), "l"(src), "r"(ok));
        }
    };

    float acc[2][4][4];
    #pragma unroll
    for (int i = 0; i < 2; i++)
        #pragma unroll
        for (int j = 0; j < 4; j++)
            #pragma unroll
            for (int q = 0; q < 4; q++) acc[i][j][q] = 0.f;

    #pragma unroll
    for (int s = 0; s < STG - 1; s++) {
        if (s < ktiles) load_stage(s, s);
        asm volatile("cp.async.commit_group;");
    }

    const int a_row = ((lane >> 3) & 1) * 8 + (lane & 7);
    const int a_kh  = lane >> 4;
    const int b_row = (lane >> 4) * 8 + (lane & 7);
    const int b_kh  = (lane >> 3) & 1;
    const int lxor  = lane & 7;

    for (int kt = 0; kt < ktiles; kt++) {
        asm volatile("cp.async.wait_group %0;" :: "n"(STG - 2));
        __syncthreads();

        if (kt + STG - 1 < ktiles) load_stage((kt + STG - 1) % STG, kt + STG - 1);
        asm volatile("cp.async.commit_group;");

        const uint32_t Ab = smem + (kt % STG) * STAGE_B;
        const uint32_t Bb = Ab + A_BYTES;

        #pragma unroll
        for (int ks = 0; ks < 4; ks++) {
            const uint32_t ca = (uint32_t)((((ks << 1) | a_kh) ^ lxor) << 4);
            const uint32_t cb = (uint32_t)((((ks << 1) | b_kh) ^ lxor) << 4);
            uint32_t a[2][4], b[4][2];
            #pragma unroll
            for (int mt = 0; mt < 2; mt++) {
                uint32_t ad = Ab + (wm + mt * 16 + a_row) * RB + ca;
                LDSM_X4(a[mt][0], a[mt][1], a[mt][2], a[mt][3], ad);
            }
            #pragma unroll
            for (int np = 0; np < 2; np++) {
                uint32_t bd = Bb + (wn + np * 16 + b_row) * RB + cb;
                LDSM_X4(b[2 * np][0], b[2 * np][1], b[2 * np + 1][0], b[2 * np + 1][1], bd);
            }
            #pragma unroll
            for (int mt = 0; mt < 2; mt++)
                #pragma unroll
                for (int nt = 0; nt < 4; nt++)
                    mma_f16(acc[mt][nt], a[mt], b[nt][0], b[nt][1]);
        }
    }

    const int g4 = lane >> 2;
    const int t2 = (lane & 3) * 2;
    #pragma unroll
    for (int mt = 0; mt < 2; mt++) {
        int gm = bm + wm + mt * 16 + g4;
        #pragma unroll
        for (int nt = 0; nt < 4; nt++) {
            int gn = bn + wn + nt * 8 + t2;
            if (gn < N) {
                float2 v0 = make_float2(acc[mt][nt][0], acc[mt][nt][1]);
                float2 v1 = make_float2(acc[mt][nt][2], acc[mt][nt][3]);
                if (EPI == 1) {
                    float b0 = bias[gn], b1 = bias[gn + 1];
                    v0.x = softplusf(v0.x + b0);
                    v0.y = softplusf(v0.y + b1);
                    v1.x = softplusf(v1.x + b0);
                    v1.y = softplusf(v1.y + b1);
                }
                *(float2*)(C + (size_t)gm * ldc + gn)       = v0;
                *(float2*)(C + (size_t)(gm + 8) * ldc + gn) = v1;
                if (EPI == 2) {
                    __half2 h0 = __floats2half2_rn(v0.x, v0.y);
                    __half2 h1 = __floats2half2_rn(v1.x, v1.y);
                    *(__half2*)(Caux + (size_t)gm * ldc + gn)       = h0;
                    *(__half2*)(Caux + (size_t)(gm + 8) * ldc + gn) = h1;
                }
            }
        }
    }
}

// ---------------------------------------------------------------------------
// x_proj split-K reduce: sum 8 partials -> fp32 + fp16
// ---------------------------------------------------------------------------
__global__ __launch_bounds__(256)
void xp_reduce_kernel()
{
    int i = blockIdx.x * 256 + threadIdx.x;
    if (i >= ROWS * XDBL_COLS) return;
    float s = 0.f;
    #pragma unroll
    for (int p = 0; p < XP_SPLITS; p++)
        s += g_xpart[(size_t)p * ROWS * XDBL_COLS + i];
    g_xdbl[i]  = s;
    g_xdblt[i] = __float2half_rn(s);
}

// ---------------------------------------------------------------------------
// Depthwise causal conv + bias + SiLU, 4 timesteps per thread (register reuse)
// -> fp32 (scan) + fp16 (x_proj A). 7 loads per 4 outputs.
// ---------------------------------------------------------------------------
__global__ __launch_bounds__(256)
void conv_silu_kernel(const float* __restrict__ xz,
                      const float* __restrict__ cw,
                      const float* __restrict__ cb,
                      float* __restrict__ xc,
                      __half* __restrict__ xct)
{
    int idx = blockIdx.x * blockDim.x + threadIdx.x;   // over ROWS/4 * D_INNER
    if (idx >= (ROWS / 4) * D_INNER) return;
    int d  = idx & (D_INNER - 1);
    int r4 = idx >> 11;                 // group of 4 rows
    int l0 = (r4 & (SEQLEN / 4 - 1)) * 4;
    int b  = r4 >> 8;                   // / (SEQLEN/4)

    const float* x_b = xz + (size_t)b * SEQLEN * (2 * D_INNER) + d;
    float w0 = cw[d * D_CONV + 0], w1 = cw[d * D_CONV + 1];
    float w2 = cw[d * D_CONV + 2], w3 = cw[d * D_CONV + 3];
    float bias = cb[d];

    // x[l0-3 .. l0+3] (7 values), zero for l < 0
    float xm3 = (l0 >= 3) ? x_b[(size_t)(l0 - 3) * (2 * D_INNER)] : 0.f;
    float xm2 = (l0 >= 2) ? x_b[(size_t)(l0 - 2) * (2 * D_INNER)] : 0.f;
    float xm1 = (l0 >= 1) ? x_b[(size_t)(l0 - 1) * (2 * D_INNER)] : 0.f;
    float x0  = x_b[(size_t)(l0 + 0) * (2 * D_INNER)];
    float x1  = x_b[(size_t)(l0 + 1) * (2 * D_INNER)];
    float x2  = x_b[(size_t)(l0 + 2) * (2 * D_INNER)];
    float x3  = x_b[(size_t)(l0 + 3) * (2 * D_INNER)];

    float o[4];
    o[0] = bias + xm3 * w0 + xm2 * w1 + xm1 * w2 + x0 * w3;
    o[1] = bias + xm2 * w0 + xm1 * w1 + x0  * w2 + x1 * w3;
    o[2] = bias + xm1 * w0 + x0  * w1 + x1  * w2 + x2 * w3;
    o[3] = bias + x0  * w0 + x1  * w1 + x2  * w2 + x3 * w3;

    size_t base = (size_t)(b * SEQLEN + l0) * D_INNER + d;
    #pragma unroll
    for (int i = 0; i < 4; i++) {
        float v = o[i] / (1.0f + __expf(-o[i]));
        xc [base + (size_t)i * D_INNER] = v;
        xct[base + (size_t)i * D_INNER] = __float2half_rn(v);
    }
}

// ---------------------------------------------------------------------------
// Selective scan, smem-chunked.
// Block = 256 threads = 16 channels x 16 states. 256 blocks.
// ---------------------------------------------------------------------------
#define SCH 64                                  // chunk length
#define NCH (SEQLEN / SCH)                      // 16 chunks

__global__ __launch_bounds__(256)
void scan_kernel(const float* __restrict__ xdbl,
                 const float* __restrict__ dt,
                 const float* __restrict__ xc,
                 const float* __restrict__ xz,
                 const float* __restrict__ A_log,
                 const float* __restrict__ Dw,
                 __half* __restrict__ y)
{
    __shared__ float s_dt[2][SCH][16];
    __shared__ float s_xc[2][SCH][16];
    __shared__ float s_z [2][SCH][16];
    __shared__ float s_B [2][SCH][16];
    __shared__ float s_C [2][SCH][16];

    const int tid = threadIdx.x;
    const int n   = tid & 15;
    const int dl  = tid >> 4;
    const int b   = blockIdx.x >> 7;
    const int d0  = (blockIdx.x & 127) * 16;
    const int d   = d0 + dl;

    const float A  = -__expf(A_log[d * D_STATE + n]);
    const float Dd = Dw[d];

    const int lr = tid >> 2;
    const int lc = tid & 3;

    const float* dt_g = dt   + (size_t)b * SEQLEN * D_INNER + d0 + lc * 4;
    const float* xc_g = xc   + (size_t)b * SEQLEN * D_INNER + d0 + lc * 4;
    const float* z_g  = xz   + (size_t)b * SEQLEN * (2 * D_INNER) + D_INNER + d0 + lc * 4;
    const float* B_g  = xdbl + (size_t)b * SEQLEN * XDBL_COLS + DT_RANK + lc * 4;
    const float* C_g  = B_g + D_STATE;

    auto load_chunk = [&](int ch, int buf) {
        int l = ch * SCH + lr;
        uint32_t ddt = (uint32_t)__cvta_generic_to_shared(&s_dt[buf][lr][lc * 4]);
        uint32_t dxc = (uint32_t)__cvta_generic_to_shared(&s_xc[buf][lr][lc * 4]);
        uint32_t dz  = (uint32_t)__cvta_generic_to_shared(&s_z [buf][lr][lc * 4]);
        uint32_t dB  = (uint32_t)__cvta_generic_to_shared(&s_B [buf][lr][lc * 4]);
        uint32_t dC  = (uint32_t)__cvta_generic_to_shared(&s_C [buf][lr][lc * 4]);
        asm volatile("cp.async.cg.shared.global [%0], [%1], 16;"
                     :: "r"(ddt), "l"(dt_g + (size_t)l * D_INNER));
        asm volatile("cp.async.cg.shared.global [%0], [%1], 16;"
                     :: "r"(dxc), "l"(xc_g + (size_t)l * D_INNER));
        asm volatile("cp.async.cg.shared.global [%0], [%1], 16;"
                     :: "r"(dz),  "l"(z_g + (size_t)l * (2 * D_INNER)));
        asm volatile("cp.async.cg.shared.global [%0], [%1], 16;"
                     :: "r"(dB),  "l"(B_g + (size_t)l * XDBL_COLS));
        asm volatile("cp.async.cg.shared.global [%0], [%1], 16;"
                     :: "r"(dC),  "l"(C_g + (size_t)l * XDBL_COLS));
    };

    __half* y_b = y + (size_t)b * SEQLEN * D_INNER + d;

    load_chunk(0, 0);
    asm volatile("cp.async.commit_group;");

    float h = 0.f;
    for (int ch = 0; ch < NCH; ch++) {
        const int buf = ch & 1;
        if (ch + 1 < NCH) load_chunk(ch + 1, buf ^ 1);
        asm volatile("cp.async.commit_group;");
        if (ch + 1 < NCH) asm volatile("cp.async.wait_group 1;");
        else              asm volatile("cp.async.wait_group 0;");
        __syncthreads();

        #pragma unroll 4
        for (int l = 0; l < SCH; l++) {
            float dtv = s_dt[buf][l][dl];
            float xcv = s_xc[buf][l][dl];
            float Bv  = s_B [buf][l][n];
            float Cv  = s_C [buf][l][n];

            float dA = __expf(dtv * A);
            h = fmaf(dA, h, dtv * xcv * Bv);

            float p = h * Cv;
            p += __shfl_xor_sync(0xffffffffu, p, 8);
            p += __shfl_xor_sync(0xffffffffu, p, 4);
            p += __shfl_xor_sync(0xffffffffu, p, 2);
            p += __shfl_xor_sync(0xffffffffu, p, 1);

            if (n == 0) {
                float zv  = s_z[buf][l][dl];
                float sil = zv / (1.0f + __expf(-zv));
                y_b[(size_t)(ch * SCH + l) * D_INNER] =
                    __float2half_rn((p + Dd * xcv) * sil);
            }
        }
        __syncthreads();
    }
}

// ---------------------------------------------------------------------------
// Launch
// ---------------------------------------------------------------------------
extern "C" void kernel_launch(void* const* d_in, const int* in_sizes, int n_in,
                              void* d_out, int out_size)
{
    const float* hidden   = (const float*)d_in[0];
    const float* norm_w   = (const float*)d_in[1];
    const float* in_proj  = (const float*)d_in[2];
    const float* conv_w   = (const float*)d_in[3];
    const float* conv_b   = (const float*)d_in[4];
    const float* x_proj   = (const float*)d_in[5];
    const float* dt_proj  = (const float*)d_in[6];
    const float* dt_b     = (const float*)d_in[7];
    const float* A_log    = (const float*)d_in[8];
    const float* Dw       = (const float*)d_in[9];
    const float* out_proj = (const float*)d_in[10];

    float* out = (float*)d_out;
    size_t half = (size_t)out_size / 2;

    __half *ht, *xct, *xdblt, *yt, *wi, *wo, *wx, *wd;
    float *xz, *xc, *xpart, *xdbl, *dt;
    cudaGetSymbolAddress((void**)&ht,    g_ht);
    cudaGetSymbolAddress((void**)&xz,    g_xz);
    cudaGetSymbolAddress((void**)&xc,    g_xc);
    cudaGetSymbolAddress((void**)&xct,   g_xct);
    cudaGetSymbolAddress((void**)&xpart, g_xpart);
    cudaGetSymbolAddress((void**)&xdbl,  g_xdbl);
    cudaGetSymbolAddress((void**)&xdblt, g_xdblt);
    cudaGetSymbolAddress((void**)&dt,    g_dt);
    cudaGetSymbolAddress((void**)&yt,    g_yt);
    cudaGetSymbolAddress((void**)&wi,    g_wi);
    cudaGetSymbolAddress((void**)&wo,    g_wo);
    cudaGetSymbolAddress((void**)&wx,    g_wx);
    cudaGetSymbolAddress((void**)&wd,    g_wd);

    cudaFuncSetAttribute(gemm_h<0>, cudaFuncAttributeMaxDynamicSharedMemorySize, GEMM_SMEM);
    cudaFuncSetAttribute(gemm_h<1>, cudaFuncAttributeMaxDynamicSharedMemorySize, GEMM_SMEM);
    cudaFuncSetAttribute(gemm_h<2>, cudaFuncAttributeMaxDynamicSharedMemorySize, GEMM_SMEM);

    // 0. weight conversion (fp16)                                  [launch 0]
    cvt_weights_kernel<<<(NW_TOTAL + 255) / 256, 256>>>(in_proj, out_proj, x_proj, dt_proj);

    // 1. RMSNorm -> fp16 + residual passthrough                    [launch 1]
    rmsnorm_kernel<<<ROWS, 256>>>(hidden, norm_w, ht, out + half);

    // 1b. dummy: keep in_proj at ncu capture slot (index 3)        [launch 2]
    dummy_kernel<<<1, 32>>>();

    // 2. in_proj: (2048 x 1024) @ (4096 x 1024)^T -> xz            [launch 3]
    gemm_h<0><<<dim3(2 * D_INNER / 64, ROWS / 128, 1), 256, GEMM_SMEM>>>(
        ht, D_MODEL, wi, D_MODEL, xz, 2 * D_INNER, nullptr,
        2 * D_INNER, D_MODEL, 0, nullptr);

    // 3. conv + silu (4 timesteps/thread) -> xc fp32 + xct fp16
    conv_silu_kernel<<<(ROWS / 4) * D_INNER / 256, 256>>>(xz, conv_w, conv_b, xc, xct);

    // 4. x_proj split-K: (2048 x 2048) @ (96 x 2048)^T -> 8 partials
    gemm_h<0><<<dim3(2, ROWS / 128, XP_SPLITS), 256, GEMM_SMEM>>>(
        xct, D_INNER, wx, D_INNER, xpart, XDBL_COLS, nullptr,
        XDBL_COLS, XP_KSPL, (long long)ROWS * XDBL_COLS, nullptr);

    // 4b. reduce -> xdbl fp32 + xdblt fp16
    xp_reduce_kernel<<<(ROWS * XDBL_COLS + 255) / 256, 256>>>();

    // 5. dt_proj + softplus: (2048 x 96[:64]) @ (2048 x 64)^T -> dt fp32
    gemm_h<1><<<dim3(D_INNER / 64, ROWS / 128, 1), 256, GEMM_SMEM>>>(
        xdblt, XDBL_COLS, wd, DT_RANK, dt, D_INNER, nullptr,
        D_INNER, DT_RANK, 0, dt_b);

    // 6. selective scan + gate -> yt fp16 (smem-chunked)
    scan_kernel<<<BATCH * D_INNER / 16, 256>>>(
        xdbl, dt, xc, xz, A_log, Dw, yt);

    // 7. out_proj: (2048 x 2048) @ (1024 x 2048)^T -> out fp32
    gemm_h<0><<<dim3(D_MODEL / 64, ROWS / 128, 1), 256, GEMM_SMEM>>>(
        yt, D_INNER, wo, D_INNER, out, D_MODEL, nullptr,
        D_MODEL, D_INNER, 0, nullptr);
}

// round 12
// speedup vs baseline: 13.8656x; 1.8320x over previous
#include <cuda_runtime.h>
#include <cuda_fp16.h>
#include <math.h>
#include <stdint.h>

// ---------------------------------------------------------------------------
// Problem constants
// ---------------------------------------------------------------------------
#define D_MODEL   1024
#define D_STATE   16
#define D_CONV    4
#define D_INNER   2048
#define DT_RANK   64
#define BATCH     2
#define SEQLEN    1024
#define ROWS      (BATCH * SEQLEN)          // 2048
#define XDBL_COLS (DT_RANK + 2 * D_STATE)   // 96
#define EPS       1e-5f

#define XP_SPLITS 8
#define XP_KSPL   (D_INNER / XP_SPLITS)     // 256
#define OP_SPLITS 2
#define OP_KSPL   (D_INNER / OP_SPLITS)     // 1024

// ---------------------------------------------------------------------------
// Scratch (__device__ globals; no cudaMalloc allowed)
// ---------------------------------------------------------------------------
__device__ __half g_ht  [ROWS * D_MODEL];        // rmsnorm out (fp16)
__device__ float  g_xz  [ROWS * 2 * D_INNER];    // in_proj out (x | z) fp32
__device__ float  g_xc  [ROWS * D_INNER];        // conv+silu fp32 (scan)
__device__ __half g_xct [ROWS * D_INNER];        // conv+silu fp16 (x_proj A)
__device__ float  g_xpart[XP_SPLITS * ROWS * XDBL_COLS]; // x_proj split-K partials
__device__ float  g_opart[OP_SPLITS * ROWS * D_MODEL];   // out_proj split-K partials
__device__ float  g_xdbl [ROWS * XDBL_COLS];     // x_proj out fp32 (scan B,C)
__device__ __half g_xdblt[ROWS * XDBL_COLS];     // x_proj out fp16 (dt A)
__device__ float  g_dt  [ROWS * D_INNER];        // softplus(dt) fp32
__device__ __half g_yt  [ROWS * D_INNER];        // scan out fp16 (out_proj A)
__device__ __half g_wi  [2 * D_INNER * D_MODEL]; // fp16 weights
__device__ __half g_wo  [D_MODEL * D_INNER];
__device__ __half g_wx  [XDBL_COLS * D_INNER];
__device__ __half g_wd  [D_INNER * DT_RANK];

// ---------------------------------------------------------------------------
// Helpers
// ---------------------------------------------------------------------------
__device__ __forceinline__ float softplusf(float v)
{
    return v > 20.f ? v : log1pf(__expf(v));
}

__device__ __forceinline__ void mma_f16(float c[4], const uint32_t a[4],
                                        const uint32_t b0, const uint32_t b1)
{
    asm volatile(
        "mma.sync.aligned.m16n8k16.row.col.f32.f16.f16.f32 "
        "{%0,%1,%2,%3}, {%4,%5,%6,%7}, {%8,%9}, {%0,%1,%2,%3};"
        : "+f"(c[0]), "+f"(c[1]), "+f"(c[2]), "+f"(c[3])
        : "r"(a[0]), "r"(a[1]), "r"(a[2]), "r"(a[3]), "r"(b0), "r"(b1));
}

#define LDSM_X4(r0, r1, r2, r3, addr) \
    asm volatile("ldmatrix.sync.aligned.m8n8.x4.shared.b16 {%0,%1,%2,%3}, [%4];" \
                 : "=r"(r0), "=r"(r1), "=r"(r2), "=r"(r3) : "r"(addr))

// ---------------------------------------------------------------------------
// Weight pre-conversion (fp32 -> fp16), x4 vectorized
// ---------------------------------------------------------------------------
#define NWI (2 * D_INNER * D_MODEL)
#define NWO (D_MODEL * D_INNER)
#define NWX (XDBL_COLS * D_INNER)
#define NWD (D_INNER * DT_RANK)
#define NW_TOTAL (NWI + NWO + NWX + NWD)

__device__ __forceinline__ void cvt4(const float* src, __half* dst, int i)
{
    float4 v = *(const float4*)(src + i);
    __half2 h0 = __floats2half2_rn(v.x, v.y);
    __half2 h1 = __floats2half2_rn(v.z, v.w);
    uint2 o;
    o.x = *(unsigned*)&h0;
    o.y = *(unsigned*)&h1;
    *(uint2*)(dst + i) = o;
}

__global__ __launch_bounds__(256)
void cvt_weights_kernel(const float* __restrict__ wi, const float* __restrict__ wo,
                        const float* __restrict__ wx, const float* __restrict__ wd)
{
    int i = (blockIdx.x * 256 + threadIdx.x) * 4;
    if (i < NWI)                       cvt4(wi, g_wi, i);
    else if (i < NWI + NWO)            cvt4(wo, g_wo, i - NWI);
    else if (i < NWI + NWO + NWX)      cvt4(wx, g_wx, i - NWI - NWO);
    else if (i < NW_TOTAL)             cvt4(wd, g_wd, i - NWI - NWO - NWX);
}

// ---------------------------------------------------------------------------
// RMSNorm -> fp16, and store raw input to output residual half
// ---------------------------------------------------------------------------
__global__ __launch_bounds__(256)
void rmsnorm_kernel(const float* __restrict__ x, const float* __restrict__ w,
                    __half* __restrict__ out, float* __restrict__ resid)
{
    int r = blockIdx.x;
    int t = threadIdx.x;
    const float4* xr = (const float4*)(x + (size_t)r * D_MODEL);
    float4 v = xr[t];
    float s = v.x * v.x + v.y * v.y + v.z * v.z + v.w * v.w;
    #pragma unroll
    for (int o = 16; o; o >>= 1) s += __shfl_xor_sync(0xffffffffu, s, o);

    __shared__ float ws[8];
    __shared__ float s_inv;
    if ((t & 31) == 0) ws[t >> 5] = s;
    __syncthreads();
    if (t == 0) {
        float tot = 0.f;
        #pragma unroll
        for (int i = 0; i < 8; i++) tot += ws[i];
        float rms = sqrtf(tot) * (1.0f / 32.0f);
        s_inv = 1.0f / (rms + EPS);
    }
    __syncthreads();
    float inv = s_inv;
    float4 wv = ((const float4*)w)[t];
    __half2 h0 = __floats2half2_rn(v.x * inv * wv.x, v.y * inv * wv.y);
    __half2 h1 = __floats2half2_rn(v.z * inv * wv.z, v.w * inv * wv.w);
    uint2 o;
    o.x = *(unsigned*)&h0;
    o.y = *(unsigned*)&h1;
    ((uint2*)(out + (size_t)r * D_MODEL))[t] = o;
    ((float4*)(resid + (size_t)r * D_MODEL))[t] = v;
}

// ---------------------------------------------------------------------------
// FP16 HMMA GEMM:  C[m][n] = sum_k A[m][k] * B[n][k]   (fp32 accumulate)
// Block tile 128x64, BK=64, 3-stage cp.async, ONE __syncthreads per ktile.
// Xor-swizzled 128B smem rows. 8 warps = 4(M) x 2(N), 3 CTAs/SM.
// ---------------------------------------------------------------------------
#define BK        64
#define STG       3
#define RB        128
#define A_BYTES   (128 * RB)
#define B_BYTES   (64 * RB)
#define STAGE_B   (A_BYTES + B_BYTES)
#define GEMM_SMEM (STG * STAGE_B)

template<int EPI>
__global__ __launch_bounds__(256, 3)
void gemm_h(const __half* __restrict__ A, int lda,
            const __half* __restrict__ B, int ldb,
            float* __restrict__ C, int ldc,
            __half* __restrict__ Caux,
            int N, int k_len, long long split_cstride,
            const float* __restrict__ bias)
{
    extern __shared__ unsigned char smem_raw[];
    const uint32_t smem = (uint32_t)__cvta_generic_to_shared(smem_raw);

    const int tid  = threadIdx.x;
    const int wid  = tid >> 5;
    const int lane = tid & 31;
    const int wm   = (wid & 3) * 32;
    const int wn   = (wid >> 2) * 32;

    const int bm = blockIdx.y * 128;
    const int bn = blockIdx.x * 64;
    const int k0base = blockIdx.z * k_len;
    C += (size_t)blockIdx.z * split_cstride;
    const int ktiles = k_len / BK;

    auto load_stage = [&](int stage, int kt) {
        const int k0 = k0base + kt * BK;
        const uint32_t sa = smem + stage * STAGE_B;
        const uint32_t sb = sa + A_BYTES;
        #pragma unroll
        for (int i = 0; i < 4; i++) {
            int lin = i * 256 + tid;
            int c   = lin & 7;
            int row = lin >> 3;
            uint32_t dst = sa + row * RB + ((c ^ (row & 7)) << 4);
            const __half* src = A + (size_t)(bm + row) * lda + k0 + c * 8;
            asm volatile("cp.async.cg.shared.global [%0], [%1], 16;"
                         :: "r"(dst), "l"(src));
        }
        #pragma unroll
        for (int i = 0; i < 2; i++) {
            int lin = i * 256 + tid;
            int c   = lin & 7;
            int row = lin >> 3;
            int gn  = bn + row;
            uint32_t dst = sb + row * RB + ((c ^ (row & 7)) << 4);
            const __half* src = B + (size_t)(gn < N ? gn : 0) * ldb + k0 + c * 8;
            int ok = (gn < N) ? 16 : 0;
            asm volatile("cp.async.cg.shared.global [%0], [%1], 16, %2;"
                         :: "r"(dst), "l"(src), "r"(ok));
        }
    };

    float acc[2][4][4];
    #pragma unroll
    for (int i = 0; i < 2; i++)
        #pragma unroll
        for (int j = 0; j < 4; j++)
            #pragma unroll
            for (int q = 0; q < 4; q++) acc[i][j][q] = 0.f;

    #pragma unroll
    for (int s = 0; s < STG - 1; s++) {
        if (s < ktiles) load_stage(s, s);
        asm volatile("cp.async.commit_group;");
    }

    const int a_row = ((lane >> 3) & 1) * 8 + (lane & 7);
    const int a_kh  = lane >> 4;
    const int b_row = (lane >> 4) * 8 + (lane & 7);
    const int b_kh  = (lane >> 3) & 1;
    const int lxor  = lane & 7;

    for (int kt = 0; kt < ktiles; kt++) {
        asm volatile("cp.async.wait_group %0;" :: "n"(STG - 2));
        __syncthreads();

        if (kt + STG - 1 < ktiles) load_stage((kt + STG - 1) % STG, kt + STG - 1);
        asm volatile("cp.async.commit_group;");

        const uint32_t Ab = smem + (kt % STG) * STAGE_B;
        const uint32_t Bb = Ab + A_BYTES;

        #pragma unroll
        for (int ks = 0; ks < 4; ks++) {
            const uint32_t ca = (uint32_t)((((ks << 1) | a_kh) ^ lxor) << 4);
            const uint32_t cb = (uint32_t)((((ks << 1) | b_kh) ^ lxor) << 4);
            uint32_t a[2][4], b[4][2];
            #pragma unroll
            for (int mt = 0; mt < 2; mt++) {
                uint32_t ad = Ab + (wm + mt * 16 + a_row) * RB + ca;
                LDSM_X4(a[mt][0], a[mt][1], a[mt][2], a[mt][3], ad);
            }
            #pragma unroll
            for (int np = 0; np < 2; np++) {
                uint32_t bd = Bb + (wn + np * 16 + b_row) * RB + cb;
                LDSM_X4(b[2 * np][0], b[2 * np][1], b[2 * np + 1][0], b[2 * np + 1][1], bd);
            }
            #pragma unroll
            for (int mt = 0; mt < 2; mt++)
                #pragma unroll
                for (int nt = 0; nt < 4; nt++)
                    mma_f16(acc[mt][nt], a[mt], b[nt][0], b[nt][1]);
        }
    }

    const int g4 = lane >> 2;
    const int t2 = (lane & 3) * 2;
    #pragma unroll
    for (int mt = 0; mt < 2; mt++) {
        int gm = bm + wm + mt * 16 + g4;
        #pragma unroll
        for (int nt = 0; nt < 4; nt++) {
            int gn = bn + wn + nt * 8 + t2;
            if (gn < N) {
                float2 v0 = make_float2(acc[mt][nt][0], acc[mt][nt][1]);
                float2 v1 = make_float2(acc[mt][nt][2], acc[mt][nt][3]);
                if (EPI == 1) {
                    float b0 = bias[gn], b1 = bias[gn + 1];
                    v0.x = softplusf(v0.x + b0);
                    v0.y = softplusf(v0.y + b1);
                    v1.x = softplusf(v1.x + b0);
                    v1.y = softplusf(v1.y + b1);
                }
                *(float2*)(C + (size_t)gm * ldc + gn)       = v0;
                *(float2*)(C + (size_t)(gm + 8) * ldc + gn) = v1;
                if (EPI == 2) {
                    __half2 h0 = __floats2half2_rn(v0.x, v0.y);
                    __half2 h1 = __floats2half2_rn(v1.x, v1.y);
                    *(__half2*)(Caux + (size_t)gm * ldc + gn)       = h0;
                    *(__half2*)(Caux + (size_t)(gm + 8) * ldc + gn) = h1;
                }
            }
        }
    }
}

// ---------------------------------------------------------------------------
// x_proj split-K reduce: sum 8 partials -> fp32 + fp16
// ---------------------------------------------------------------------------
__global__ __launch_bounds__(256)
void xp_reduce_kernel()
{
    int i = blockIdx.x * 256 + threadIdx.x;
    if (i >= ROWS * XDBL_COLS) return;
    float s = 0.f;
    #pragma unroll
    for (int p = 0; p < XP_SPLITS; p++)
        s += g_xpart[(size_t)p * ROWS * XDBL_COLS + i];
    g_xdbl[i]  = s;
    g_xdblt[i] = __float2half_rn(s);
}

// ---------------------------------------------------------------------------
// out_proj split-K reduce: out = part0 + part1 (vectorized float4)
// ---------------------------------------------------------------------------
__global__ __launch_bounds__(256)
void op_reduce_kernel(float* __restrict__ out)
{
    int i = (blockIdx.x * 256 + threadIdx.x) * 4;
    if (i >= ROWS * D_MODEL) return;
    float4 a = *(const float4*)(g_opart + i);
    float4 b = *(const float4*)(g_opart + (size_t)ROWS * D_MODEL + i);
    float4 r;
    r.x = a.x + b.x; r.y = a.y + b.y; r.z = a.z + b.z; r.w = a.w + b.w;
    *(float4*)(out + i) = r;
}

// ---------------------------------------------------------------------------
// Depthwise causal conv + bias + SiLU, 4 timesteps per thread
// ---------------------------------------------------------------------------
__global__ __launch_bounds__(256)
void conv_silu_kernel(const float* __restrict__ xz,
                      const float* __restrict__ cw,
                      const float* __restrict__ cb,
                      float* __restrict__ xc,
                      __half* __restrict__ xct)
{
    int idx = blockIdx.x * blockDim.x + threadIdx.x;
    if (idx >= (ROWS / 4) * D_INNER) return;
    int d  = idx & (D_INNER - 1);
    int r4 = idx >> 11;
    int l0 = (r4 & (SEQLEN / 4 - 1)) * 4;
    int b  = r4 >> 8;

    const float* x_b = xz + (size_t)b * SEQLEN * (2 * D_INNER) + d;
    float w0 = cw[d * D_CONV + 0], w1 = cw[d * D_CONV + 1];
    float w2 = cw[d * D_CONV + 2], w3 = cw[d * D_CONV + 3];
    float bias = cb[d];

    float xm3 = (l0 >= 3) ? x_b[(size_t)(l0 - 3) * (2 * D_INNER)] : 0.f;
    float xm2 = (l0 >= 2) ? x_b[(size_t)(l0 - 2) * (2 * D_INNER)] : 0.f;
    float xm1 = (l0 >= 1) ? x_b[(size_t)(l0 - 1) * (2 * D_INNER)] : 0.f;
    float x0  = x_b[(size_t)(l0 + 0) * (2 * D_INNER)];
    float x1  = x_b[(size_t)(l0 + 1) * (2 * D_INNER)];
    float x2  = x_b[(size_t)(l0 + 2) * (2 * D_INNER)];
    float x3  = x_b[(size_t)(l0 + 3) * (2 * D_INNER)];

    float o[4];
    o[0] = bias + xm3 * w0 + xm2 * w1 + xm1 * w2 + x0 * w3;
    o[1] = bias + xm2 * w0 + xm1 * w1 + x0  * w2 + x1 * w3;
    o[2] = bias + xm1 * w0 + x0  * w1 + x1  * w2 + x2 * w3;
    o[3] = bias + x0  * w0 + x1  * w1 + x2  * w2 + x3 * w3;

    size_t base = (size_t)(b * SEQLEN + l0) * D_INNER + d;
    #pragma unroll
    for (int i = 0; i < 4; i++) {
        float v = o[i] / (1.0f + __expf(-o[i]));
        xc [base + (size_t)i * D_INNER] = v;
        xct[base + (size_t)i * D_INNER] = __float2half_rn(v);
    }
}

// ---------------------------------------------------------------------------
// Selective scan, smem-chunked, smem-staged state reduction.
// Block = 256 threads = 16 channels x 16 states. 256 blocks.
// Compute loop writes h*C to s_p; end-of-chunk parallel reduce applies
// D*xc and SiLU gate. No per-step shuffle chain.
// ---------------------------------------------------------------------------
#define SCH 64
#define NCH (SEQLEN / SCH)

__global__ __launch_bounds__(256)
void scan_kernel(const float* __restrict__ xdbl,
                 const float* __restrict__ dt,
                 const float* __restrict__ xc,
                 const float* __restrict__ xz,
                 const float* __restrict__ A_log,
                 const float* __restrict__ Dw,
                 __half* __restrict__ y)
{
    __shared__ float s_dt[2][SCH][16];
    __shared__ float s_xc[2][SCH][16];
    __shared__ float s_z [2][SCH][16];
    __shared__ float s_B [2][SCH][16];
    __shared__ float s_C [2][SCH][16];
    __shared__ float s_p [SCH][16][17];     // padded: stride 17 kills conflicts

    const int tid = threadIdx.x;
    const int n   = tid & 15;
    const int dl  = tid >> 4;
    const int b   = blockIdx.x >> 7;
    const int d0  = (blockIdx.x & 127) * 16;
    const int d   = d0 + dl;

    const float A = -__expf(A_log[d * D_STATE + n]);

    // reduce-phase mapping
    const int rdl = tid & 15;               // channel for reduce
    const int rl0 = tid >> 4;               // base l (0..15), +16*i
    const float rDd = Dw[d0 + rdl];

    const int lr = tid >> 2;
    const int lc = tid & 3;

    const float* dt_g = dt   + (size_t)b * SEQLEN * D_INNER + d0 + lc * 4;
    const float* xc_g = xc   + (size_t)b * SEQLEN * D_INNER + d0 + lc * 4;
    const float* z_g  = xz   + (size_t)b * SEQLEN * (2 * D_INNER) + D_INNER + d0 + lc * 4;
    const float* B_g  = xdbl + (size_t)b * SEQLEN * XDBL_COLS + DT_RANK + lc * 4;
    const float* C_g  = B_g + D_STATE;

    auto load_chunk = [&](int ch, int buf) {
        int l = ch * SCH + lr;
        uint32_t ddt = (uint32_t)__cvta_generic_to_shared(&s_dt[buf][lr][lc * 4]);
        uint32_t dxc = (uint32_t)__cvta_generic_to_shared(&s_xc[buf][lr][lc * 4]);
        uint32_t dz  = (uint32_t)__cvta_generic_to_shared(&s_z [buf][lr][lc * 4]);
        uint32_t dB  = (uint32_t)__cvta_generic_to_shared(&s_B [buf][lr][lc * 4]);
        uint32_t dC  = (uint32_t)__cvta_generic_to_shared(&s_C [buf][lr][lc * 4]);
        asm volatile("cp.async.cg.shared.global [%0], [%1], 16;"
                     :: "r"(ddt), "l"(dt_g + (size_t)l * D_INNER));
        asm volatile("cp.async.cg.shared.global [%0], [%1], 16;"
                     :: "r"(dxc), "l"(xc_g + (size_t)l * D_INNER));
        asm volatile("cp.async.cg.shared.global [%0], [%1], 16;"
                     :: "r"(dz),  "l"(z_g + (size_t)l * (2 * D_INNER)));
        asm volatile("cp.async.cg.shared.global [%0], [%1], 16;"
                     :: "r"(dB),  "l"(B_g + (size_t)l * XDBL_COLS));
        asm volatile("cp.async.cg.shared.global [%0], [%1], 16;"
                     :: "r"(dC),  "l"(C_g + (size_t)l * XDBL_COLS));
    };

    __half* y_b = y + (size_t)b * SEQLEN * D_INNER + d0 + rdl;

    load_chunk(0, 0);
    asm volatile("cp.async.commit_group;");

    float h = 0.f;
    for (int ch = 0; ch < NCH; ch++) {
        const int buf = ch & 1;
        if (ch + 1 < NCH) load_chunk(ch + 1, buf ^ 1);
        asm volatile("cp.async.commit_group;");
        if (ch + 1 < NCH) asm volatile("cp.async.wait_group 1;");
        else              asm volatile("cp.async.wait_group 0;");
        __syncthreads();

        #pragma unroll 4
        for (int l = 0; l < SCH; l++) {
            float dtv = s_dt[buf][l][dl];
            float xcv = s_xc[buf][l][dl];
            float Bv  = s_B [buf][l][n];
            float Cv  = s_C [buf][l][n];

            float dA = __expf(dtv * A);
            h = fmaf(dA, h, dtv * xcv * Bv);
            s_p[l][dl][n] = h * Cv;
        }
        __syncthreads();

        // parallel reduce + gate: thread (rl0, rdl) handles l = rl0 + 16*i
        #pragma unroll
        for (int i = 0; i < 4; i++) {
            int l = rl0 + 16 * i;
            const float* pr = s_p[l][rdl];
            float s = 0.f;
            #pragma unroll
            for (int q = 0; q < 16; q++) s += pr[q];
            float xcv = s_xc[buf][l][rdl];
            float zv  = s_z [buf][l][rdl];
            float sil = zv / (1.0f + __expf(-zv));
            y_b[(size_t)(ch * SCH + l) * D_INNER] =
                __float2half_rn((s + rDd * xcv) * sil);
        }
        __syncthreads();
    }
}

// ---------------------------------------------------------------------------
// Launch
// ---------------------------------------------------------------------------
extern "C" void kernel_launch(void* const* d_in, const int* in_sizes, int n_in,
                              void* d_out, int out_size)
{
    const float* hidden   = (const float*)d_in[0];
    const float* norm_w   = (const float*)d_in[1];
    const float* in_proj  = (const float*)d_in[2];
    const float* conv_w   = (const float*)d_in[3];
    const float* conv_b   = (const float*)d_in[4];
    const float* x_proj   = (const float*)d_in[5];
    const float* dt_proj  = (const float*)d_in[6];
    const float* dt_b     = (const float*)d_in[7];
    const float* A_log    = (const float*)d_in[8];
    const float* Dw       = (const float*)d_in[9];
    const float* out_proj = (const float*)d_in[10];

    float* out = (float*)d_out;
    size_t half = (size_t)out_size / 2;

    __half *ht, *xct, *xdblt, *yt, *wi, *wo, *wx, *wd;
    float *xz, *xc, *xpart, *opart, *xdbl, *dt;
    cudaGetSymbolAddress((void**)&ht,    g_ht);
    cudaGetSymbolAddress((void**)&xz,    g_xz);
    cudaGetSymbolAddress((void**)&xc,    g_xc);
    cudaGetSymbolAddress((void**)&xct,   g_xct);
    cudaGetSymbolAddress((void**)&xpart, g_xpart);
    cudaGetSymbolAddress((void**)&opart, g_opart);
    cudaGetSymbolAddress((void**)&xdbl,  g_xdbl);
    cudaGetSymbolAddress((void**)&xdblt, g_xdblt);
    cudaGetSymbolAddress((void**)&dt,    g_dt);
    cudaGetSymbolAddress((void**)&yt,    g_yt);
    cudaGetSymbolAddress((void**)&wi,    g_wi);
    cudaGetSymbolAddress((void**)&wo,    g_wo);
    cudaGetSymbolAddress((void**)&wx,    g_wx);
    cudaGetSymbolAddress((void**)&wd,    g_wd);

    cudaFuncSetAttribute(gemm_h<0>, cudaFuncAttributeMaxDynamicSharedMemorySize, GEMM_SMEM);
    cudaFuncSetAttribute(gemm_h<1>, cudaFuncAttributeMaxDynamicSharedMemorySize, GEMM_SMEM);
    cudaFuncSetAttribute(gemm_h<2>, cudaFuncAttributeMaxDynamicSharedMemorySize, GEMM_SMEM);

    // 0. weight conversion (fp16)
    cvt_weights_kernel<<<(NW_TOTAL / 4 + 255) / 256, 256>>>(in_proj, out_proj, x_proj, dt_proj);

    // 1. RMSNorm -> fp16 + residual passthrough
    rmsnorm_kernel<<<ROWS, 256>>>(hidden, norm_w, ht, out + half);

    // 2. in_proj: (2048 x 1024) @ (4096 x 1024)^T -> xz
    gemm_h<0><<<dim3(2 * D_INNER / 64, ROWS / 128, 1), 256, GEMM_SMEM>>>(
        ht, D_MODEL, wi, D_MODEL, xz, 2 * D_INNER, nullptr,
        2 * D_INNER, D_MODEL, 0, nullptr);

    // 3. conv + silu (4 timesteps/thread) -> xc fp32 + xct fp16
    conv_silu_kernel<<<(ROWS / 4) * D_INNER / 256, 256>>>(xz, conv_w, conv_b, xc, xct);

    // 4. x_proj split-K: (2048 x 2048) @ (96 x 2048)^T -> 8 partials
    gemm_h<0><<<dim3(2, ROWS / 128, XP_SPLITS), 256, GEMM_SMEM>>>(
        xct, D_INNER, wx, D_INNER, xpart, XDBL_COLS, nullptr,
        XDBL_COLS, XP_KSPL, (long long)ROWS * XDBL_COLS, nullptr);

    // 4b. reduce -> xdbl fp32 + xdblt fp16
    xp_reduce_kernel<<<(ROWS * XDBL_COLS + 255) / 256, 256>>>();

    // 5. dt_proj + softplus: (2048 x 96[:64]) @ (2048 x 64)^T -> dt fp32
    gemm_h<1><<<dim3(D_INNER / 64, ROWS / 128, 1), 256, GEMM_SMEM>>>(
        xdblt, XDBL_COLS, wd, DT_RANK, dt, D_INNER, nullptr,
        D_INNER, DT_RANK, 0, dt_b);

    // 6. selective scan + gate -> yt fp16
    scan_kernel<<<BATCH * D_INNER / 16, 256>>>(
        xdbl, dt, xc, xz, A_log, Dw, yt);

    // 7. out_proj split-K=2: (2048 x 2048) @ (1024 x 2048)^T -> 2 partials
    gemm_h<0><<<dim3(D_MODEL / 64, ROWS / 128, OP_SPLITS), 256, GEMM_SMEM>>>(
        yt, D_INNER, wo, D_INNER, opart, D_MODEL, nullptr,
        D_MODEL, OP_KSPL, (long long)ROWS * D_MODEL, nullptr);

    // 7b. reduce partials -> out
    op_reduce_kernel<<<(ROWS * D_MODEL / 4 + 255) / 256, 256>>>(out);
}

// round 13
// speedup vs baseline: 14.1100x; 1.0176x over previous
#include <cuda_runtime.h>
#include <cuda_fp16.h>
#include <math.h>
#include <stdint.h>

// ---------------------------------------------------------------------------
// Problem constants
// ---------------------------------------------------------------------------
#define D_MODEL   1024
#define D_STATE   16
#define D_CONV    4
#define D_INNER   2048
#define DT_RANK   64
#define BATCH     2
#define SEQLEN    1024
#define ROWS      (BATCH * SEQLEN)          // 2048
#define XDBL_COLS (DT_RANK + 2 * D_STATE)   // 96
#define EPS       1e-5f

#define XP_SPLITS 8
#define XP_KSPL   (D_INNER / XP_SPLITS)     // 256
#define OP_SPLITS 4
#define OP_KSPL   (D_INNER / OP_SPLITS)     // 512

// ---------------------------------------------------------------------------
// Scratch (__device__ globals; no cudaMalloc allowed)
// ---------------------------------------------------------------------------
__device__ __half g_ht  [ROWS * D_MODEL];        // rmsnorm out (fp16)
__device__ float  g_xz  [ROWS * 2 * D_INNER];    // in_proj out (x | z) fp32
__device__ float  g_xc  [ROWS * D_INNER];        // conv+silu fp32 (scan)
__device__ __half g_xct [ROWS * D_INNER];        // conv+silu fp16 (x_proj A)
__device__ float  g_xpart[XP_SPLITS * ROWS * XDBL_COLS]; // x_proj split-K partials
__device__ float  g_opart[OP_SPLITS * ROWS * D_MODEL];   // out_proj split-K partials
__device__ float  g_xdbl [ROWS * XDBL_COLS];     // x_proj out fp32 (scan B,C)
__device__ __half g_xdblt[ROWS * XDBL_COLS];     // x_proj out fp16 (dt A)
__device__ float  g_dt  [ROWS * D_INNER];        // softplus(dt) fp32
__device__ __half g_yt  [ROWS * D_INNER];        // scan out fp16 (out_proj A)
__device__ __half g_wi  [2 * D_INNER * D_MODEL]; // fp16 weights
__device__ __half g_wo  [D_MODEL * D_INNER];
__device__ __half g_wx  [XDBL_COLS * D_INNER];
__device__ __half g_wd  [D_INNER * DT_RANK];

// ---------------------------------------------------------------------------
// Helpers
// ---------------------------------------------------------------------------
__device__ __forceinline__ float softplusf(float v)
{
    return v > 20.f ? v : log1pf(__expf(v));
}

__device__ __forceinline__ void mma_f16(float c[4], const uint32_t a[4],
                                        const uint32_t b0, const uint32_t b1)
{
    asm volatile(
        "mma.sync.aligned.m16n8k16.row.col.f32.f16.f16.f32 "
        "{%0,%1,%2,%3}, {%4,%5,%6,%7}, {%8,%9}, {%0,%1,%2,%3};"
        : "+f"(c[0]), "+f"(c[1]), "+f"(c[2]), "+f"(c[3])
        : "r"(a[0]), "r"(a[1]), "r"(a[2]), "r"(a[3]), "r"(b0), "r"(b1));
}

#define LDSM_X4(r0, r1, r2, r3, addr) \
    asm volatile("ldmatrix.sync.aligned.m8n8.x4.shared.b16 {%0,%1,%2,%3}, [%4];" \
                 : "=r"(r0), "=r"(r1), "=r"(r2), "=r"(r3) : "r"(addr))

// ---------------------------------------------------------------------------
// Weight conversion sizes
// ---------------------------------------------------------------------------
#define NWI (2 * D_INNER * D_MODEL)
#define NWO (D_MODEL * D_INNER)
#define NWX (XDBL_COLS * D_INNER)
#define NWD (D_INNER * DT_RANK)
#define NW_TOTAL (NWI + NWO + NWX + NWD)
#define NW_BLOCKS ((NW_TOTAL / 4 + 255) / 256)

__device__ __forceinline__ void cvt4(const float* src, __half* dst, int i)
{
    float4 v = *(const float4*)(src + i);
    __half2 h0 = __floats2half2_rn(v.x, v.y);
    __half2 h1 = __floats2half2_rn(v.z, v.w);
    uint2 o;
    o.x = *(unsigned*)&h0;
    o.y = *(unsigned*)&h1;
    *(uint2*)(dst + i) = o;
}

// ---------------------------------------------------------------------------
// Fused: RMSNorm (blocks 0..ROWS-1) + weight cvt (blocks ROWS..)
// ---------------------------------------------------------------------------
__global__ __launch_bounds__(256)
void prep_kernel(const float* __restrict__ x, const float* __restrict__ w,
                 __half* __restrict__ out, float* __restrict__ resid,
                 const float* __restrict__ wi, const float* __restrict__ wo,
                 const float* __restrict__ wx, const float* __restrict__ wd)
{
    if (blockIdx.x >= ROWS) {
        int i = ((blockIdx.x - ROWS) * 256 + threadIdx.x) * 4;
        if (i < NWI)                       cvt4(wi, g_wi, i);
        else if (i < NWI + NWO)            cvt4(wo, g_wo, i - NWI);
        else if (i < NWI + NWO + NWX)      cvt4(wx, g_wx, i - NWI - NWO);
        else if (i < NW_TOTAL)             cvt4(wd, g_wd, i - NWI - NWO - NWX);
        return;
    }

    int r = blockIdx.x;
    int t = threadIdx.x;
    const float4* xr = (const float4*)(x + (size_t)r * D_MODEL);
    float4 v = xr[t];
    float s = v.x * v.x + v.y * v.y + v.z * v.z + v.w * v.w;
    #pragma unroll
    for (int o = 16; o; o >>= 1) s += __shfl_xor_sync(0xffffffffu, s, o);

    __shared__ float ws[8];
    __shared__ float s_inv;
    if ((t & 31) == 0) ws[t >> 5] = s;
    __syncthreads();
    if (t == 0) {
        float tot = 0.f;
        #pragma unroll
        for (int i = 0; i < 8; i++) tot += ws[i];
        float rms = sqrtf(tot) * (1.0f / 32.0f);
        s_inv = 1.0f / (rms + EPS);
    }
    __syncthreads();
    float inv = s_inv;
    float4 wv = ((const float4*)w)[t];
    __half2 h0 = __floats2half2_rn(v.x * inv * wv.x, v.y * inv * wv.y);
    __half2 h1 = __floats2half2_rn(v.z * inv * wv.z, v.w * inv * wv.w);
    uint2 o;
    o.x = *(unsigned*)&h0;
    o.y = *(unsigned*)&h1;
    ((uint2*)(out + (size_t)r * D_MODEL))[t] = o;
    ((float4*)(resid + (size_t)r * D_MODEL))[t] = v;
}

// ---------------------------------------------------------------------------
// FP16 HMMA GEMM (v1): CTA 128x64, BK=64, warp 32x32, 3 CTAs/SM.
// ---------------------------------------------------------------------------
#define BK        64
#define STG       3
#define RB        128
#define A_BYTES   (128 * RB)
#define B_BYTES   (64 * RB)
#define STAGE_B   (A_BYTES + B_BYTES)
#define GEMM_SMEM (STG * STAGE_B)

template<int EPI>
__global__ __launch_bounds__(256, 3)
void gemm_h(const __half* __restrict__ A, int lda,
            const __half* __restrict__ B, int ldb,
            float* __restrict__ C, int ldc,
            __half* __restrict__ Caux,
            int N, int k_len, long long split_cstride,
            const float* __restrict__ bias)
{
    extern __shared__ unsigned char smem_raw[];
    const uint32_t smem = (uint32_t)__cvta_generic_to_shared(smem_raw);

    const int tid  = threadIdx.x;
    const int wid  = tid >> 5;
    const int lane = tid & 31;
    const int wm   = (wid & 3) * 32;
    const int wn   = (wid >> 2) * 32;

    const int bm = blockIdx.y * 128;
    const int bn = blockIdx.x * 64;
    const int k0base = blockIdx.z * k_len;
    C += (size_t)blockIdx.z * split_cstride;
    const int ktiles = k_len / BK;

    auto load_stage = [&](int stage, int kt) {
        const int k0 = k0base + kt * BK;
        const uint32_t sa = smem + stage * STAGE_B;
        const uint32_t sb = sa + A_BYTES;
        #pragma unroll
        for (int i = 0; i < 4; i++) {
            int lin = i * 256 + tid;
            int c   = lin & 7;
            int row = lin >> 3;
            uint32_t dst = sa + row * RB + ((c ^ (row & 7)) << 4);
            const __half* src = A + (size_t)(bm + row) * lda + k0 + c * 8;
            asm volatile("cp.async.cg.shared.global [%0], [%1], 16;"
                         :: "r"(dst), "l"(src));
        }
        #pragma unroll
        for (int i = 0; i < 2; i++) {
            int lin = i * 256 + tid;
            int c   = lin & 7;
            int row = lin >> 3;
            int gn  = bn + row;
            uint32_t dst = sb + row * RB + ((c ^ (row & 7)) << 4);
            const __half* src = B + (size_t)(gn < N ? gn : 0) * ldb + k0 + c * 8;
            int ok = (gn < N) ? 16 : 0;
            asm volatile("cp.async.cg.shared.global [%0], [%1], 16, %2;"
                         :: "r"(dst), "l"(src), "r"(ok));
        }
    };

    float acc[2][4][4];
    #pragma unroll
    for (int i = 0; i < 2; i++)
        #pragma unroll
        for (int j = 0; j < 4; j++)
            #pragma unroll
            for (int q = 0; q < 4; q++) acc[i][j][q] = 0.f;

    #pragma unroll
    for (int s = 0; s < STG - 1; s++) {
        if (s < ktiles) load_stage(s, s);
        asm volatile("cp.async.commit_group;");
    }

    const int a_row = ((lane >> 3) & 1) * 8 + (lane & 7);
    const int a_kh  = lane >> 4;
    const int b_row = (lane >> 4) * 8 + (lane & 7);
    const int b_kh  = (lane >> 3) & 1;
    const int lxor  = lane & 7;

    for (int kt = 0; kt < ktiles; kt++) {
        asm volatile("cp.async.wait_group %0;" :: "n"(STG - 2));
        __syncthreads();

        if (kt + STG - 1 < ktiles) load_stage((kt + STG - 1) % STG, kt + STG - 1);
        asm volatile("cp.async.commit_group;");

        const uint32_t Ab = smem + (kt % STG) * STAGE_B;
        const uint32_t Bb = Ab + A_BYTES;

        #pragma unroll
        for (int ks = 0; ks < 4; ks++) {
            const uint32_t ca = (uint32_t)((((ks << 1) | a_kh) ^ lxor) << 4);
            const uint32_t cb = (uint32_t)((((ks << 1) | b_kh) ^ lxor) << 4);
            uint32_t a[2][4], b[4][2];
            #pragma unroll
            for (int mt = 0; mt < 2; mt++) {
                uint32_t ad = Ab + (wm + mt * 16 + a_row) * RB + ca;
                LDSM_X4(a[mt][0], a[mt][1], a[mt][2], a[mt][3], ad);
            }
            #pragma unroll
            for (int np = 0; np < 2; np++) {
                uint32_t bd = Bb + (wn + np * 16 + b_row) * RB + cb;
                LDSM_X4(b[2 * np][0], b[2 * np][1], b[2 * np + 1][0], b[2 * np + 1][1], bd);
            }
            #pragma unroll
            for (int mt = 0; mt < 2; mt++)
                #pragma unroll
                for (int nt = 0; nt < 4; nt++)
                    mma_f16(acc[mt][nt], a[mt], b[nt][0], b[nt][1]);
        }
    }

    const int g4 = lane >> 2;
    const int t2 = (lane & 3) * 2;
    #pragma unroll
    for (int mt = 0; mt < 2; mt++) {
        int gm = bm + wm + mt * 16 + g4;
        #pragma unroll
        for (int nt = 0; nt < 4; nt++) {
            int gn = bn + wn + nt * 8 + t2;
            if (gn < N) {
                float2 v0 = make_float2(acc[mt][nt][0], acc[mt][nt][1]);
                float2 v1 = make_float2(acc[mt][nt][2], acc[mt][nt][3]);
                if (EPI == 1) {
                    float b0 = bias[gn], b1 = bias[gn + 1];
                    v0.x = softplusf(v0.x + b0);
                    v0.y = softplusf(v0.y + b1);
                    v1.x = softplusf(v1.x + b0);
                    v1.y = softplusf(v1.y + b1);
                }
                *(float2*)(C + (size_t)gm * ldc + gn)       = v0;
                *(float2*)(C + (size_t)(gm + 8) * ldc + gn) = v1;
                if (EPI == 2) {
                    __half2 h0 = __floats2half2_rn(v0.x, v0.y);
                    __half2 h1 = __floats2half2_rn(v1.x, v1.y);
                    *(__half2*)(Caux + (size_t)gm * ldc + gn)       = h0;
                    *(__half2*)(Caux + (size_t)(gm + 8) * ldc + gn) = h1;
                }
            }
        }
    }
}

// ---------------------------------------------------------------------------
// FP16 HMMA GEMM (v2): CTA 128x128, BK=64, 8 warps = 2(M)x4(N), warp 64x32.
// Fewer LDSM per MMA and half the A traffic; 2 CTAs/SM. For large-N GEMMs.
// ---------------------------------------------------------------------------
#define A2_BYTES   (128 * RB)
#define STAGE_B2   (2 * A2_BYTES)            // 32 KB
#define GEMM_SMEM2 (STG * STAGE_B2)          // 96 KB

__global__ __launch_bounds__(256, 2)
void gemm_h2(const __half* __restrict__ A, int lda,
             const __half* __restrict__ B, int ldb,
             float* __restrict__ C, int ldc,
             int N, int K)
{
    extern __shared__ unsigned char smem_raw[];
    const uint32_t smem = (uint32_t)__cvta_generic_to_shared(smem_raw);

    const int tid  = threadIdx.x;
    const int wid  = tid >> 5;
    const int lane = tid & 31;
    const int wm   = (wid & 1) * 64;     // 2 warps along M
    const int wn   = (wid >> 1) * 32;    // 4 warps along N

    const int bm = blockIdx.y * 128;
    const int bn = blockIdx.x * 128;
    const int ktiles = K / BK;

    auto load_stage = [&](int stage, int kt) {
        const int k0 = kt * BK;
        const uint32_t sa = smem + stage * STAGE_B2;
        const uint32_t sb = sa + A2_BYTES;
        #pragma unroll
        for (int i = 0; i < 4; i++) {
            int lin = i * 256 + tid;
            int c   = lin & 7;
            int row = lin >> 3;
            uint32_t dst = sa + row * RB + ((c ^ (row & 7)) << 4);
            const __half* src = A + (size_t)(bm + row) * lda + k0 + c * 8;
            asm volatile("cp.async.cg.shared.global [%0], [%1], 16;"
                         :: "r"(dst), "l"(src));
        }
        #pragma unroll
        for (int i = 0; i < 4; i++) {
            int lin = i * 256 + tid;
            int c   = lin & 7;
            int row = lin >> 3;
            int gn  = bn + row;
            uint32_t dst = sb + row * RB + ((c ^ (row & 7)) << 4);
            const __half* src = B + (size_t)(gn < N ? gn : 0) * ldb + k0 + c * 8;
            int ok = (gn < N) ? 16 : 0;
            asm volatile("cp.async.cg.shared.global [%0], [%1], 16, %2;"
                         :: "r"(dst), "l"(src), "r"(ok));
        }
    };

    float acc[4][4][4];
    #pragma unroll
    for (int i = 0; i < 4; i++)
        #pragma unroll
        for (int j = 0; j < 4; j++)
            #pragma unroll
            for (int q = 0; q < 4; q++) acc[i][j][q] = 0.f;

    #pragma unroll
    for (int s = 0; s < STG - 1; s++) {
        if (s < ktiles) load_stage(s, s);
        asm volatile("cp.async.commit_group;");
    }

    const int a_row = ((lane >> 3) & 1) * 8 + (lane & 7);
    const int a_kh  = lane >> 4;
    const int b_row = (lane >> 4) * 8 + (lane & 7);
    const int b_kh  = (lane >> 3) & 1;
    const int lxor  = lane & 7;

    for (int kt = 0; kt < ktiles; kt++) {
        asm volatile("cp.async.wait_group %0;" :: "n"(STG - 2));
        __syncthreads();

        if (kt + STG - 1 < ktiles) load_stage((kt + STG - 1) % STG, kt + STG - 1);
        asm volatile("cp.async.commit_group;");

        const uint32_t Ab = smem + (kt % STG) * STAGE_B2;
        const uint32_t Bb = Ab + A2_BYTES;

        #pragma unroll
        for (int ks = 0; ks < 4; ks++) {
            const uint32_t ca = (uint32_t)((((ks << 1) | a_kh) ^ lxor) << 4);
            const uint32_t cb = (uint32_t)((((ks << 1) | b_kh) ^ lxor) << 4);
            uint32_t a[4][4], b[4][2];
            #pragma unroll
            for (int mt = 0; mt < 4; mt++) {
                uint32_t ad = Ab + (wm + mt * 16 + a_row) * RB + ca;
                LDSM_X4(a[mt][0], a[mt][1], a[mt][2], a[mt][3], ad);
            }
            #pragma unroll
            for (int np = 0; np < 2; np++) {
                uint32_t bd = Bb + (wn + np * 16 + b_row) * RB + cb;
                LDSM_X4(b[2 * np][0], b[2 * np][1], b[2 * np + 1][0], b[2 * np + 1][1], bd);
            }
            #pragma unroll
            for (int mt = 0; mt < 4; mt++)
                #pragma unroll
                for (int nt = 0; nt < 4; nt++)
                    mma_f16(acc[mt][nt], a[mt], b[nt][0], b[nt][1]);
        }
    }

    const int g4 = lane >> 2;
    const int t2 = (lane & 3) * 2;
    #pragma unroll
    for (int mt = 0; mt < 4; mt++) {
        int gm = bm + wm + mt * 16 + g4;
        #pragma unroll
        for (int nt = 0; nt < 4; nt++) {
            int gn = bn + wn + nt * 8 + t2;
            if (gn < N) {
                *(float2*)(C + (size_t)gm * ldc + gn) =
                    make_float2(acc[mt][nt][0], acc[mt][nt][1]);
                *(float2*)(C + (size_t)(gm + 8) * ldc + gn) =
                    make_float2(acc[mt][nt][2], acc[mt][nt][3]);
            }
        }
    }
}

// ---------------------------------------------------------------------------
// x_proj split-K reduce: sum 8 partials -> fp32 + fp16
// ---------------------------------------------------------------------------
__global__ __launch_bounds__(256)
void xp_reduce_kernel()
{
    int i = blockIdx.x * 256 + threadIdx.x;
    if (i >= ROWS * XDBL_COLS) return;
    float s = 0.f;
    #pragma unroll
    for (int p = 0; p < XP_SPLITS; p++)
        s += g_xpart[(size_t)p * ROWS * XDBL_COLS + i];
    g_xdbl[i]  = s;
    g_xdblt[i] = __float2half_rn(s);
}

// ---------------------------------------------------------------------------
// out_proj split-K reduce: out = sum of 4 partials (vectorized float4)
// ---------------------------------------------------------------------------
__global__ __launch_bounds__(256)
void op_reduce_kernel(float* __restrict__ out)
{
    int i = (blockIdx.x * 256 + threadIdx.x) * 4;
    if (i >= ROWS * D_MODEL) return;
    float4 r = *(const float4*)(g_opart + i);
    #pragma unroll
    for (int p = 1; p < OP_SPLITS; p++) {
        float4 a = *(const float4*)(g_opart + (size_t)p * ROWS * D_MODEL + i);
        r.x += a.x; r.y += a.y; r.z += a.z; r.w += a.w;
    }
    *(float4*)(out + i) = r;
}

// ---------------------------------------------------------------------------
// Depthwise causal conv + bias + SiLU, 4 timesteps per thread
// ---------------------------------------------------------------------------
__global__ __launch_bounds__(256)
void conv_silu_kernel(const float* __restrict__ xz,
                      const float* __restrict__ cw,
                      const float* __restrict__ cb,
                      float* __restrict__ xc,
                      __half* __restrict__ xct)
{
    int idx = blockIdx.x * blockDim.x + threadIdx.x;
    if (idx >= (ROWS / 4) * D_INNER) return;
    int d  = idx & (D_INNER - 1);
    int r4 = idx >> 11;
    int l0 = (r4 & (SEQLEN / 4 - 1)) * 4;
    int b  = r4 >> 8;

    const float* x_b = xz + (size_t)b * SEQLEN * (2 * D_INNER) + d;
    float w0 = cw[d * D_CONV + 0], w1 = cw[d * D_CONV + 1];
    float w2 = cw[d * D_CONV + 2], w3 = cw[d * D_CONV + 3];
    float bias = cb[d];

    float xm3 = (l0 >= 3) ? x_b[(size_t)(l0 - 3) * (2 * D_INNER)] : 0.f;
    float xm2 = (l0 >= 2) ? x_b[(size_t)(l0 - 2) * (2 * D_INNER)] : 0.f;
    float xm1 = (l0 >= 1) ? x_b[(size_t)(l0 - 1) * (2 * D_INNER)] : 0.f;
    float x0  = x_b[(size_t)(l0 + 0) * (2 * D_INNER)];
    float x1  = x_b[(size_t)(l0 + 1) * (2 * D_INNER)];
    float x2  = x_b[(size_t)(l0 + 2) * (2 * D_INNER)];
    float x3  = x_b[(size_t)(l0 + 3) * (2 * D_INNER)];

    float o[4];
    o[0] = bias + xm3 * w0 + xm2 * w1 + xm1 * w2 + x0 * w3;
    o[1] = bias + xm2 * w0 + xm1 * w1 + x0  * w2 + x1 * w3;
    o[2] = bias + xm1 * w0 + x0  * w1 + x1  * w2 + x2 * w3;
    o[3] = bias + x0  * w0 + x1  * w1 + x2  * w2 + x3 * w3;

    size_t base = (size_t)(b * SEQLEN + l0) * D_INNER + d;
    #pragma unroll
    for (int i = 0; i < 4; i++) {
        float v = o[i] / (1.0f + __expf(-o[i]));
        xc [base + (size_t)i * D_INNER] = v;
        xct[base + (size_t)i * D_INNER] = __float2half_rn(v);
    }
}

// ---------------------------------------------------------------------------
// Selective scan, smem-chunked, smem-staged state reduction.
// ---------------------------------------------------------------------------
#define SCH 64
#define NCH (SEQLEN / SCH)

__global__ __launch_bounds__(256)
void scan_kernel(const float* __restrict__ xdbl,
                 const float* __restrict__ dt,
                 const float* __restrict__ xc,
                 const float* __restrict__ xz,
                 const float* __restrict__ A_log,
                 const float* __restrict__ Dw,
                 __half* __restrict__ y)
{
    __shared__ float s_dt[2][SCH][16];
    __shared__ float s_xc[2][SCH][16];
    __shared__ float s_z [2][SCH][16];
    __shared__ float s_B [2][SCH][16];
    __shared__ float s_C [2][SCH][16];
    __shared__ float s_p [SCH][16][17];

    const int tid = threadIdx.x;
    const int n   = tid & 15;
    const int dl  = tid >> 4;
    const int b   = blockIdx.x >> 7;
    const int d0  = (blockIdx.x & 127) * 16;
    const int d   = d0 + dl;

    const float A = -__expf(A_log[d * D_STATE + n]);

    const int rdl = tid & 15;
    const int rl0 = tid >> 4;
    const float rDd = Dw[d0 + rdl];

    const int lr = tid >> 2;
    const int lc = tid & 3;

    const float* dt_g = dt   + (size_t)b * SEQLEN * D_INNER + d0 + lc * 4;
    const float* xc_g = xc   + (size_t)b * SEQLEN * D_INNER + d0 + lc * 4;
    const float* z_g  = xz   + (size_t)b * SEQLEN * (2 * D_INNER) + D_INNER + d0 + lc * 4;
    const float* B_g  = xdbl + (size_t)b * SEQLEN * XDBL_COLS + DT_RANK + lc * 4;
    const float* C_g  = B_g + D_STATE;

    auto load_chunk = [&](int ch, int buf) {
        int l = ch * SCH + lr;
        uint32_t ddt = (uint32_t)__cvta_generic_to_shared(&s_dt[buf][lr][lc * 4]);
        uint32_t dxc = (uint32_t)__cvta_generic_to_shared(&s_xc[buf][lr][lc * 4]);
        uint32_t dz  = (uint32_t)__cvta_generic_to_shared(&s_z [buf][lr][lc * 4]);
        uint32_t dB  = (uint32_t)__cvta_generic_to_shared(&s_B [buf][lr][lc * 4]);
        uint32_t dC  = (uint32_t)__cvta_generic_to_shared(&s_C [buf][lr][lc * 4]);
        asm volatile("cp.async.cg.shared.global [%0], [%1], 16;"
                     :: "r"(ddt), "l"(dt_g + (size_t)l * D_INNER));
        asm volatile("cp.async.cg.shared.global [%0], [%1], 16;"
                     :: "r"(dxc), "l"(xc_g + (size_t)l * D_INNER));
        asm volatile("cp.async.cg.shared.global [%0], [%1], 16;"
                     :: "r"(dz),  "l"(z_g + (size_t)l * (2 * D_INNER)));
        asm volatile("cp.async.cg.shared.global [%0], [%1], 16;"
                     :: "r"(dB),  "l"(B_g + (size_t)l * XDBL_COLS));
        asm volatile("cp.async.cg.shared.global [%0], [%1], 16;"
                     :: "r"(dC),  "l"(C_g + (size_t)l * XDBL_COLS));
    };

    __half* y_b = y + (size_t)b * SEQLEN * D_INNER + d0 + rdl;

    load_chunk(0, 0);
    asm volatile("cp.async.commit_group;");

    float h = 0.f;
    for (int ch = 0; ch < NCH; ch++) {
        const int buf = ch & 1;
        if (ch + 1 < NCH) load_chunk(ch + 1, buf ^ 1);
        asm volatile("cp.async.commit_group;");
        if (ch + 1 < NCH) asm volatile("cp.async.wait_group 1;");
        else              asm volatile("cp.async.wait_group 0;");
        __syncthreads();

        #pragma unroll 4
        for (int l = 0; l < SCH; l++) {
            float dtv = s_dt[buf][l][dl];
            float xcv = s_xc[buf][l][dl];
            float Bv  = s_B [buf][l][n];
            float Cv  = s_C [buf][l][n];

            float dA = __expf(dtv * A);
            h = fmaf(dA, h, dtv * xcv * Bv);
            s_p[l][dl][n] = h * Cv;
        }
        __syncthreads();

        #pragma unroll
        for (int i = 0; i < 4; i++) {
            int l = rl0 + 16 * i;
            const float* pr = s_p[l][rdl];
            float s = 0.f;
            #pragma unroll
            for (int q = 0; q < 16; q++) s += pr[q];
            float xcv = s_xc[buf][l][rdl];
            float zv  = s_z [buf][l][rdl];
            float sil = zv / (1.0f + __expf(-zv));
            y_b[(size_t)(ch * SCH + l) * D_INNER] =
                __float2half_rn((s + rDd * xcv) * sil);
        }
        __syncthreads();
    }
}

// ---------------------------------------------------------------------------
// Launch
// ---------------------------------------------------------------------------
extern "C" void kernel_launch(void* const* d_in, const int* in_sizes, int n_in,
                              void* d_out, int out_size)
{
    const float* hidden   = (const float*)d_in[0];
    const float* norm_w   = (const float*)d_in[1];
    const float* in_proj  = (const float*)d_in[2];
    const float* conv_w   = (const float*)d_in[3];
    const float* conv_b   = (const float*)d_in[4];
    const float* x_proj   = (const float*)d_in[5];
    const float* dt_proj  = (const float*)d_in[6];
    const float* dt_b     = (const float*)d_in[7];
    const float* A_log    = (const float*)d_in[8];
    const float* Dw       = (const float*)d_in[9];
    const float* out_proj = (const float*)d_in[10];

    float* out = (float*)d_out;
    size_t half = (size_t)out_size / 2;

    __half *ht, *xct, *xdblt, *yt, *wi, *wo, *wx, *wd;
    float *xz, *xc, *xpart, *opart, *xdbl, *dt;
    cudaGetSymbolAddress((void**)&ht,    g_ht);
    cudaGetSymbolAddress((void**)&xz,    g_xz);
    cudaGetSymbolAddress((void**)&xc,    g_xc);
    cudaGetSymbolAddress((void**)&xct,   g_xct);
    cudaGetSymbolAddress((void**)&xpart, g_xpart);
    cudaGetSymbolAddress((void**)&opart, g_opart);
    cudaGetSymbolAddress((void**)&xdbl,  g_xdbl);
    cudaGetSymbolAddress((void**)&xdblt, g_xdblt);
    cudaGetSymbolAddress((void**)&dt,    g_dt);
    cudaGetSymbolAddress((void**)&yt,    g_yt);
    cudaGetSymbolAddress((void**)&wi,    g_wi);
    cudaGetSymbolAddress((void**)&wo,    g_wo);
    cudaGetSymbolAddress((void**)&wx,    g_wx);
    cudaGetSymbolAddress((void**)&wd,    g_wd);

    cudaFuncSetAttribute(gemm_h<0>, cudaFuncAttributeMaxDynamicSharedMemorySize, GEMM_SMEM);
    cudaFuncSetAttribute(gemm_h<1>, cudaFuncAttributeMaxDynamicSharedMemorySize, GEMM_SMEM);
    cudaFuncSetAttribute(gemm_h2, cudaFuncAttributeMaxDynamicSharedMemorySize, GEMM_SMEM2);

    // 0+1. fused weight cvt + RMSNorm + residual passthrough
    prep_kernel<<<ROWS + NW_BLOCKS, 256>>>(hidden, norm_w, ht, out + half,
                                           in_proj, out_proj, x_proj, dt_proj);

    // 2. in_proj (gemm v2, 128x128): (2048 x 1024) @ (4096 x 1024)^T -> xz
    gemm_h2<<<dim3(2 * D_INNER / 128, ROWS / 128), 256, GEMM_SMEM2>>>(
        ht, D_MODEL, wi, D_MODEL, xz, 2 * D_INNER,
        2 * D_INNER, D_MODEL);

    // 3. conv + silu (4 timesteps/thread) -> xc fp32 + xct fp16
    conv_silu_kernel<<<(ROWS / 4) * D_INNER / 256, 256>>>(xz, conv_w, conv_b, xc, xct);

    // 4. x_proj split-K: (2048 x 2048) @ (96 x 2048)^T -> 8 partials
    gemm_h<0><<<dim3(2, ROWS / 128, XP_SPLITS), 256, GEMM_SMEM>>>(
        xct, D_INNER, wx, D_INNER, xpart, XDBL_COLS, nullptr,
        XDBL_COLS, XP_KSPL, (long long)ROWS * XDBL_COLS, nullptr);

    // 4b. reduce -> xdbl fp32 + xdblt fp16
    xp_reduce_kernel<<<(ROWS * XDBL_COLS + 255) / 256, 256>>>();

    // 5. dt_proj + softplus: (2048 x 96[:64]) @ (2048 x 64)^T -> dt fp32
    gemm_h<1><<<dim3(D_INNER / 64, ROWS / 128, 1), 256, GEMM_SMEM>>>(
        xdblt, XDBL_COLS, wd, DT_RANK, dt, D_INNER, nullptr,
        D_INNER, DT_RANK, 0, dt_b);

    // 6. selective scan + gate -> yt fp16
    scan_kernel<<<BATCH * D_INNER / 16, 256>>>(
        xdbl, dt, xc, xz, A_log, Dw, yt);

    // 7. out_proj split-K=4: (2048 x 2048) @ (1024 x 2048)^T -> 4 partials
    gemm_h<0><<<dim3(D_MODEL / 64, ROWS / 128, OP_SPLITS), 256, GEMM_SMEM>>>(
        yt, D_INNER, wo, D_INNER, opart, D_MODEL, nullptr,
        D_MODEL, OP_KSPL, (long long)ROWS * D_MODEL, nullptr);

    // 7b. reduce partials -> out
    op_reduce_kernel<<<(ROWS * D_MODEL / 4 + 255) / 256, 256>>>(out);
}

// round 14
// speedup vs baseline: 14.1412x; 1.0022x over previous
#include <cuda_runtime.h>
#include <cuda_fp16.h>
#include <math.h>
#include <stdint.h>

// ---------------------------------------------------------------------------
// Problem constants
// ---------------------------------------------------------------------------
#define D_MODEL   1024
#define D_STATE   16
#define D_CONV    4
#define D_INNER   2048
#define DT_RANK   64
#define BATCH     2
#define SEQLEN    1024
#define ROWS      (BATCH * SEQLEN)          // 2048
#define XDBL_COLS (DT_RANK + 2 * D_STATE)   // 96
#define EPS       1e-5f

#define XP_SPLITS 8
#define XP_KSPL   (D_INNER / XP_SPLITS)     // 256
#define OP_SPLITS 4
#define OP_KSPL   (D_INNER / OP_SPLITS)     // 512

// ---------------------------------------------------------------------------
// Scratch (__device__ globals; no cudaMalloc allowed)
// ---------------------------------------------------------------------------
__device__ __half g_ht  [ROWS * D_MODEL];        // rmsnorm out (fp16)
__device__ float  g_xz  [ROWS * 2 * D_INNER];    // in_proj out (x | z) fp32
__device__ float  g_xc  [ROWS * D_INNER];        // conv+silu fp32 (scan)
__device__ __half g_xct [ROWS * D_INNER];        // conv+silu fp16 (x_proj A)
__device__ float  g_xpart[XP_SPLITS * ROWS * XDBL_COLS]; // x_proj split-K partials
__device__ float  g_opart[OP_SPLITS * ROWS * D_MODEL];   // out_proj split-K partials
__device__ float  g_xdbl [ROWS * XDBL_COLS];     // x_proj out fp32 (scan B,C)
__device__ __half g_xdblt[ROWS * XDBL_COLS];     // x_proj out fp16 (dt A)
__device__ float  g_dt  [ROWS * D_INNER];        // softplus(dt) fp32
__device__ __half g_yt  [ROWS * D_INNER];        // scan out fp16 (out_proj A)
__device__ __half g_wi  [2 * D_INNER * D_MODEL]; // fp16 weights
__device__ __half g_wo  [D_MODEL * D_INNER];
__device__ __half g_wx  [XDBL_COLS * D_INNER];
__device__ __half g_wd  [D_INNER * DT_RANK];

// ---------------------------------------------------------------------------
// Helpers
// ---------------------------------------------------------------------------
__device__ __forceinline__ float softplusf(float v)
{
    return v > 20.f ? v : log1pf(__expf(v));
}

__device__ __forceinline__ void mma_f16(float c[4], const uint32_t a[4],
                                        const uint32_t b0, const uint32_t b1)
{
    asm volatile(
        "mma.sync.aligned.m16n8k16.row.col.f32.f16.f16.f32 "
        "{%0,%1,%2,%3}, {%4,%5,%6,%7}, {%8,%9}, {%0,%1,%2,%3};"
        : "+f"(c[0]), "+f"(c[1]), "+f"(c[2]), "+f"(c[3])
        : "r"(a[0]), "r"(a[1]), "r"(a[2]), "r"(a[3]), "r"(b0), "r"(b1));
}

#define LDSM_X4(r0, r1, r2, r3, addr) \
    asm volatile("ldmatrix.sync.aligned.m8n8.x4.shared.b16 {%0,%1,%2,%3}, [%4];" \
                 : "=r"(r0), "=r"(r1), "=r"(r2), "=r"(r3) : "r"(addr))

// ---------------------------------------------------------------------------
// Weight conversion sizes
// ---------------------------------------------------------------------------
#define NWI (2 * D_INNER * D_MODEL)
#define NWO (D_MODEL * D_INNER)
#define NWX (XDBL_COLS * D_INNER)
#define NWD (D_INNER * DT_RANK)
#define NW_TOTAL (NWI + NWO + NWX + NWD)
#define NW_BLOCKS ((NW_TOTAL / 4 + 255) / 256)

__device__ __forceinline__ void cvt4(const float* src, __half* dst, int i)
{
    float4 v = *(const float4*)(src + i);
    __half2 h0 = __floats2half2_rn(v.x, v.y);
    __half2 h1 = __floats2half2_rn(v.z, v.w);
    uint2 o;
    o.x = *(unsigned*)&h0;
    o.y = *(unsigned*)&h1;
    *(uint2*)(dst + i) = o;
}

// ---------------------------------------------------------------------------
// Fused: RMSNorm (blocks 0..ROWS-1) + weight cvt (blocks ROWS..)
// ---------------------------------------------------------------------------
__global__ __launch_bounds__(256)
void prep_kernel(const float* __restrict__ x, const float* __restrict__ w,
                 __half* __restrict__ out, float* __restrict__ resid,
                 const float* __restrict__ wi, const float* __restrict__ wo,
                 const float* __restrict__ wx, const float* __restrict__ wd)
{
    if (blockIdx.x >= ROWS) {
        int i = ((blockIdx.x - ROWS) * 256 + threadIdx.x) * 4;
        if (i < NWI)                       cvt4(wi, g_wi, i);
        else if (i < NWI + NWO)            cvt4(wo, g_wo, i - NWI);
        else if (i < NWI + NWO + NWX)      cvt4(wx, g_wx, i - NWI - NWO);
        else if (i < NW_TOTAL)             cvt4(wd, g_wd, i - NWI - NWO - NWX);
        return;
    }

    int r = blockIdx.x;
    int t = threadIdx.x;
    const float4* xr = (const float4*)(x + (size_t)r * D_MODEL);
    float4 v = xr[t];
    float s = v.x * v.x + v.y * v.y + v.z * v.z + v.w * v.w;
    #pragma unroll
    for (int o = 16; o; o >>= 1) s += __shfl_xor_sync(0xffffffffu, s, o);

    __shared__ float ws[8];
    __shared__ float s_inv;
    if ((t & 31) == 0) ws[t >> 5] = s;
    __syncthreads();
    if (t == 0) {
        float tot = 0.f;
        #pragma unroll
        for (int i = 0; i < 8; i++) tot += ws[i];
        float rms = sqrtf(tot) * (1.0f / 32.0f);
        s_inv = 1.0f / (rms + EPS);
    }
    __syncthreads();
    float inv = s_inv;
    float4 wv = ((const float4*)w)[t];
    __half2 h0 = __floats2half2_rn(v.x * inv * wv.x, v.y * inv * wv.y);
    __half2 h1 = __floats2half2_rn(v.z * inv * wv.z, v.w * inv * wv.w);
    uint2 o;
    o.x = *(unsigned*)&h0;
    o.y = *(unsigned*)&h1;
    ((uint2*)(out + (size_t)r * D_MODEL))[t] = o;
    ((float4*)(resid + (size_t)r * D_MODEL))[t] = v;
}

// ---------------------------------------------------------------------------
// FP16 HMMA GEMM: CTA 128x64, BK=64, warp 32x32, 3 CTAs/SM, 1 sync/ktile.
// EPI: 0 = fp32 store; 1 = softplus(acc+bias) fp32; 2 = fp32 + fp16 dup.
// ---------------------------------------------------------------------------
#define BK        64
#define STG       3
#define RB        128
#define A_BYTES   (128 * RB)
#define B_BYTES   (64 * RB)
#define STAGE_B   (A_BYTES + B_BYTES)
#define GEMM_SMEM (STG * STAGE_B)

template<int EPI>
__global__ __launch_bounds__(256, 3)
void gemm_h(const __half* __restrict__ A, int lda,
            const __half* __restrict__ B, int ldb,
            float* __restrict__ C, int ldc,
            __half* __restrict__ Caux,
            int N, int k_len, long long split_cstride,
            const float* __restrict__ bias)
{
    extern __shared__ unsigned char smem_raw[];
    const uint32_t smem = (uint32_t)__cvta_generic_to_shared(smem_raw);

    const int tid  = threadIdx.x;
    const int wid  = tid >> 5;
    const int lane = tid & 31;
    const int wm   = (wid & 3) * 32;
    const int wn   = (wid >> 2) * 32;

    const int bm = blockIdx.y * 128;
    const int bn = blockIdx.x * 64;
    const int k0base = blockIdx.z * k_len;
    C += (size_t)blockIdx.z * split_cstride;
    const int ktiles = k_len / BK;

    auto load_stage = [&](int stage, int kt) {
        const int k0 = k0base + kt * BK;
        const uint32_t sa = smem + stage * STAGE_B;
        const uint32_t sb = sa + A_BYTES;
        #pragma unroll
        for (int i = 0; i < 4; i++) {
            int lin = i * 256 + tid;
            int c   = lin & 7;
            int row = lin >> 3;
            uint32_t dst = sa + row * RB + ((c ^ (row & 7)) << 4);
            const __half* src = A + (size_t)(bm + row) * lda + k0 + c * 8;
            asm volatile("cp.async.cg.shared.global [%0], [%1], 16;"
                         :: "r"(dst), "l"(src));
        }
        #pragma unroll
        for (int i = 0; i < 2; i++) {
            int lin = i * 256 + tid;
            int c   = lin & 7;
            int row = lin >> 3;
            int gn  = bn + row;
            uint32_t dst = sb + row * RB + ((c ^ (row & 7)) << 4);
            const __half* src = B + (size_t)(gn < N ? gn : 0) * ldb + k0 + c * 8;
            int ok = (gn < N) ? 16 : 0;
            asm volatile("cp.async.cg.shared.global [%0], [%1], 16, %2;"
                         :: "r"(dst), "l"(src), "r"(ok));
        }
    };

    float acc[2][4][4];
    #pragma unroll
    for (int i = 0; i < 2; i++)
        #pragma unroll
        for (int j = 0; j < 4; j++)
            #pragma unroll
            for (int q = 0; q < 4; q++) acc[i][j][q] = 0.f;

    #pragma unroll
    for (int s = 0; s < STG - 1; s++) {
        if (s < ktiles) load_stage(s, s);
        asm volatile("cp.async.commit_group;");
    }

    const int a_row = ((lane >> 3) & 1) * 8 + (lane & 7);
    const int a_kh  = lane >> 4;
    const int b_row = (lane >> 4) * 8 + (lane & 7);
    const int b_kh  = (lane >> 3) & 1;
    const int lxor  = lane & 7;

    for (int kt = 0; kt < ktiles; kt++) {
        asm volatile("cp.async.wait_group %0;" :: "n"(STG - 2));
        __syncthreads();

        if (kt + STG - 1 < ktiles) load_stage((kt + STG - 1) % STG, kt + STG - 1);
        asm volatile("cp.async.commit_group;");

        const uint32_t Ab = smem + (kt % STG) * STAGE_B;
        const uint32_t Bb = Ab + A_BYTES;

        #pragma unroll
        for (int ks = 0; ks < 4; ks++) {
            const uint32_t ca = (uint32_t)((((ks << 1) | a_kh) ^ lxor) << 4);
            const uint32_t cb = (uint32_t)((((ks << 1) | b_kh) ^ lxor) << 4);
            uint32_t a[2][4], b[4][2];
            #pragma unroll
            for (int mt = 0; mt < 2; mt++) {
                uint32_t ad = Ab + (wm + mt * 16 + a_row) * RB + ca;
                LDSM_X4(a[mt][0], a[mt][1], a[mt][2], a[mt][3], ad);
            }
            #pragma unroll
            for (int np = 0; np < 2; np++) {
                uint32_t bd = Bb + (wn + np * 16 + b_row) * RB + cb;
                LDSM_X4(b[2 * np][0], b[2 * np][1], b[2 * np + 1][0], b[2 * np + 1][1], bd);
            }
            #pragma unroll
            for (int mt = 0; mt < 2; mt++)
                #pragma unroll
                for (int nt = 0; nt < 4; nt++)
                    mma_f16(acc[mt][nt], a[mt], b[nt][0], b[nt][1]);
        }
    }

    const int g4 = lane >> 2;
    const int t2 = (lane & 3) * 2;
    #pragma unroll
    for (int mt = 0; mt < 2; mt++) {
        int gm = bm + wm + mt * 16 + g4;
        #pragma unroll
        for (int nt = 0; nt < 4; nt++) {
            int gn = bn + wn + nt * 8 + t2;
            if (gn < N) {
                float2 v0 = make_float2(acc[mt][nt][0], acc[mt][nt][1]);
                float2 v1 = make_float2(acc[mt][nt][2], acc[mt][nt][3]);
                if (EPI == 1) {
                    float b0 = bias[gn], b1 = bias[gn + 1];
                    v0.x = softplusf(v0.x + b0);
                    v0.y = softplusf(v0.y + b1);
                    v1.x = softplusf(v1.x + b0);
                    v1.y = softplusf(v1.y + b1);
                }
                *(float2*)(C + (size_t)gm * ldc + gn)       = v0;
                *(float2*)(C + (size_t)(gm + 8) * ldc + gn) = v1;
                if (EPI == 2) {
                    __half2 h0 = __floats2half2_rn(v0.x, v0.y);
                    __half2 h1 = __floats2half2_rn(v1.x, v1.y);
                    *(__half2*)(Caux + (size_t)gm * ldc + gn)       = h0;
                    *(__half2*)(Caux + (size_t)(gm + 8) * ldc + gn) = h1;
                }
            }
        }
    }
}

// ---------------------------------------------------------------------------
// x_proj split-K reduce: sum 8 partials -> fp32 + fp16
// ---------------------------------------------------------------------------
__global__ __launch_bounds__(256)
void xp_reduce_kernel()
{
    int i = blockIdx.x * 256 + threadIdx.x;
    if (i >= ROWS * XDBL_COLS) return;
    float s = 0.f;
    #pragma unroll
    for (int p = 0; p < XP_SPLITS; p++)
        s += g_xpart[(size_t)p * ROWS * XDBL_COLS + i];
    g_xdbl[i]  = s;
    g_xdblt[i] = __float2half_rn(s);
}

// ---------------------------------------------------------------------------
// out_proj split-K reduce: out = sum of 4 partials (vectorized float4)
// ---------------------------------------------------------------------------
__global__ __launch_bounds__(256)
void op_reduce_kernel(float* __restrict__ out)
{
    int i = (blockIdx.x * 256 + threadIdx.x) * 4;
    if (i >= ROWS * D_MODEL) return;
    float4 r = *(const float4*)(g_opart + i);
    #pragma unroll
    for (int p = 1; p < OP_SPLITS; p++) {
        float4 a = *(const float4*)(g_opart + (size_t)p * ROWS * D_MODEL + i);
        r.x += a.x; r.y += a.y; r.z += a.z; r.w += a.w;
    }
    *(float4*)(out + i) = r;
}

// ---------------------------------------------------------------------------
// Depthwise causal conv + bias + SiLU, 4 channels x 4 timesteps per thread.
// 7 float4 loads -> 16 outputs; float4/uint2 stores.
// ---------------------------------------------------------------------------
__global__ __launch_bounds__(256)
void conv_silu_kernel(const float* __restrict__ xz,
                      const float* __restrict__ cw,
                      const float* __restrict__ cb,
                      float* __restrict__ xc,
                      __half* __restrict__ xct)
{
    int idx = blockIdx.x * blockDim.x + threadIdx.x;   // (ROWS/4) * (D_INNER/4)
    if (idx >= (ROWS / 4) * (D_INNER / 4)) return;
    int d4 = (idx & (D_INNER / 4 - 1)) * 4;
    int r4 = idx >> 9;                   // / (D_INNER/4)
    int l0 = (r4 & (SEQLEN / 4 - 1)) * 4;
    int b  = r4 >> 8;

    const float* x_b = xz + (size_t)b * SEQLEN * (2 * D_INNER) + d4;

    float4 xv[7];
    #pragma unroll
    for (int j = 0; j < 7; j++) {
        int l = l0 + j - 3;
        xv[j] = (l >= 0) ? *(const float4*)(x_b + (size_t)l * (2 * D_INNER))
                         : make_float4(0.f, 0.f, 0.f, 0.f);
    }

    float4 wv[4];   // wv[c] = weights for channel d4+c
    #pragma unroll
    for (int c = 0; c < 4; c++)
        wv[c] = *(const float4*)(cw + (d4 + c) * D_CONV);
    float4 bv = *(const float4*)(cb + d4);

    size_t base = (size_t)(b * SEQLEN + l0) * D_INNER + d4;
    #pragma unroll
    for (int i = 0; i < 4; i++) {
        const float* xi0 = &xv[i].x;         // xv[i..i+3] are taps for step i
        float o[4];
        #pragma unroll
        for (int c = 0; c < 4; c++) {
            const float* w = &wv[c].x;
            float acc = (&bv.x)[c];
            #pragma unroll
            for (int k = 0; k < 4; k++)
                acc = fmaf((&xv[i + k].x)[c], w[k], acc);
            o[c] = acc / (1.0f + __expf(-acc));
        }
        *(float4*)(xc + base + (size_t)i * D_INNER) =
            make_float4(o[0], o[1], o[2], o[3]);
        __half2 h0 = __floats2half2_rn(o[0], o[1]);
        __half2 h1 = __floats2half2_rn(o[2], o[3]);
        uint2 u;
        u.x = *(unsigned*)&h0;
        u.y = *(unsigned*)&h1;
        *(uint2*)(xct + base + (size_t)i * D_INNER) = u;
    }
}

// ---------------------------------------------------------------------------
// Selective scan, smem-chunked, smem-staged state reduction.
// ---------------------------------------------------------------------------
#define SCH 64
#define NCH (SEQLEN / SCH)

__global__ __launch_bounds__(256)
void scan_kernel(const float* __restrict__ xdbl,
                 const float* __restrict__ dt,
                 const float* __restrict__ xc,
                 const float* __restrict__ xz,
                 const float* __restrict__ A_log,
                 const float* __restrict__ Dw,
                 __half* __restrict__ y)
{
    __shared__ float s_dt[2][SCH][16];
    __shared__ float s_xc[2][SCH][16];
    __shared__ float s_z [2][SCH][16];
    __shared__ float s_B [2][SCH][16];
    __shared__ float s_C [2][SCH][16];
    __shared__ float s_p [SCH][16][17];

    const int tid = threadIdx.x;
    const int n   = tid & 15;
    const int dl  = tid >> 4;
    const int b   = blockIdx.x >> 7;
    const int d0  = (blockIdx.x & 127) * 16;
    const int d   = d0 + dl;

    const float A = -__expf(A_log[d * D_STATE + n]);

    const int rdl = tid & 15;
    const int rl0 = tid >> 4;
    const float rDd = Dw[d0 + rdl];

    const int lr = tid >> 2;
    const int lc = tid & 3;

    const float* dt_g = dt   + (size_t)b * SEQLEN * D_INNER + d0 + lc * 4;
    const float* xc_g = xc   + (size_t)b * SEQLEN * D_INNER + d0 + lc * 4;
    const float* z_g  = xz   + (size_t)b * SEQLEN * (2 * D_INNER) + D_INNER + d0 + lc * 4;
    const float* B_g  = xdbl + (size_t)b * SEQLEN * XDBL_COLS + DT_RANK + lc * 4;
    const float* C_g  = B_g + D_STATE;

    auto load_chunk = [&](int ch, int buf) {
        int l = ch * SCH + lr;
        uint32_t ddt = (uint32_t)__cvta_generic_to_shared(&s_dt[buf][lr][lc * 4]);
        uint32_t dxc = (uint32_t)__cvta_generic_to_shared(&s_xc[buf][lr][lc * 4]);
        uint32_t dz  = (uint32_t)__cvta_generic_to_shared(&s_z [buf][lr][lc * 4]);
        uint32_t dB  = (uint32_t)__cvta_generic_to_shared(&s_B [buf][lr][lc * 4]);
        uint32_t dC  = (uint32_t)__cvta_generic_to_shared(&s_C [buf][lr][lc * 4]);
        asm volatile("cp.async.cg.shared.global [%0], [%1], 16;"
                     :: "r"(ddt), "l"(dt_g + (size_t)l * D_INNER));
        asm volatile("cp.async.cg.shared.global [%0], [%1], 16;"
                     :: "r"(dxc), "l"(xc_g + (size_t)l * D_INNER));
        asm volatile("cp.async.cg.shared.global [%0], [%1], 16;"
                     :: "r"(dz),  "l"(z_g + (size_t)l * (2 * D_INNER)));
        asm volatile("cp.async.cg.shared.global [%0], [%1], 16;"
                     :: "r"(dB),  "l"(B_g + (size_t)l * XDBL_COLS));
        asm volatile("cp.async.cg.shared.global [%0], [%1], 16;"
                     :: "r"(dC),  "l"(C_g + (size_t)l * XDBL_COLS));
    };

    __half* y_b = y + (size_t)b * SEQLEN * D_INNER + d0 + rdl;

    load_chunk(0, 0);
    asm volatile("cp.async.commit_group;");

    float h = 0.f;
    for (int ch = 0; ch < NCH; ch++) {
        const int buf = ch & 1;
        if (ch + 1 < NCH) load_chunk(ch + 1, buf ^ 1);
        asm volatile("cp.async.commit_group;");
        if (ch + 1 < NCH) asm volatile("cp.async.wait_group 1;");
        else              asm volatile("cp.async.wait_group 0;");
        __syncthreads();

        #pragma unroll 4
        for (int l = 0; l < SCH; l++) {
            float dtv = s_dt[buf][l][dl];
            float xcv = s_xc[buf][l][dl];
            float Bv  = s_B [buf][l][n];
            float Cv  = s_C [buf][l][n];

            float dA = __expf(dtv * A);
            h = fmaf(dA, h, dtv * xcv * Bv);
            s_p[l][dl][n] = h * Cv;
        }
        __syncthreads();

        #pragma unroll
        for (int i = 0; i < 4; i++) {
            int l = rl0 + 16 * i;
            const float* pr = s_p[l][rdl];
            float s = 0.f;
            #pragma unroll
            for (int q = 0; q < 16; q++) s += pr[q];
            float xcv = s_xc[buf][l][rdl];
            float zv  = s_z [buf][l][rdl];
            float sil = zv / (1.0f + __expf(-zv));
            y_b[(size_t)(ch * SCH + l) * D_INNER] =
                __float2half_rn((s + rDd * xcv) * sil);
        }
        __syncthreads();
    }
}

// ---------------------------------------------------------------------------
// Launch
// ---------------------------------------------------------------------------
extern "C" void kernel_launch(void* const* d_in, const int* in_sizes, int n_in,
                              void* d_out, int out_size)
{
    const float* hidden   = (const float*)d_in[0];
    const float* norm_w   = (const float*)d_in[1];
    const float* in_proj  = (const float*)d_in[2];
    const float* conv_w   = (const float*)d_in[3];
    const float* conv_b   = (const float*)d_in[4];
    const float* x_proj   = (const float*)d_in[5];
    const float* dt_proj  = (const float*)d_in[6];
    const float* dt_b     = (const float*)d_in[7];
    const float* A_log    = (const float*)d_in[8];
    const float* Dw       = (const float*)d_in[9];
    const float* out_proj = (const float*)d_in[10];

    float* out = (float*)d_out;
    size_t half = (size_t)out_size / 2;

    __half *ht, *xct, *xdblt, *yt, *wi, *wo, *wx, *wd;
    float *xz, *xc, *xpart, *opart, *xdbl, *dt;
    cudaGetSymbolAddress((void**)&ht,    g_ht);
    cudaGetSymbolAddress((void**)&xz,    g_xz);
    cudaGetSymbolAddress((void**)&xc,    g_xc);
    cudaGetSymbolAddress((void**)&xct,   g_xct);
    cudaGetSymbolAddress((void**)&xpart, g_xpart);
    cudaGetSymbolAddress((void**)&opart, g_opart);
    cudaGetSymbolAddress((void**)&xdbl,  g_xdbl);
    cudaGetSymbolAddress((void**)&xdblt, g_xdblt);
    cudaGetSymbolAddress((void**)&dt,    g_dt);
    cudaGetSymbolAddress((void**)&yt,    g_yt);
    cudaGetSymbolAddress((void**)&wi,    g_wi);
    cudaGetSymbolAddress((void**)&wo,    g_wo);
    cudaGetSymbolAddress((void**)&wx,    g_wx);
    cudaGetSymbolAddress((void**)&wd,    g_wd);

    cudaFuncSetAttribute(gemm_h<0>, cudaFuncAttributeMaxDynamicSharedMemorySize, GEMM_SMEM);
    cudaFuncSetAttribute(gemm_h<1>, cudaFuncAttributeMaxDynamicSharedMemorySize, GEMM_SMEM);

    // 0+1. fused weight cvt + RMSNorm + residual passthrough
    prep_kernel<<<ROWS + NW_BLOCKS, 256>>>(hidden, norm_w, ht, out + half,
                                           in_proj, out_proj, x_proj, dt_proj);

    // 2. in_proj: (2048 x 1024) @ (4096 x 1024)^T -> xz
    gemm_h<0><<<dim3(2 * D_INNER / 64, ROWS / 128, 1), 256, GEMM_SMEM>>>(
        ht, D_MODEL, wi, D_MODEL, xz, 2 * D_INNER, nullptr,
        2 * D_INNER, D_MODEL, 0, nullptr);

    // 3. conv + silu (4ch x 4steps/thread) -> xc fp32 + xct fp16
    conv_silu_kernel<<<(ROWS / 4) * (D_INNER / 4) / 256, 256>>>(
        xz, conv_w, conv_b, xc, xct);

    // 4. x_proj split-K: (2048 x 2048) @ (96 x 2048)^T -> 8 partials
    gemm_h<0><<<dim3(2, ROWS / 128, XP_SPLITS), 256, GEMM_SMEM>>>(
        xct, D_INNER, wx, D_INNER, xpart, XDBL_COLS, nullptr,
        XDBL_COLS, XP_KSPL, (long long)ROWS * XDBL_COLS, nullptr);

    // 4b. reduce -> xdbl fp32 + xdblt fp16
    xp_reduce_kernel<<<(ROWS * XDBL_COLS + 255) / 256, 256>>>();

    // 5. dt_proj + softplus: (2048 x 96[:64]) @ (2048 x 64)^T -> dt fp32
    gemm_h<1><<<dim3(D_INNER / 64, ROWS / 128, 1), 256, GEMM_SMEM>>>(
        xdblt, XDBL_COLS, wd, DT_RANK, dt, D_INNER, nullptr,
        D_INNER, DT_RANK, 0, dt_b);

    // 6. selective scan + gate -> yt fp16
    scan_kernel<<<BATCH * D_INNER / 16, 256>>>(
        xdbl, dt, xc, xz, A_log, Dw, yt);

    // 7. out_proj split-K=4: (2048 x 2048) @ (1024 x 2048)^T -> 4 partials
    gemm_h<0><<<dim3(D_MODEL / 64, ROWS / 128, OP_SPLITS), 256, GEMM_SMEM>>>(
        yt, D_INNER, wo, D_INNER, opart, D_MODEL, nullptr,
        D_MODEL, OP_KSPL, (long long)ROWS * D_MODEL, nullptr);

    // 7b. reduce partials -> out
    op_reduce_kernel<<<(ROWS * D_MODEL / 4 + 255) / 256, 256>>>(out);
}